// round 11
// baseline (speedup 1.0000x reference)
#include <cuda_runtime.h>
#include <math.h>
#include <stdint.h>

#define BATCH 4
#define TOK   1024
#define DIM   512
#define RDIM  64
#define NS0   1024
#define NS1   256
#define NS2   64
#define DR    (DIM*RDIM)   /* 32768 */

// ---------------- scratch (static device memory; no cudaMalloc) -------------
__device__ float g_q [BATCH*TOK*RDIM];
__device__ float g_q2[BATCH*TOK*RDIM];
__device__ float g_k [BATCH*NS0*RDIM];
__device__ float g_k2[BATCH*NS0*RDIM];
__device__ float g_kr [BATCH*NS0*RDIM];     // read-path k partials (stream s1)
__device__ float g_kr2[BATCH*NS0*RDIM];
__device__ float g_rq[2*3*BATCH*TOK*RDIM];  // [split][route][b] read-path q parts
__device__ float g_lg [BATCH*TOK*NS0];      // transition logits (16MB)
__device__ float g_lgr[BATCH*TOK*NS0];      // read-path logits/attn (16MB)
__device__ float g_ds[BATCH*NS0];
__device__ float g_dv[BATCH*NS0*DIM];
__device__ float g_s0[BATCH*NS0];
__device__ float g_v0[BATCH*NS0*DIM];
__device__ float g_s1[BATCH*NS1];
__device__ float g_v1[BATCH*NS1*DIM];
__device__ float g_s2[BATCH*NS2];
__device__ float g_v2[BATCH*NS2*DIM];
__device__ float g_r [BATCH*TOK*DIM];

// ---------------- tf32 helpers ------------------------------------------------
__device__ __forceinline__ uint32_t f2tf32(float x) {
    uint32_t u;
    asm("cvt.rna.tf32.f32 %0, %1;" : "=r"(u) : "f"(x));
    return u;
}
__device__ __forceinline__ void mma_tf32(float* c, uint32_t a0, uint32_t a1,
                                         uint32_t a2, uint32_t a3,
                                         uint32_t b0, uint32_t b1) {
    asm volatile(
        "mma.sync.aligned.m16n8k8.row.col.f32.tf32.tf32.f32 "
        "{%0,%1,%2,%3}, {%4,%5,%6,%7}, {%8,%9}, {%0,%1,%2,%3};"
        : "+f"(c[0]), "+f"(c[1]), "+f"(c[2]), "+f"(c[3])
        : "r"(a0), "r"(a1), "r"(a2), "r"(a3), "r"(b0), "r"(b1));
}

// order-preserving monotone encoding of float (total order, -inf lowest)
__device__ __forceinline__ uint32_t fmono(float x) {
    uint32_t u = __float_as_uint(x);
    return (u & 0x80000000u) ? ~u : (u | 0x80000000u);
}
__device__ __forceinline__ float fdemono(uint32_t k) {
    uint32_t u = (k & 0x80000000u) ? (k & 0x7fffffffu) : ~k;
    return __uint_as_float(u);
}

// ---------------- fused zero of ds + dv (head only) --------------------------
__global__ void fill_ds_dv(float* __restrict__ ds, float4* __restrict__ dv4,
                           int nds, int ndv4) {
    const int stride = gridDim.x * blockDim.x;
    const int i0 = blockIdx.x * blockDim.x + threadIdx.x;
    for (int j = i0; j < nds; j += stride) ds[j] = 0.f;
    const float4 z = make_float4(0.f, 0.f, 0.f, 0.f);
    for (int j = i0; j < ndv4; j += stride) dv4[j] = z;
}

// ============ split-K projection GEMM core (64x64 tile, K=256 slice) =========
__device__ __forceinline__ void proj_body(const float* __restrict__ Ab,
                                          const float* __restrict__ Bb,
                                          float* __restrict__ Cb, int m0)
{
    __shared__ float sAt[16][68];
    __shared__ float sBt[16][68];
    const int tid = threadIdx.x;
    const int tx = tid & 15, ty = tid >> 4;
    const int arow = tid >> 2, ak4 = (tid & 3) << 2;
    const int bk = tid >> 4, bn4 = (tid & 15) << 2;

    float acc[4][4];
#pragma unroll
    for (int i = 0; i < 4; i++)
#pragma unroll
        for (int j = 0; j < 4; j++) acc[i][j] = 0.f;

    float4 pa = *(const float4*)(Ab + (size_t)(m0 + arow) * DIM + ak4);
    float4 pb = *(const float4*)(Bb + (size_t)bk * RDIM + bn4);
    sAt[ak4 + 0][arow] = pa.x; sAt[ak4 + 1][arow] = pa.y;
    sAt[ak4 + 2][arow] = pa.z; sAt[ak4 + 3][arow] = pa.w;
    *(float4*)&sBt[bk][bn4] = pb;
    __syncthreads();

    for (int k0 = 16; k0 < 256; k0 += 16) {
        pa = *(const float4*)(Ab + (size_t)(m0 + arow) * DIM + k0 + ak4);
        pb = *(const float4*)(Bb + (size_t)(k0 + bk) * RDIM + bn4);
#pragma unroll
        for (int kk = 0; kk < 16; kk++) {
            float4 a  = *(const float4*)&sAt[kk][ty << 2];
            float4 bq = *(const float4*)&sBt[kk][tx << 2];
            float aa[4] = {a.x, a.y, a.z, a.w};
            float bb[4] = {bq.x, bq.y, bq.z, bq.w};
#pragma unroll
            for (int i = 0; i < 4; i++)
#pragma unroll
                for (int j = 0; j < 4; j++) acc[i][j] += aa[i] * bb[j];
        }
        __syncthreads();
        sAt[ak4 + 0][arow] = pa.x; sAt[ak4 + 1][arow] = pa.y;
        sAt[ak4 + 2][arow] = pa.z; sAt[ak4 + 3][arow] = pa.w;
        *(float4*)&sBt[bk][bn4] = pb;
        __syncthreads();
    }
#pragma unroll
    for (int kk = 0; kk < 16; kk++) {
        float4 a  = *(const float4*)&sAt[kk][ty << 2];
        float4 bq = *(const float4*)&sBt[kk][tx << 2];
        float aa[4] = {a.x, a.y, a.z, a.w};
        float bb[4] = {bq.x, bq.y, bq.z, bq.w};
#pragma unroll
        for (int i = 0; i < 4; i++)
#pragma unroll
            for (int j = 0; j < 4; j++) acc[i][j] += aa[i] * bb[j];
    }
#pragma unroll
    for (int i = 0; i < 4; i++) {
        size_t idx = (size_t)(m0 + (ty << 2) + i) * RDIM + (tx << 2);
        *(float4*)(Cb + idx) = make_float4(acc[i][0], acc[i][1], acc[i][2], acc[i][3]);
    }
}

// dual q/k projection, split-K=2. grid (2, Ns/64 + Nd/64, BATCH)
__global__ void __launch_bounds__(256)
qk_gemm_sk(const float* __restrict__ src, const float* __restrict__ dst,
           const float* __restrict__ W,
           float* __restrict__ q0, float* __restrict__ q1,
           float* __restrict__ k0, float* __restrict__ k1, int Ns, int Nd)
{
    const int b = blockIdx.z, s = blockIdx.x;
    const int nyq = Ns >> 6;
    const bool isQ = (int)blockIdx.y < nyq;
    const float* Ab = (isQ ? src + (size_t)b * Ns * DIM
                           : dst + (size_t)b * Nd * DIM) + s * 256;
    const float* Bb = (isQ ? W : W + DR) + (size_t)s * 256 * RDIM;
    float* Cb = isQ ? (s ? q1 : q0) + (size_t)b * Ns * RDIM
                    : (s ? k1 : k0) + (size_t)b * Nd * RDIM;
    const int m0 = (isQ ? blockIdx.y : blockIdx.y - nyq) * 64;
    proj_body(Ab, Bb, Cb, m0);
}

// read-path q projections: 3 routes in one launch. grid (2, TOK/64, 3*BATCH)
__global__ void __launch_bounds__(256)
rq_gemm_sk(const float* __restrict__ tok, const float* __restrict__ rr,
           float* __restrict__ rqp)
{
    const int s = blockIdx.x;
    const int l = blockIdx.z / BATCH, b = blockIdx.z % BATCH;
    const float* Ab = tok + (size_t)b * TOK * DIM + s * 256;
    const float* Bb = rr + (size_t)l * 2 * DR + (size_t)s * 256 * RDIM;
    float* Cb = rqp + ((size_t)(s * 3 + l) * BATCH + b) * TOK * RDIM;
    proj_body(Ab, Bb, Cb, blockIdx.y * 64);
}

// ---------------- logits GEMM (64x64 tile, small cases) ----------------------
__global__ void __launch_bounds__(256)
atb_gemm(const float* __restrict__ A0, const float* __restrict__ A1,
         const float* __restrict__ B0, const float* __restrict__ B1,
         float* __restrict__ C, int M, int N)
{
    __shared__ float sAt[64][68];
    __shared__ float sBt[64][68];
    const int b = blockIdx.z;
    const size_t aoff = (size_t)b * M * 64;
    const size_t boff = (size_t)b * N * 64;
    const int m0 = blockIdx.y * 64, n0 = blockIdx.x * 64;
    const int tid = threadIdx.x;
    const int tx = tid & 15, ty = tid >> 4;
    const int row = tid >> 2, q4 = (tid & 3) << 2;

#pragma unroll
    for (int c = 0; c < 4; c++) {
        const int kk0 = q4 + c * 16;
        const size_t ai = aoff + (size_t)(m0 + row) * 64 + kk0;
        const size_t bi = boff + (size_t)(n0 + row) * 64 + kk0;
        float4 av = *(const float4*)(A0 + ai);
        float4 a1 = *(const float4*)(A1 + ai);
        float4 bv = *(const float4*)(B0 + bi);
        float4 b1 = *(const float4*)(B1 + bi);
        av.x += a1.x; av.y += a1.y; av.z += a1.z; av.w += a1.w;
        bv.x += b1.x; bv.y += b1.y; bv.z += b1.z; bv.w += b1.w;
        sAt[kk0 + 0][row] = av.x; sAt[kk0 + 1][row] = av.y;
        sAt[kk0 + 2][row] = av.z; sAt[kk0 + 3][row] = av.w;
        sBt[kk0 + 0][row] = bv.x; sBt[kk0 + 1][row] = bv.y;
        sBt[kk0 + 2][row] = bv.z; sBt[kk0 + 3][row] = bv.w;
    }
    __syncthreads();

    float acc[4][4];
#pragma unroll
    for (int i = 0; i < 4; i++)
#pragma unroll
        for (int j = 0; j < 4; j++) acc[i][j] = 0.f;
#pragma unroll 16
    for (int kk = 0; kk < 64; kk++) {
        float4 a  = *(const float4*)&sAt[kk][ty << 2];
        float4 bq = *(const float4*)&sBt[kk][tx << 2];
        float aa[4] = {a.x, a.y, a.z, a.w};
        float bb[4] = {bq.x, bq.y, bq.z, bq.w};
#pragma unroll
        for (int i = 0; i < 4; i++)
#pragma unroll
            for (int j = 0; j < 4; j++) acc[i][j] += aa[i] * bb[j];
    }
#pragma unroll
    for (int i = 0; i < 4; i++) {
        size_t idx = (size_t)b * M * N + (size_t)(m0 + (ty << 2) + i) * N + n0 + (tx << 2);
        float4 cv = make_float4(0.125f * acc[i][0], 0.125f * acc[i][1],
                                0.125f * acc[i][2], 0.125f * acc[i][3]);
        *(float4*)(C + idx) = cv;
    }
}

// ---------------- logits GEMM big: 128x128 tile, 8x8 micro, K=64 resident ----
__global__ void __launch_bounds__(256)
atb_big(const float* __restrict__ A0, const float* __restrict__ A1,
        const float* __restrict__ B0, const float* __restrict__ B1,
        float* __restrict__ C, int M, int N)
{
    extern __shared__ float sm[];
    float (*sAt)[132] = (float(*)[132])sm;
    float (*sBt)[132] = (float(*)[132])(sm + 64 * 132);
    const int b = blockIdx.z;
    const size_t aoff = (size_t)b * M * 64;
    const size_t boff = (size_t)b * N * 64;
    const int m0 = blockIdx.y * 128, n0 = blockIdx.x * 128;
    const int tid = threadIdx.x;
    const int tx = tid & 15, ty = tid >> 4;

    for (int idx = tid; idx < 2048; idx += 256) {
        const int row = idx >> 4, kq = (idx & 15) << 2;
        const size_t ai = aoff + (size_t)(m0 + row) * 64 + kq;
        const size_t bi = boff + (size_t)(n0 + row) * 64 + kq;
        float4 av = *(const float4*)(A0 + ai);
        float4 a1 = *(const float4*)(A1 + ai);
        float4 bv = *(const float4*)(B0 + bi);
        float4 b1 = *(const float4*)(B1 + bi);
        av.x += a1.x; av.y += a1.y; av.z += a1.z; av.w += a1.w;
        bv.x += b1.x; bv.y += b1.y; bv.z += b1.z; bv.w += b1.w;
        sAt[kq + 0][row] = av.x; sAt[kq + 1][row] = av.y;
        sAt[kq + 2][row] = av.z; sAt[kq + 3][row] = av.w;
        sBt[kq + 0][row] = bv.x; sBt[kq + 1][row] = bv.y;
        sBt[kq + 2][row] = bv.z; sBt[kq + 3][row] = bv.w;
    }
    __syncthreads();

    float acc[8][8];
#pragma unroll
    for (int i = 0; i < 8; i++)
#pragma unroll
        for (int j = 0; j < 8; j++) acc[i][j] = 0.f;

#pragma unroll 8
    for (int kk = 0; kk < 64; kk++) {
        float4 a0 = *(const float4*)&sAt[kk][ty << 2];
        float4 a1 = *(const float4*)&sAt[kk][64 + (ty << 2)];
        float4 b0 = *(const float4*)&sBt[kk][tx << 2];
        float4 b1 = *(const float4*)&sBt[kk][64 + (tx << 2)];
        float av[8] = {a0.x, a0.y, a0.z, a0.w, a1.x, a1.y, a1.z, a1.w};
        float bv[8] = {b0.x, b0.y, b0.z, b0.w, b1.x, b1.y, b1.z, b1.w};
#pragma unroll
        for (int i = 0; i < 8; i++)
#pragma unroll
            for (int j = 0; j < 8; j++) acc[i][j] += av[i] * bv[j];
    }

#pragma unroll
    for (int ih = 0; ih < 2; ih++)
#pragma unroll
        for (int i = 0; i < 4; i++) {
            const int m = m0 + ih * 64 + (ty << 2) + i;
            const size_t base = (size_t)b * M * N + (size_t)m * N + n0;
#pragma unroll
            for (int jh = 0; jh < 2; jh++) {
                const int r = ih * 4 + i;
                float4 cv = make_float4(0.125f * acc[r][jh * 4 + 0],
                                        0.125f * acc[r][jh * 4 + 1],
                                        0.125f * acc[r][jh * 4 + 2],
                                        0.125f * acc[r][jh * 4 + 3]);
                *(float4*)(C + base + jh * 64 + (tx << 2)) = cv;
            }
        }
}

// ---------------- tf32 tensor-core GEMM: 128x128 tile, warp 64x32 ------------
__global__ void __launch_bounds__(256)
ab_gemm_tf32(const float* __restrict__ A, const float* __restrict__ Bm,
             float* __restrict__ C, const float* __restrict__ Cinit,
             const float* __restrict__ gatep,
             int M, int N, int K,
             long long strA, long long strB, long long strC)
{
    __shared__ uint32_t sA[16][136];
    __shared__ uint32_t sB[16][136];
    const int b = blockIdx.z;
    const float* Ab = A  + (size_t)b * strA;
    const float* Bb = Bm + (size_t)b * strB;
    const int m0 = blockIdx.y * 128, n0 = blockIdx.x * 128;
    const int tid = threadIdx.x, lane = tid & 31, warp = tid >> 5;
    const int wm = (warp >> 2) * 64, wn = (warp & 3) * 32;
    const int gid = lane >> 2, tid4 = lane & 3;
    const int arow = tid >> 1, ak = (tid & 1) * 8;
    const int bk = tid >> 4, bn = (tid & 15) * 8;

    float acc[4][4][4];
#pragma unroll
    for (int mi = 0; mi < 4; mi++)
#pragma unroll
        for (int ni = 0; ni < 4; ni++)
#pragma unroll
            for (int t = 0; t < 4; t++) acc[mi][ni][t] = 0.f;

    float4 pa0, pa1, pb0, pb1;
    {
        const float* ap = Ab + (size_t)(m0 + arow) * K + ak;
        pa0 = *(const float4*)ap; pa1 = *(const float4*)(ap + 4);
        const float* bp = Bb + (size_t)bk * N + n0 + bn;
        pb0 = *(const float4*)bp; pb1 = *(const float4*)(bp + 4);
        sA[ak + 0][arow] = f2tf32(pa0.x); sA[ak + 1][arow] = f2tf32(pa0.y);
        sA[ak + 2][arow] = f2tf32(pa0.z); sA[ak + 3][arow] = f2tf32(pa0.w);
        sA[ak + 4][arow] = f2tf32(pa1.x); sA[ak + 5][arow] = f2tf32(pa1.y);
        sA[ak + 6][arow] = f2tf32(pa1.z); sA[ak + 7][arow] = f2tf32(pa1.w);
        sB[bk][bn + 0] = f2tf32(pb0.x); sB[bk][bn + 1] = f2tf32(pb0.y);
        sB[bk][bn + 2] = f2tf32(pb0.z); sB[bk][bn + 3] = f2tf32(pb0.w);
        sB[bk][bn + 4] = f2tf32(pb1.x); sB[bk][bn + 5] = f2tf32(pb1.y);
        sB[bk][bn + 6] = f2tf32(pb1.z); sB[bk][bn + 7] = f2tf32(pb1.w);
        __syncthreads();
    }

#define TF32_COMPUTE_TILE                                                     \
    _Pragma("unroll")                                                         \
    for (int ks = 0; ks < 2; ks++) {                                          \
        const int kk = ks * 8;                                                \
        uint32_t af[4][4], bf[4][2];                                          \
        _Pragma("unroll")                                                     \
        for (int mi = 0; mi < 4; mi++) {                                      \
            const int m = wm + mi * 16 + gid;                                 \
            af[mi][0] = sA[kk + tid4][m];                                     \
            af[mi][1] = sA[kk + tid4][m + 8];                                 \
            af[mi][2] = sA[kk + 4 + tid4][m];                                 \
            af[mi][3] = sA[kk + 4 + tid4][m + 8];                             \
        }                                                                     \
        _Pragma("unroll")                                                     \
        for (int ni = 0; ni < 4; ni++) {                                      \
            const int n = wn + ni * 8 + gid;                                  \
            bf[ni][0] = sB[kk + tid4][n];                                     \
            bf[ni][1] = sB[kk + 4 + tid4][n];                                 \
        }                                                                     \
        _Pragma("unroll")                                                     \
        for (int mi = 0; mi < 4; mi++)                                        \
            _Pragma("unroll")                                                 \
            for (int ni = 0; ni < 4; ni++)                                    \
                mma_tf32(acc[mi][ni], af[mi][0], af[mi][1], af[mi][2],        \
                         af[mi][3], bf[ni][0], bf[ni][1]);                    \
    }

    for (int k0 = 16; k0 < K; k0 += 16) {
        const float* ap = Ab + (size_t)(m0 + arow) * K + k0 + ak;
        pa0 = *(const float4*)ap; pa1 = *(const float4*)(ap + 4);
        const float* bp = Bb + (size_t)(k0 + bk) * N + n0 + bn;
        pb0 = *(const float4*)bp; pb1 = *(const float4*)(bp + 4);
        TF32_COMPUTE_TILE
        __syncthreads();
        sA[ak + 0][arow] = f2tf32(pa0.x); sA[ak + 1][arow] = f2tf32(pa0.y);
        sA[ak + 2][arow] = f2tf32(pa0.z); sA[ak + 3][arow] = f2tf32(pa0.w);
        sA[ak + 4][arow] = f2tf32(pa1.x); sA[ak + 5][arow] = f2tf32(pa1.y);
        sA[ak + 6][arow] = f2tf32(pa1.z); sA[ak + 7][arow] = f2tf32(pa1.w);
        sB[bk][bn + 0] = f2tf32(pb0.x); sB[bk][bn + 1] = f2tf32(pb0.y);
        sB[bk][bn + 2] = f2tf32(pb0.z); sB[bk][bn + 3] = f2tf32(pb0.w);
        sB[bk][bn + 4] = f2tf32(pb1.x); sB[bk][bn + 5] = f2tf32(pb1.y);
        sB[bk][bn + 6] = f2tf32(pb1.z); sB[bk][bn + 7] = f2tf32(pb1.w);
        __syncthreads();
    }
    TF32_COMPUTE_TILE
#undef TF32_COMPUTE_TILE

    float alpha = 1.f;
    if (gatep) alpha = 1.f / (1.f + expf(-*gatep));
#pragma unroll
    for (int mi = 0; mi < 4; mi++) {
#pragma unroll
        for (int ni = 0; ni < 4; ni++) {
            const int r0 = m0 + wm + mi * 16 + gid;
            const int cc = n0 + wn + ni * 8 + 2 * tid4;
            const size_t i0 = (size_t)b * strC + (size_t)r0 * N + cc;
            const size_t i1 = (size_t)b * strC + (size_t)(r0 + 8) * N + cc;
            float2 v0 = make_float2(alpha * acc[mi][ni][0], alpha * acc[mi][ni][1]);
            float2 v1 = make_float2(alpha * acc[mi][ni][2], alpha * acc[mi][ni][3]);
            if (Cinit) {
                float2 c0 = *(const float2*)(Cinit + i0);
                float2 c1 = *(const float2*)(Cinit + i1);
                v0.x += c0.x; v0.y += c0.y;
                v1.x += c1.x; v1.y += c1.y;
            }
            *(float2*)(C + i0) = v0;
            *(float2*)(C + i1) = v1;
        }
    }
}

// ---------------- top-k + signed softmax + softplus-state scatter ------------
// one warp per source row. tie-break matches jax.lax.top_k (lower index first).
// Scan uses early-exit insertion (typical insert lands 1-3 slots from bottom);
// merge uses smem lane-private sorted lists + redux argmax (R10 win).
__global__ void __launch_bounds__(256)
topk_scatter(const float* __restrict__ logits, const float* __restrict__ srcval,
             const float* __restrict__ srcstate, float* __restrict__ ds,
             float* __restrict__ dv, const float* __restrict__ gatep,
             int Ns, int Nd)
{
    __shared__ uint32_t skey[8][16][32];
    __shared__ int      sidx[8][16][32];
    const int warp = threadIdx.x >> 5, lane = threadIdx.x & 31;
    const int row = blockIdx.x * 8 + warp;      // = b*Ns + s
    const int b = row / Ns;
    const float* L = logits + (size_t)row * Nd;

    float tv[16]; int ti[16];
#pragma unroll
    for (int i = 0; i < 16; i++) { tv[i] = -INFINITY; ti[i] = 0x40000000; }

    // per-lane top-16 over strided candidates (sorted ascending).
    // early-exit bubble: identical semantics to the full pass (strict > swaps)
    for (int n = lane; n < Nd; n += 32) {
        float c = L[n];
        if (c > tv[0]) {
            tv[0] = c; ti[0] = n;
            for (int i = 0; i < 15; i++) {
                if (!(tv[i] > tv[i + 1])) break;
                float t = tv[i]; tv[i] = tv[i + 1]; tv[i + 1] = t;
                int u = ti[i]; ti[i] = ti[i + 1]; ti[i + 1] = u;
            }
        }
    }

    // spill lane-private sorted list (descending) to shared for dynamic idx
#pragma unroll
    for (int j = 0; j < 16; j++) {
        skey[warp][j][lane] = fmono(tv[15 - j]);
        sidx[warp][j][lane] = ti[15 - j];
    }

    // merge: 16x [redux-max on keys, redux-min on idx for tie-break, pop]
    float sel_v = 0.f; int sel_i = 0;
    int pos = 0;
#pragma unroll 1
    for (int it = 0; it < 16; ++it) {
        uint32_t key = skey[warp][pos][lane];
        int idx = sidx[warp][pos][lane];
        uint32_t mx = __reduce_max_sync(0xffffffffu, key);
        unsigned cand = (key == mx) ? (unsigned)idx : 0x7fffffffu;
        unsigned mni = __reduce_min_sync(0xffffffffu, cand);
        pos += (key == mx && (unsigned)idx == mni) ? 1 : 0;
        if (lane == it) { sel_v = fdemono(mx); sel_i = (int)mni; }
    }

    // signed softmax over the 16 selected values (lanes 0..15 own one each)
    float a_ = (lane < 16) ? fabsf(sel_v) : -INFINITY;
    float m = a_;
#pragma unroll
    for (int o = 16; o; o >>= 1) m = fmaxf(m, __shfl_xor_sync(0xffffffffu, m, o));
    float e = (lane < 16) ? expf(a_ - m) : 0.f;
    float ssum = e;
#pragma unroll
    for (int o = 16; o; o >>= 1) ssum += __shfl_xor_sync(0xffffffffu, ssum, o);
    float sgn = (sel_v > 0.f) ? 1.f : ((sel_v < 0.f) ? -1.f : 0.f);
    float st = srcstate[row];
    float sp = fmaxf(st, 0.f) + log1pf(expf(-fabsf(st)));
    float gate = 1.f;
    if (gatep) gate = 1.f / (1.f + expf(-*gatep));
    float cc = sgn * (e / ssum) * sp * gate;

    if (lane < 16) atomicAdd(ds + (size_t)b * Nd + sel_i, cc);

    const float* srow = srcval + (size_t)row * DIM;
    float4 xr[4];
#pragma unroll
    for (int t = 0; t < 4; t++)
        xr[t] = *(const float4*)(srow + (lane << 2) + (t << 7));
#pragma unroll 1
    for (int i = 0; i < 16; i++) {
        float ci = __shfl_sync(0xffffffffu, cc, i);
        int   di = __shfl_sync(0xffffffffu, sel_i, i);
        float* dst = dv + ((size_t)b * Nd + di) * DIM + (lane << 2);
#pragma unroll
        for (int t = 0; t < 4; t++) {
            asm volatile("red.global.add.v4.f32 [%0], {%1, %2, %3, %4};"
                         :: "l"(dst + (t << 7)),
                            "f"(ci * xr[t].x), "f"(ci * xr[t].y),
                            "f"(ci * xr[t].z), "f"(ci * xr[t].w)
                         : "memory");
        }
    }
}

// ---------------- fused apply: LN rows + signed-softmax state (self-clean) ---
__global__ void __launch_bounds__(256)
apply_both(const float* __restrict__ st, float* __restrict__ ds,
           float* __restrict__ s_out,
           const float* __restrict__ val, float* __restrict__ dvv,
           float* __restrict__ v_out,
           const float* __restrict__ gamma, const float* __restrict__ beta,
           int Nd)
{
    const int tid = threadIdx.x;
    const int nln = BATCH * Nd;
    __shared__ float ss[256], sq[256];
    if ((int)blockIdx.x < nln) {
        const int row = blockIdx.x;
        float2 x = ((const float2*)(val + (size_t)row * DIM))[tid];
        float2 d = ((float2*)(dvv + (size_t)row * DIM))[tid];
        ((float2*)(dvv + (size_t)row * DIM))[tid] = make_float2(0.f, 0.f);
        x.x += d.x; x.y += d.y;
        ss[tid] = x.x + x.y;
        sq[tid] = x.x * x.x + x.y * x.y;
        __syncthreads();
        for (int o = 128; o; o >>= 1) {
            if (tid < o) { ss[tid] += ss[tid + o]; sq[tid] += sq[tid + o]; }
            __syncthreads();
        }
        float mean = ss[0] * (1.f / DIM);
        float var = sq[0] * (1.f / DIM) - mean * mean;
        float rs = rsqrtf(var + 1e-5f);
        float2 g = ((const float2*)gamma)[tid];
        float2 bb = ((const float2*)beta)[tid];
        float2 y;
        y.x = (x.x - mean) * rs * g.x + bb.x;
        y.y = (x.y - mean) * rs * g.y + bb.y;
        ((float2*)(v_out + (size_t)row * DIM))[tid] = y;
    } else {
        const int b = blockIdx.x - nln;
        const float* S = st + (size_t)b * Nd;
        float* D = ds + (size_t)b * Nd;
        float x[4]; float mx = -INFINITY;
#pragma unroll
        for (int i = 0; i < 4; i++) {
            int n = tid + i * 256;
            x[i] = (n < Nd) ? (S[n] + D[n]) : 0.f;
            if (n < Nd) { mx = fmaxf(mx, fabsf(x[i])); D[n] = 0.f; }
        }
        ss[tid] = mx; __syncthreads();
        for (int o = 128; o; o >>= 1) {
            if (tid < o) ss[tid] = fmaxf(ss[tid], ss[tid + o]);
            __syncthreads();
        }
        mx = ss[0]; __syncthreads();
        float e[4]; float s = 0.f;
#pragma unroll
        for (int i = 0; i < 4; i++) {
            int n = tid + i * 256;
            e[i] = (n < Nd) ? expf(fabsf(x[i]) - mx) : 0.f;
            s += e[i];
        }
        ss[tid] = s; __syncthreads();
        for (int o = 128; o; o >>= 1) {
            if (tid < o) ss[tid] += ss[tid + o];
            __syncthreads();
        }
        float inv = 1.f / ss[0];
#pragma unroll
        for (int i = 0; i < 4; i++) {
            int n = tid + i * 256;
            if (n < Nd) {
                float sgn = (x[i] > 0.f) ? 1.f : ((x[i] < 0.f) ? -1.f : 0.f);
                s_out[(size_t)b * Nd + n] = sgn * e[i] * inv;
            }
        }
    }
}

// ---------------- plain row softmax (read attention) -------------------------
__global__ void __launch_bounds__(256)
row_softmax(float* __restrict__ L, int N)
{
    const int row = blockIdx.x, tid = threadIdx.x;
    float* p = L + (size_t)row * N;
    float x[4]; float mx = -INFINITY;
#pragma unroll
    for (int i = 0; i < 4; i++) {
        int n = tid + i * 256;
        x[i] = (n < N) ? p[n] : -INFINITY;
        mx = fmaxf(mx, x[i]);
    }
    __shared__ float sm[256];
    sm[tid] = mx; __syncthreads();
    for (int o = 128; o; o >>= 1) { if (tid < o) sm[tid] = fmaxf(sm[tid], sm[tid + o]); __syncthreads(); }
    mx = sm[0]; __syncthreads();
    float e[4]; float s = 0.f;
#pragma unroll
    for (int i = 0; i < 4; i++) {
        int n = tid + i * 256;
        e[i] = (n < N) ? expf(x[i] - mx) : 0.f;
        s += e[i];
    }
    sm[tid] = s; __syncthreads();
    for (int o = 128; o; o >>= 1) { if (tid < o) sm[tid] += sm[tid + o]; __syncthreads(); }
    float inv = 1.f / sm[0];
#pragma unroll
    for (int i = 0; i < 4; i++) {
        int n = tid + i * 256;
        if (n < N) p[n] = e[i] * inv;
    }
}

// ---------------- host orchestration -----------------------------------------
static inline void launch_atb(const float* A0, const float* A1,
                              const float* B0, const float* B1,
                              float* C, int M, int N, cudaStream_t st)
{
    if (M >= 1024 && N >= 128 && (M % 128) == 0 && (N % 128) == 0)
        atb_big<<<dim3(N / 128, M / 128, BATCH), 256, 67584, st>>>(A0, A1, B0, B1, C, M, N);
    else
        atb_gemm<<<dim3(N / 64, M / 64, BATCH), 256, 0, st>>>(A0, A1, B0, B1, C, M, N);
}

static void run_trans(const float* srcv, const float* srcs, int Ns,
                      const float* dstv, int Nd,
                      const float* W, const float* gatep,
                      const float* st_in, const float* vl_in,
                      float* s_out, float* v_out,
                      const float* gamma, const float* beta,
                      float* q, float* q2, float* kb, float* kb2,
                      float* lg, float* dsb, float* dvb)
{
    qk_gemm_sk<<<dim3(2, Ns / 64 + Nd / 64, BATCH), 256>>>(srcv, dstv, W,
        q, q2, kb, kb2, Ns, Nd);
    launch_atb(q, q2, kb, kb2, lg, Ns, Nd, 0);
    topk_scatter<<<BATCH * Ns / 8, 256>>>(lg, srcv, srcs, dsb, dvb, gatep, Ns, Nd);
    apply_both<<<BATCH * Nd + BATCH, 256>>>(st_in, dsb, s_out, vl_in, dvb, v_out,
                                            gamma, beta, Nd);
}

static void read_level(int l, const float* mv, int S,
                       const float* rr, const float* rp, const float* rg,
                       const float* tok_val, float* out,
                       float* rq, float* kr, float* kr2, float* lgr, float* r,
                       cudaStream_t st)
{
    const size_t RQS = (size_t)3 * BATCH * TOK * RDIM;
    const size_t RQL = (size_t)BATCH * TOK * RDIM;
    qk_gemm_sk<<<dim3(2, S / 64, BATCH), 256, 0, st>>>(mv, mv,
        rr + (size_t)l * 2 * DR, kr, kr2, kr, kr2, 0, S);
    launch_atb(rq + (size_t)l * RQL, rq + RQS + (size_t)l * RQL, kr, kr2,
               lgr, TOK, S, st);
    row_softmax<<<BATCH * TOK, 256, 0, st>>>(lgr, S);
    ab_gemm_tf32<<<dim3(DIM / 128, TOK / 128, BATCH), 256, 0, st>>>(lgr, mv, r,
        nullptr, nullptr, TOK, DIM, S, (long long)TOK * S, (long long)S * DIM,
        (long long)TOK * DIM);
    ab_gemm_tf32<<<dim3(DIM / 128, TOK / 128, BATCH), 256, 0, st>>>(r,
        rp + (size_t)l * DIM * DIM, out, (l == 0) ? tok_val : out, rg + l,
        TOK, DIM, DIM, (long long)TOK * DIM, 0, (long long)TOK * DIM);
}

extern "C" void kernel_launch(void* const* d_in, const int* in_sizes, int n_in,
                              void* d_out, int out_size)
{
    const float* tok_val   = (const float*)d_in[0];
    const float* tok_state = (const float*)d_in[1];
    const float* ms0 = (const float*)d_in[2];
    const float* mv0 = (const float*)d_in[3];
    const float* ms1 = (const float*)d_in[4];
    const float* mv1 = (const float*)d_in[5];
    const float* ms2 = (const float*)d_in[6];
    const float* mv2 = (const float*)d_in[7];
    const float* wr  = (const float*)d_in[8];
    const float* pr  = (const float*)d_in[9];
    const float* lr  = (const float*)d_in[10];
    const float* sr  = (const float*)d_in[11];
    const float* sg  = (const float*)d_in[12];
    const float* lgam = (const float*)d_in[13];
    const float* lbet = (const float*)d_in[14];
    const float* rr  = (const float*)d_in[15];
    const float* rp  = (const float*)d_in[16];
    const float* rg  = (const float*)d_in[17];
    float* out = (float*)d_out;

    static bool _attr = []() {
        cudaFuncSetAttribute(atb_big,
            cudaFuncAttributeMaxDynamicSharedMemorySize, 67584);
        return true;
    }();
    (void)_attr;
    static cudaStream_t s1 = []() {
        cudaStream_t s; cudaStreamCreateWithFlags(&s, cudaStreamNonBlocking);
        return s;
    }();
    static cudaEvent_t ev0 = []() {
        cudaEvent_t e; cudaEventCreateWithFlags(&e, cudaEventDisableTiming);
        return e;
    }();
    static cudaEvent_t ev1 = []() {
        cudaEvent_t e; cudaEventCreateWithFlags(&e, cudaEventDisableTiming);
        return e;
    }();
    static cudaEvent_t ev2 = []() {
        cudaEvent_t e; cudaEventCreateWithFlags(&e, cudaEventDisableTiming);
        return e;
    }();
    static cudaEvent_t evF = []() {
        cudaEvent_t e; cudaEventCreateWithFlags(&e, cudaEventDisableTiming);
        return e;
    }();

    float *q, *q2, *kb, *kb2, *kr, *kr2, *rq, *lg, *lgr, *dsb, *dvb;
    float *s0, *v0, *s1v, *v1, *s2, *v2, *r;
    cudaGetSymbolAddress((void**)&q,   g_q);
    cudaGetSymbolAddress((void**)&q2,  g_q2);
    cudaGetSymbolAddress((void**)&kb,  g_k);
    cudaGetSymbolAddress((void**)&kb2, g_k2);
    cudaGetSymbolAddress((void**)&kr,  g_kr);
    cudaGetSymbolAddress((void**)&kr2, g_kr2);
    cudaGetSymbolAddress((void**)&rq,  g_rq);
    cudaGetSymbolAddress((void**)&lg,  g_lg);
    cudaGetSymbolAddress((void**)&lgr, g_lgr);
    cudaGetSymbolAddress((void**)&dsb, g_ds);
    cudaGetSymbolAddress((void**)&dvb, g_dv);
    cudaGetSymbolAddress((void**)&s0,  g_s0);
    cudaGetSymbolAddress((void**)&v0,  g_v0);
    cudaGetSymbolAddress((void**)&s1v, g_s1);
    cudaGetSymbolAddress((void**)&v1,  g_v1);
    cudaGetSymbolAddress((void**)&s2,  g_s2);
    cudaGetSymbolAddress((void**)&v2,  g_v2);
    cudaGetSymbolAddress((void**)&r,   g_r);

    // head: read-path q projections (depend only on tok_val), delta zero-fill
    rq_gemm_sk<<<dim3(2, TOK / 64, 3 * BATCH), 256>>>(tok_val, rr, rq);
    fill_ds_dv<<<2048, 256>>>(dsb, (float4*)dvb, BATCH * NS0,
                              BATCH * NS0 * DIM / 4);

    // ---- level 0 ----
    run_trans(tok_val, tok_state, TOK, mv0, NS0, wr, nullptr,
              ms0, mv0, s0, v0, lgam + 0 * DIM, lbet + 0 * DIM,
              q, q2, kb, kb2, lg, dsb, dvb);
    run_trans(v0, s0, NS0, v0, NS0, pr + 0 * 2 * DR, nullptr,
              s0, v0, s0, v0, lgam + 0 * DIM, lbet + 0 * DIM,
              q, q2, kb, kb2, lg, dsb, dvb);
    cudaEventRecord(ev0, 0);
    cudaStreamWaitEvent(s1, ev0, 0);
    read_level(0, v0, NS0, rr, rp, rg, tok_val, out, rq, kr, kr2, lgr, r, s1);

    // ---- level 1 ----
    run_trans(v0, s0, NS0, mv1, NS1, lr + 0 * 2 * DR, nullptr,
              ms1, mv1, s1v, v1, lgam + 1 * DIM, lbet + 1 * DIM,
              q, q2, kb, kb2, lg, dsb, dvb);
    run_trans(tok_val, tok_state, TOK, v1, NS1, sr + 0 * 2 * DR, sg + 0,
              s1v, v1, s1v, v1, lgam + 1 * DIM, lbet + 1 * DIM,
              q, q2, kb, kb2, lg, dsb, dvb);
    run_trans(v1, s1v, NS1, v1, NS1, pr + 1 * 2 * DR, nullptr,
              s1v, v1, s1v, v1, lgam + 1 * DIM, lbet + 1 * DIM,
              q, q2, kb, kb2, lg, dsb, dvb);
    cudaEventRecord(ev1, 0);
    cudaStreamWaitEvent(s1, ev1, 0);
    read_level(1, v1, NS1, rr, rp, rg, tok_val, out, rq, kr, kr2, lgr, r, s1);

    // ---- level 2 ----
    run_trans(v1, s1v, NS1, mv2, NS2, lr + 1 * 2 * DR, nullptr,
              ms2, mv2, s2, v2, lgam + 2 * DIM, lbet + 2 * DIM,
              q, q2, kb, kb2, lg, dsb, dvb);
    run_trans(v0, s0, NS0, v2, NS2, sr + 1 * 2 * DR, sg + 1,
              s2, v2, s2, v2, lgam + 2 * DIM, lbet + 2 * DIM,
              q, q2, kb, kb2, lg, dsb, dvb);
    run_trans(v2, s2, NS2, v2, NS2, pr + 2 * 2 * DR, nullptr,
              s2, v2, s2, v2, lgam + 2 * DIM, lbet + 2 * DIM,
              q, q2, kb, kb2, lg, dsb, dvb);
    cudaEventRecord(ev2, 0);
    cudaStreamWaitEvent(s1, ev2, 0);
    read_level(2, v2, NS2, rr, rp, rg, tok_val, out, rq, kr, kr2, lgr, r, s1);

    // join read stream back into the main (captured) stream
    cudaEventRecord(evF, s1);
    cudaStreamWaitEvent((cudaStream_t)0, evF, 0);
}

// round 12
// speedup vs baseline: 1.1957x; 1.1957x over previous
#include <cuda_runtime.h>
#include <math.h>
#include <stdint.h>

#define BATCH 4
#define TOK   1024
#define DIM   512
#define RDIM  64
#define NS0   1024
#define NS1   256
#define NS2   64
#define DR    (DIM*RDIM)   /* 32768 */

// ---------------- scratch (static device memory; no cudaMalloc) -------------
__device__ float g_q [BATCH*TOK*RDIM];
__device__ float g_q2[BATCH*TOK*RDIM];
__device__ float g_k [BATCH*NS0*RDIM];
__device__ float g_k2[BATCH*NS0*RDIM];
__device__ float g_kr [BATCH*NS0*RDIM];     // read-path k partials (stream s1)
__device__ float g_kr2[BATCH*NS0*RDIM];
__device__ float g_rq[2*3*BATCH*TOK*RDIM];  // [split][route][b] read-path q parts
__device__ float g_lg [BATCH*TOK*NS0];      // transition logits (16MB)
__device__ float g_lgr[BATCH*TOK*NS0];      // read-path logits/attn (16MB)
__device__ float g_ds[BATCH*NS0];
__device__ float g_dv[BATCH*NS0*DIM];
__device__ float g_s0[BATCH*NS0];
__device__ float g_v0[BATCH*NS0*DIM];
__device__ float g_s1[BATCH*NS1];
__device__ float g_v1[BATCH*NS1*DIM];
__device__ float g_s2[BATCH*NS2];
__device__ float g_v2[BATCH*NS2*DIM];
__device__ float g_r [BATCH*TOK*DIM];

// ---------------- tf32 helpers ------------------------------------------------
__device__ __forceinline__ uint32_t f2tf32(float x) {
    uint32_t u;
    asm("cvt.rna.tf32.f32 %0, %1;" : "=r"(u) : "f"(x));
    return u;
}
__device__ __forceinline__ void mma_tf32(float* c, uint32_t a0, uint32_t a1,
                                         uint32_t a2, uint32_t a3,
                                         uint32_t b0, uint32_t b1) {
    asm volatile(
        "mma.sync.aligned.m16n8k8.row.col.f32.tf32.tf32.f32 "
        "{%0,%1,%2,%3}, {%4,%5,%6,%7}, {%8,%9}, {%0,%1,%2,%3};"
        : "+f"(c[0]), "+f"(c[1]), "+f"(c[2]), "+f"(c[3])
        : "r"(a0), "r"(a1), "r"(a2), "r"(a3), "r"(b0), "r"(b1));
}

// order-preserving monotone encoding of float (total order, -inf lowest)
__device__ __forceinline__ uint32_t fmono(float x) {
    uint32_t u = __float_as_uint(x);
    return (u & 0x80000000u) ? ~u : (u | 0x80000000u);
}
__device__ __forceinline__ float fdemono(uint32_t k) {
    uint32_t u = (k & 0x80000000u) ? (k & 0x7fffffffu) : ~k;
    return __uint_as_float(u);
}

// ---------------- fused zero of ds + dv (head only) --------------------------
__global__ void fill_ds_dv(float* __restrict__ ds, float4* __restrict__ dv4,
                           int nds, int ndv4) {
    const int stride = gridDim.x * blockDim.x;
    const int i0 = blockIdx.x * blockDim.x + threadIdx.x;
    for (int j = i0; j < nds; j += stride) ds[j] = 0.f;
    const float4 z = make_float4(0.f, 0.f, 0.f, 0.f);
    for (int j = i0; j < ndv4; j += stride) dv4[j] = z;
}

// ============ split-K projection GEMM core (64x64 tile, K=256 slice) =========
__device__ __forceinline__ void proj_body(const float* __restrict__ Ab,
                                          const float* __restrict__ Bb,
                                          float* __restrict__ Cb, int m0)
{
    __shared__ float sAt[16][68];
    __shared__ float sBt[16][68];
    const int tid = threadIdx.x;
    const int tx = tid & 15, ty = tid >> 4;
    const int arow = tid >> 2, ak4 = (tid & 3) << 2;
    const int bk = tid >> 4, bn4 = (tid & 15) << 2;

    float acc[4][4];
#pragma unroll
    for (int i = 0; i < 4; i++)
#pragma unroll
        for (int j = 0; j < 4; j++) acc[i][j] = 0.f;

    float4 pa = *(const float4*)(Ab + (size_t)(m0 + arow) * DIM + ak4);
    float4 pb = *(const float4*)(Bb + (size_t)bk * RDIM + bn4);
    sAt[ak4 + 0][arow] = pa.x; sAt[ak4 + 1][arow] = pa.y;
    sAt[ak4 + 2][arow] = pa.z; sAt[ak4 + 3][arow] = pa.w;
    *(float4*)&sBt[bk][bn4] = pb;
    __syncthreads();

    for (int k0 = 16; k0 < 256; k0 += 16) {
        pa = *(const float4*)(Ab + (size_t)(m0 + arow) * DIM + k0 + ak4);
        pb = *(const float4*)(Bb + (size_t)(k0 + bk) * RDIM + bn4);
#pragma unroll
        for (int kk = 0; kk < 16; kk++) {
            float4 a  = *(const float4*)&sAt[kk][ty << 2];
            float4 bq = *(const float4*)&sBt[kk][tx << 2];
            float aa[4] = {a.x, a.y, a.z, a.w};
            float bb[4] = {bq.x, bq.y, bq.z, bq.w};
#pragma unroll
            for (int i = 0; i < 4; i++)
#pragma unroll
                for (int j = 0; j < 4; j++) acc[i][j] += aa[i] * bb[j];
        }
        __syncthreads();
        sAt[ak4 + 0][arow] = pa.x; sAt[ak4 + 1][arow] = pa.y;
        sAt[ak4 + 2][arow] = pa.z; sAt[ak4 + 3][arow] = pa.w;
        *(float4*)&sBt[bk][bn4] = pb;
        __syncthreads();
    }
#pragma unroll
    for (int kk = 0; kk < 16; kk++) {
        float4 a  = *(const float4*)&sAt[kk][ty << 2];
        float4 bq = *(const float4*)&sBt[kk][tx << 2];
        float aa[4] = {a.x, a.y, a.z, a.w};
        float bb[4] = {bq.x, bq.y, bq.z, bq.w};
#pragma unroll
        for (int i = 0; i < 4; i++)
#pragma unroll
            for (int j = 0; j < 4; j++) acc[i][j] += aa[i] * bb[j];
    }
#pragma unroll
    for (int i = 0; i < 4; i++) {
        size_t idx = (size_t)(m0 + (ty << 2) + i) * RDIM + (tx << 2);
        *(float4*)(Cb + idx) = make_float4(acc[i][0], acc[i][1], acc[i][2], acc[i][3]);
    }
}

// dual q/k projection, split-K=2. grid (2, Ns/64 + Nd/64, BATCH)
__global__ void __launch_bounds__(256)
qk_gemm_sk(const float* __restrict__ src, const float* __restrict__ dst,
           const float* __restrict__ W,
           float* __restrict__ q0, float* __restrict__ q1,
           float* __restrict__ k0, float* __restrict__ k1, int Ns, int Nd)
{
    const int b = blockIdx.z, s = blockIdx.x;
    const int nyq = Ns >> 6;
    const bool isQ = (int)blockIdx.y < nyq;
    const float* Ab = (isQ ? src + (size_t)b * Ns * DIM
                           : dst + (size_t)b * Nd * DIM) + s * 256;
    const float* Bb = (isQ ? W : W + DR) + (size_t)s * 256 * RDIM;
    float* Cb = isQ ? (s ? q1 : q0) + (size_t)b * Ns * RDIM
                    : (s ? k1 : k0) + (size_t)b * Nd * RDIM;
    const int m0 = (isQ ? blockIdx.y : blockIdx.y - nyq) * 64;
    proj_body(Ab, Bb, Cb, m0);
}

// read-path q projections: 3 routes in one launch. grid (2, TOK/64, 3*BATCH)
__global__ void __launch_bounds__(256)
rq_gemm_sk(const float* __restrict__ tok, const float* __restrict__ rr,
           float* __restrict__ rqp)
{
    const int s = blockIdx.x;
    const int l = blockIdx.z / BATCH, b = blockIdx.z % BATCH;
    const float* Ab = tok + (size_t)b * TOK * DIM + s * 256;
    const float* Bb = rr + (size_t)l * 2 * DR + (size_t)s * 256 * RDIM;
    float* Cb = rqp + ((size_t)(s * 3 + l) * BATCH + b) * TOK * RDIM;
    proj_body(Ab, Bb, Cb, blockIdx.y * 64);
}

// ---------------- logits GEMM (64x64 tile, small cases) ----------------------
__global__ void __launch_bounds__(256)
atb_gemm(const float* __restrict__ A0, const float* __restrict__ A1,
         const float* __restrict__ B0, const float* __restrict__ B1,
         float* __restrict__ C, int M, int N)
{
    __shared__ float sAt[64][68];
    __shared__ float sBt[64][68];
    const int b = blockIdx.z;
    const size_t aoff = (size_t)b * M * 64;
    const size_t boff = (size_t)b * N * 64;
    const int m0 = blockIdx.y * 64, n0 = blockIdx.x * 64;
    const int tid = threadIdx.x;
    const int tx = tid & 15, ty = tid >> 4;
    const int row = tid >> 2, q4 = (tid & 3) << 2;

#pragma unroll
    for (int c = 0; c < 4; c++) {
        const int kk0 = q4 + c * 16;
        const size_t ai = aoff + (size_t)(m0 + row) * 64 + kk0;
        const size_t bi = boff + (size_t)(n0 + row) * 64 + kk0;
        float4 av = *(const float4*)(A0 + ai);
        float4 a1 = *(const float4*)(A1 + ai);
        float4 bv = *(const float4*)(B0 + bi);
        float4 b1 = *(const float4*)(B1 + bi);
        av.x += a1.x; av.y += a1.y; av.z += a1.z; av.w += a1.w;
        bv.x += b1.x; bv.y += b1.y; bv.z += b1.z; bv.w += b1.w;
        sAt[kk0 + 0][row] = av.x; sAt[kk0 + 1][row] = av.y;
        sAt[kk0 + 2][row] = av.z; sAt[kk0 + 3][row] = av.w;
        sBt[kk0 + 0][row] = bv.x; sBt[kk0 + 1][row] = bv.y;
        sBt[kk0 + 2][row] = bv.z; sBt[kk0 + 3][row] = bv.w;
    }
    __syncthreads();

    float acc[4][4];
#pragma unroll
    for (int i = 0; i < 4; i++)
#pragma unroll
        for (int j = 0; j < 4; j++) acc[i][j] = 0.f;
#pragma unroll 16
    for (int kk = 0; kk < 64; kk++) {
        float4 a  = *(const float4*)&sAt[kk][ty << 2];
        float4 bq = *(const float4*)&sBt[kk][tx << 2];
        float aa[4] = {a.x, a.y, a.z, a.w};
        float bb[4] = {bq.x, bq.y, bq.z, bq.w};
#pragma unroll
        for (int i = 0; i < 4; i++)
#pragma unroll
            for (int j = 0; j < 4; j++) acc[i][j] += aa[i] * bb[j];
    }
#pragma unroll
    for (int i = 0; i < 4; i++) {
        size_t idx = (size_t)b * M * N + (size_t)(m0 + (ty << 2) + i) * N + n0 + (tx << 2);
        float4 cv = make_float4(0.125f * acc[i][0], 0.125f * acc[i][1],
                                0.125f * acc[i][2], 0.125f * acc[i][3]);
        *(float4*)(C + idx) = cv;
    }
}

// ---------------- logits GEMM big: 128x128 tile, 8x8 micro, K=64 resident ----
__global__ void __launch_bounds__(256)
atb_big(const float* __restrict__ A0, const float* __restrict__ A1,
        const float* __restrict__ B0, const float* __restrict__ B1,
        float* __restrict__ C, int M, int N)
{
    extern __shared__ float sm[];
    float (*sAt)[132] = (float(*)[132])sm;
    float (*sBt)[132] = (float(*)[132])(sm + 64 * 132);
    const int b = blockIdx.z;
    const size_t aoff = (size_t)b * M * 64;
    const size_t boff = (size_t)b * N * 64;
    const int m0 = blockIdx.y * 128, n0 = blockIdx.x * 128;
    const int tid = threadIdx.x;
    const int tx = tid & 15, ty = tid >> 4;

    for (int idx = tid; idx < 2048; idx += 256) {
        const int row = idx >> 4, kq = (idx & 15) << 2;
        const size_t ai = aoff + (size_t)(m0 + row) * 64 + kq;
        const size_t bi = boff + (size_t)(n0 + row) * 64 + kq;
        float4 av = *(const float4*)(A0 + ai);
        float4 a1 = *(const float4*)(A1 + ai);
        float4 bv = *(const float4*)(B0 + bi);
        float4 b1 = *(const float4*)(B1 + bi);
        av.x += a1.x; av.y += a1.y; av.z += a1.z; av.w += a1.w;
        bv.x += b1.x; bv.y += b1.y; bv.z += b1.z; bv.w += b1.w;
        sAt[kq + 0][row] = av.x; sAt[kq + 1][row] = av.y;
        sAt[kq + 2][row] = av.z; sAt[kq + 3][row] = av.w;
        sBt[kq + 0][row] = bv.x; sBt[kq + 1][row] = bv.y;
        sBt[kq + 2][row] = bv.z; sBt[kq + 3][row] = bv.w;
    }
    __syncthreads();

    float acc[8][8];
#pragma unroll
    for (int i = 0; i < 8; i++)
#pragma unroll
        for (int j = 0; j < 8; j++) acc[i][j] = 0.f;

#pragma unroll 8
    for (int kk = 0; kk < 64; kk++) {
        float4 a0 = *(const float4*)&sAt[kk][ty << 2];
        float4 a1 = *(const float4*)&sAt[kk][64 + (ty << 2)];
        float4 b0 = *(const float4*)&sBt[kk][tx << 2];
        float4 b1 = *(const float4*)&sBt[kk][64 + (tx << 2)];
        float av[8] = {a0.x, a0.y, a0.z, a0.w, a1.x, a1.y, a1.z, a1.w};
        float bv[8] = {b0.x, b0.y, b0.z, b0.w, b1.x, b1.y, b1.z, b1.w};
#pragma unroll
        for (int i = 0; i < 8; i++)
#pragma unroll
            for (int j = 0; j < 8; j++) acc[i][j] += av[i] * bv[j];
    }

#pragma unroll
    for (int ih = 0; ih < 2; ih++)
#pragma unroll
        for (int i = 0; i < 4; i++) {
            const int m = m0 + ih * 64 + (ty << 2) + i;
            const size_t base = (size_t)b * M * N + (size_t)m * N + n0;
#pragma unroll
            for (int jh = 0; jh < 2; jh++) {
                const int r = ih * 4 + i;
                float4 cv = make_float4(0.125f * acc[r][jh * 4 + 0],
                                        0.125f * acc[r][jh * 4 + 1],
                                        0.125f * acc[r][jh * 4 + 2],
                                        0.125f * acc[r][jh * 4 + 3]);
                *(float4*)(C + base + jh * 64 + (tx << 2)) = cv;
            }
        }
}

// ---------------- tf32 tensor-core GEMM: 128x128 tile, warp 64x32 ------------
__global__ void __launch_bounds__(256)
ab_gemm_tf32(const float* __restrict__ A, const float* __restrict__ Bm,
             float* __restrict__ C, const float* __restrict__ Cinit,
             const float* __restrict__ gatep,
             int M, int N, int K,
             long long strA, long long strB, long long strC)
{
    __shared__ uint32_t sA[16][136];
    __shared__ uint32_t sB[16][136];
    const int b = blockIdx.z;
    const float* Ab = A  + (size_t)b * strA;
    const float* Bb = Bm + (size_t)b * strB;
    const int m0 = blockIdx.y * 128, n0 = blockIdx.x * 128;
    const int tid = threadIdx.x, lane = tid & 31, warp = tid >> 5;
    const int wm = (warp >> 2) * 64, wn = (warp & 3) * 32;
    const int gid = lane >> 2, tid4 = lane & 3;
    const int arow = tid >> 1, ak = (tid & 1) * 8;
    const int bk = tid >> 4, bn = (tid & 15) * 8;

    float acc[4][4][4];
#pragma unroll
    for (int mi = 0; mi < 4; mi++)
#pragma unroll
        for (int ni = 0; ni < 4; ni++)
#pragma unroll
            for (int t = 0; t < 4; t++) acc[mi][ni][t] = 0.f;

    float4 pa0, pa1, pb0, pb1;
    {
        const float* ap = Ab + (size_t)(m0 + arow) * K + ak;
        pa0 = *(const float4*)ap; pa1 = *(const float4*)(ap + 4);
        const float* bp = Bb + (size_t)bk * N + n0 + bn;
        pb0 = *(const float4*)bp; pb1 = *(const float4*)(bp + 4);
        sA[ak + 0][arow] = f2tf32(pa0.x); sA[ak + 1][arow] = f2tf32(pa0.y);
        sA[ak + 2][arow] = f2tf32(pa0.z); sA[ak + 3][arow] = f2tf32(pa0.w);
        sA[ak + 4][arow] = f2tf32(pa1.x); sA[ak + 5][arow] = f2tf32(pa1.y);
        sA[ak + 6][arow] = f2tf32(pa1.z); sA[ak + 7][arow] = f2tf32(pa1.w);
        sB[bk][bn + 0] = f2tf32(pb0.x); sB[bk][bn + 1] = f2tf32(pb0.y);
        sB[bk][bn + 2] = f2tf32(pb0.z); sB[bk][bn + 3] = f2tf32(pb0.w);
        sB[bk][bn + 4] = f2tf32(pb1.x); sB[bk][bn + 5] = f2tf32(pb1.y);
        sB[bk][bn + 6] = f2tf32(pb1.z); sB[bk][bn + 7] = f2tf32(pb1.w);
        __syncthreads();
    }

#define TF32_COMPUTE_TILE                                                     \
    _Pragma("unroll")                                                         \
    for (int ks = 0; ks < 2; ks++) {                                          \
        const int kk = ks * 8;                                                \
        uint32_t af[4][4], bf[4][2];                                          \
        _Pragma("unroll")                                                     \
        for (int mi = 0; mi < 4; mi++) {                                      \
            const int m = wm + mi * 16 + gid;                                 \
            af[mi][0] = sA[kk + tid4][m];                                     \
            af[mi][1] = sA[kk + tid4][m + 8];                                 \
            af[mi][2] = sA[kk + 4 + tid4][m];                                 \
            af[mi][3] = sA[kk + 4 + tid4][m + 8];                             \
        }                                                                     \
        _Pragma("unroll")                                                     \
        for (int ni = 0; ni < 4; ni++) {                                      \
            const int n = wn + ni * 8 + gid;                                  \
            bf[ni][0] = sB[kk + tid4][n];                                     \
            bf[ni][1] = sB[kk + 4 + tid4][n];                                 \
        }                                                                     \
        _Pragma("unroll")                                                     \
        for (int mi = 0; mi < 4; mi++)                                        \
            _Pragma("unroll")                                                 \
            for (int ni = 0; ni < 4; ni++)                                    \
                mma_tf32(acc[mi][ni], af[mi][0], af[mi][1], af[mi][2],        \
                         af[mi][3], bf[ni][0], bf[ni][1]);                    \
    }

    for (int k0 = 16; k0 < K; k0 += 16) {
        const float* ap = Ab + (size_t)(m0 + arow) * K + k0 + ak;
        pa0 = *(const float4*)ap; pa1 = *(const float4*)(ap + 4);
        const float* bp = Bb + (size_t)(k0 + bk) * N + n0 + bn;
        pb0 = *(const float4*)bp; pb1 = *(const float4*)(bp + 4);
        TF32_COMPUTE_TILE
        __syncthreads();
        sA[ak + 0][arow] = f2tf32(pa0.x); sA[ak + 1][arow] = f2tf32(pa0.y);
        sA[ak + 2][arow] = f2tf32(pa0.z); sA[ak + 3][arow] = f2tf32(pa0.w);
        sA[ak + 4][arow] = f2tf32(pa1.x); sA[ak + 5][arow] = f2tf32(pa1.y);
        sA[ak + 6][arow] = f2tf32(pa1.z); sA[ak + 7][arow] = f2tf32(pa1.w);
        sB[bk][bn + 0] = f2tf32(pb0.x); sB[bk][bn + 1] = f2tf32(pb0.y);
        sB[bk][bn + 2] = f2tf32(pb0.z); sB[bk][bn + 3] = f2tf32(pb0.w);
        sB[bk][bn + 4] = f2tf32(pb1.x); sB[bk][bn + 5] = f2tf32(pb1.y);
        sB[bk][bn + 6] = f2tf32(pb1.z); sB[bk][bn + 7] = f2tf32(pb1.w);
        __syncthreads();
    }
    TF32_COMPUTE_TILE
#undef TF32_COMPUTE_TILE

    float alpha = 1.f;
    if (gatep) alpha = 1.f / (1.f + expf(-*gatep));
#pragma unroll
    for (int mi = 0; mi < 4; mi++) {
#pragma unroll
        for (int ni = 0; ni < 4; ni++) {
            const int r0 = m0 + wm + mi * 16 + gid;
            const int cc = n0 + wn + ni * 8 + 2 * tid4;
            const size_t i0 = (size_t)b * strC + (size_t)r0 * N + cc;
            const size_t i1 = (size_t)b * strC + (size_t)(r0 + 8) * N + cc;
            float2 v0 = make_float2(alpha * acc[mi][ni][0], alpha * acc[mi][ni][1]);
            float2 v1 = make_float2(alpha * acc[mi][ni][2], alpha * acc[mi][ni][3]);
            if (Cinit) {
                float2 c0 = *(const float2*)(Cinit + i0);
                float2 c1 = *(const float2*)(Cinit + i1);
                v0.x += c0.x; v0.y += c0.y;
                v1.x += c1.x; v1.y += c1.y;
            }
            *(float2*)(C + i0) = v0;
            *(float2*)(C + i1) = v1;
        }
    }
}

// ---------------- top-k + signed softmax + softplus-state scatter ------------
// one warp per source row. tie-break matches jax.lax.top_k (lower index first).
// Scan: R10 fully-unrolled bubble insert (register-resident; early-exit variant
// spilled to local memory and regressed). Merge: smem lists + redux argmax.
__global__ void __launch_bounds__(256)
topk_scatter(const float* __restrict__ logits, const float* __restrict__ srcval,
             const float* __restrict__ srcstate, float* __restrict__ ds,
             float* __restrict__ dv, const float* __restrict__ gatep,
             int Ns, int Nd)
{
    __shared__ uint32_t skey[8][16][32];
    __shared__ int      sidx[8][16][32];
    const int warp = threadIdx.x >> 5, lane = threadIdx.x & 31;
    const int row = blockIdx.x * 8 + warp;      // = b*Ns + s
    const int b = row / Ns;
    const float* L = logits + (size_t)row * Nd;

    float tv[16]; int ti[16];
#pragma unroll
    for (int i = 0; i < 16; i++) { tv[i] = -INFINITY; ti[i] = 0x40000000; }

    // per-lane top-16 over strided candidates (sorted ascending)
    for (int n = lane; n < Nd; n += 32) {
        float c = L[n];
        if (c > tv[0]) {
            tv[0] = c; ti[0] = n;
#pragma unroll
            for (int i = 0; i < 15; i++) {
                if (tv[i] > tv[i + 1]) {
                    float t = tv[i]; tv[i] = tv[i + 1]; tv[i + 1] = t;
                    int u = ti[i]; ti[i] = ti[i + 1]; ti[i + 1] = u;
                }
            }
        }
    }

    // spill lane-private sorted list (descending) to shared for dynamic idx
#pragma unroll
    for (int j = 0; j < 16; j++) {
        skey[warp][j][lane] = fmono(tv[15 - j]);
        sidx[warp][j][lane] = ti[15 - j];
    }

    // merge: 16x [redux-max on keys, redux-min on idx for tie-break, pop]
    float sel_v = 0.f; int sel_i = 0;
    int pos = 0;
#pragma unroll 1
    for (int it = 0; it < 16; ++it) {
        uint32_t key = skey[warp][pos][lane];
        int idx = sidx[warp][pos][lane];
        uint32_t mx = __reduce_max_sync(0xffffffffu, key);
        unsigned cand = (key == mx) ? (unsigned)idx : 0x7fffffffu;
        unsigned mni = __reduce_min_sync(0xffffffffu, cand);
        pos += (key == mx && (unsigned)idx == mni) ? 1 : 0;
        if (lane == it) { sel_v = fdemono(mx); sel_i = (int)mni; }
    }

    // signed softmax over the 16 selected values (lanes 0..15 own one each)
    float a_ = (lane < 16) ? fabsf(sel_v) : -INFINITY;
    float m = a_;
#pragma unroll
    for (int o = 16; o; o >>= 1) m = fmaxf(m, __shfl_xor_sync(0xffffffffu, m, o));
    float e = (lane < 16) ? expf(a_ - m) : 0.f;
    float ssum = e;
#pragma unroll
    for (int o = 16; o; o >>= 1) ssum += __shfl_xor_sync(0xffffffffu, ssum, o);
    float sgn = (sel_v > 0.f) ? 1.f : ((sel_v < 0.f) ? -1.f : 0.f);
    float st = srcstate[row];
    float sp = fmaxf(st, 0.f) + log1pf(expf(-fabsf(st)));
    float gate = 1.f;
    if (gatep) gate = 1.f / (1.f + expf(-*gatep));
    float cc = sgn * (e / ssum) * sp * gate;

    if (lane < 16) atomicAdd(ds + (size_t)b * Nd + sel_i, cc);

    const float* srow = srcval + (size_t)row * DIM;
    float4 xr[4];
#pragma unroll
    for (int t = 0; t < 4; t++)
        xr[t] = *(const float4*)(srow + (lane << 2) + (t << 7));
#pragma unroll 1
    for (int i = 0; i < 16; i++) {
        float ci = __shfl_sync(0xffffffffu, cc, i);
        int   di = __shfl_sync(0xffffffffu, sel_i, i);
        float* dst = dv + ((size_t)b * Nd + di) * DIM + (lane << 2);
#pragma unroll
        for (int t = 0; t < 4; t++) {
            asm volatile("red.global.add.v4.f32 [%0], {%1, %2, %3, %4};"
                         :: "l"(dst + (t << 7)),
                            "f"(ci * xr[t].x), "f"(ci * xr[t].y),
                            "f"(ci * xr[t].z), "f"(ci * xr[t].w)
                         : "memory");
        }
    }
}

// ---------------- fused apply: LN rows + signed-softmax state (self-clean) ---
__global__ void __launch_bounds__(256)
apply_both(const float* __restrict__ st, float* __restrict__ ds,
           float* __restrict__ s_out,
           const float* __restrict__ val, float* __restrict__ dvv,
           float* __restrict__ v_out,
           const float* __restrict__ gamma, const float* __restrict__ beta,
           int Nd)
{
    const int tid = threadIdx.x;
    const int nln = BATCH * Nd;
    __shared__ float ss[256], sq[256];
    if ((int)blockIdx.x < nln) {
        const int row = blockIdx.x;
        float2 x = ((const float2*)(val + (size_t)row * DIM))[tid];
        float2 d = ((float2*)(dvv + (size_t)row * DIM))[tid];
        ((float2*)(dvv + (size_t)row * DIM))[tid] = make_float2(0.f, 0.f);
        x.x += d.x; x.y += d.y;
        ss[tid] = x.x + x.y;
        sq[tid] = x.x * x.x + x.y * x.y;
        __syncthreads();
        for (int o = 128; o; o >>= 1) {
            if (tid < o) { ss[tid] += ss[tid + o]; sq[tid] += sq[tid + o]; }
            __syncthreads();
        }
        float mean = ss[0] * (1.f / DIM);
        float var = sq[0] * (1.f / DIM) - mean * mean;
        float rs = rsqrtf(var + 1e-5f);
        float2 g = ((const float2*)gamma)[tid];
        float2 bb = ((const float2*)beta)[tid];
        float2 y;
        y.x = (x.x - mean) * rs * g.x + bb.x;
        y.y = (x.y - mean) * rs * g.y + bb.y;
        ((float2*)(v_out + (size_t)row * DIM))[tid] = y;
    } else {
        const int b = blockIdx.x - nln;
        const float* S = st + (size_t)b * Nd;
        float* D = ds + (size_t)b * Nd;
        float x[4]; float mx = -INFINITY;
#pragma unroll
        for (int i = 0; i < 4; i++) {
            int n = tid + i * 256;
            x[i] = (n < Nd) ? (S[n] + D[n]) : 0.f;
            if (n < Nd) { mx = fmaxf(mx, fabsf(x[i])); D[n] = 0.f; }
        }
        ss[tid] = mx; __syncthreads();
        for (int o = 128; o; o >>= 1) {
            if (tid < o) ss[tid] = fmaxf(ss[tid], ss[tid + o]);
            __syncthreads();
        }
        mx = ss[0]; __syncthreads();
        float e[4]; float s = 0.f;
#pragma unroll
        for (int i = 0; i < 4; i++) {
            int n = tid + i * 256;
            e[i] = (n < Nd) ? expf(fabsf(x[i]) - mx) : 0.f;
            s += e[i];
        }
        ss[tid] = s; __syncthreads();
        for (int o = 128; o; o >>= 1) {
            if (tid < o) ss[tid] += ss[tid + o];
            __syncthreads();
        }
        float inv = 1.f / ss[0];
#pragma unroll
        for (int i = 0; i < 4; i++) {
            int n = tid + i * 256;
            if (n < Nd) {
                float sgn = (x[i] > 0.f) ? 1.f : ((x[i] < 0.f) ? -1.f : 0.f);
                s_out[(size_t)b * Nd + n] = sgn * e[i] * inv;
            }
        }
    }
}

// ---------------- plain row softmax (read attention) -------------------------
__global__ void __launch_bounds__(256)
row_softmax(float* __restrict__ L, int N)
{
    const int row = blockIdx.x, tid = threadIdx.x;
    float* p = L + (size_t)row * N;
    float x[4]; float mx = -INFINITY;
#pragma unroll
    for (int i = 0; i < 4; i++) {
        int n = tid + i * 256;
        x[i] = (n < N) ? p[n] : -INFINITY;
        mx = fmaxf(mx, x[i]);
    }
    __shared__ float sm[256];
    sm[tid] = mx; __syncthreads();
    for (int o = 128; o; o >>= 1) { if (tid < o) sm[tid] = fmaxf(sm[tid], sm[tid + o]); __syncthreads(); }
    mx = sm[0]; __syncthreads();
    float e[4]; float s = 0.f;
#pragma unroll
    for (int i = 0; i < 4; i++) {
        int n = tid + i * 256;
        e[i] = (n < N) ? expf(x[i] - mx) : 0.f;
        s += e[i];
    }
    sm[tid] = s; __syncthreads();
    for (int o = 128; o; o >>= 1) { if (tid < o) sm[tid] += sm[tid + o]; __syncthreads(); }
    float inv = 1.f / sm[0];
#pragma unroll
    for (int i = 0; i < 4; i++) {
        int n = tid + i * 256;
        if (n < N) p[n] = e[i] * inv;
    }
}

// ---------------- host orchestration -----------------------------------------
static inline void launch_atb(const float* A0, const float* A1,
                              const float* B0, const float* B1,
                              float* C, int M, int N, cudaStream_t st)
{
    if (M >= 1024 && N >= 128 && (M % 128) == 0 && (N % 128) == 0)
        atb_big<<<dim3(N / 128, M / 128, BATCH), 256, 67584, st>>>(A0, A1, B0, B1, C, M, N);
    else
        atb_gemm<<<dim3(N / 64, M / 64, BATCH), 256, 0, st>>>(A0, A1, B0, B1, C, M, N);
}

static void run_trans(const float* srcv, const float* srcs, int Ns,
                      const float* dstv, int Nd,
                      const float* W, const float* gatep,
                      const float* st_in, const float* vl_in,
                      float* s_out, float* v_out,
                      const float* gamma, const float* beta,
                      float* q, float* q2, float* kb, float* kb2,
                      float* lg, float* dsb, float* dvb)
{
    qk_gemm_sk<<<dim3(2, Ns / 64 + Nd / 64, BATCH), 256>>>(srcv, dstv, W,
        q, q2, kb, kb2, Ns, Nd);
    launch_atb(q, q2, kb, kb2, lg, Ns, Nd, 0);
    topk_scatter<<<BATCH * Ns / 8, 256>>>(lg, srcv, srcs, dsb, dvb, gatep, Ns, Nd);
    apply_both<<<BATCH * Nd + BATCH, 256>>>(st_in, dsb, s_out, vl_in, dvb, v_out,
                                            gamma, beta, Nd);
}

static void read_level(int l, const float* mv, int S,
                       const float* rr, const float* rp, const float* rg,
                       const float* tok_val, float* out,
                       float* rq, float* kr, float* kr2, float* lgr, float* r,
                       cudaStream_t st)
{
    const size_t RQS = (size_t)3 * BATCH * TOK * RDIM;
    const size_t RQL = (size_t)BATCH * TOK * RDIM;
    qk_gemm_sk<<<dim3(2, S / 64, BATCH), 256, 0, st>>>(mv, mv,
        rr + (size_t)l * 2 * DR, kr, kr2, kr, kr2, 0, S);
    launch_atb(rq + (size_t)l * RQL, rq + RQS + (size_t)l * RQL, kr, kr2,
               lgr, TOK, S, st);
    row_softmax<<<BATCH * TOK, 256, 0, st>>>(lgr, S);
    ab_gemm_tf32<<<dim3(DIM / 128, TOK / 128, BATCH), 256, 0, st>>>(lgr, mv, r,
        nullptr, nullptr, TOK, DIM, S, (long long)TOK * S, (long long)S * DIM,
        (long long)TOK * DIM);
    ab_gemm_tf32<<<dim3(DIM / 128, TOK / 128, BATCH), 256, 0, st>>>(r,
        rp + (size_t)l * DIM * DIM, out, (l == 0) ? tok_val : out, rg + l,
        TOK, DIM, DIM, (long long)TOK * DIM, 0, (long long)TOK * DIM);
}

extern "C" void kernel_launch(void* const* d_in, const int* in_sizes, int n_in,
                              void* d_out, int out_size)
{
    const float* tok_val   = (const float*)d_in[0];
    const float* tok_state = (const float*)d_in[1];
    const float* ms0 = (const float*)d_in[2];
    const float* mv0 = (const float*)d_in[3];
    const float* ms1 = (const float*)d_in[4];
    const float* mv1 = (const float*)d_in[5];
    const float* ms2 = (const float*)d_in[6];
    const float* mv2 = (const float*)d_in[7];
    const float* wr  = (const float*)d_in[8];
    const float* pr  = (const float*)d_in[9];
    const float* lr  = (const float*)d_in[10];
    const float* sr  = (const float*)d_in[11];
    const float* sg  = (const float*)d_in[12];
    const float* lgam = (const float*)d_in[13];
    const float* lbet = (const float*)d_in[14];
    const float* rr  = (const float*)d_in[15];
    const float* rp  = (const float*)d_in[16];
    const float* rg  = (const float*)d_in[17];
    float* out = (float*)d_out;

    static bool _attr = []() {
        cudaFuncSetAttribute(atb_big,
            cudaFuncAttributeMaxDynamicSharedMemorySize, 67584);
        return true;
    }();
    (void)_attr;
    static cudaStream_t s1 = []() {
        cudaStream_t s; cudaStreamCreateWithFlags(&s, cudaStreamNonBlocking);
        return s;
    }();
    static cudaEvent_t evH = []() {
        cudaEvent_t e; cudaEventCreateWithFlags(&e, cudaEventDisableTiming);
        return e;
    }();
    static cudaEvent_t evFill = []() {
        cudaEvent_t e; cudaEventCreateWithFlags(&e, cudaEventDisableTiming);
        return e;
    }();
    static cudaEvent_t ev0 = []() {
        cudaEvent_t e; cudaEventCreateWithFlags(&e, cudaEventDisableTiming);
        return e;
    }();
    static cudaEvent_t ev1 = []() {
        cudaEvent_t e; cudaEventCreateWithFlags(&e, cudaEventDisableTiming);
        return e;
    }();
    static cudaEvent_t ev2 = []() {
        cudaEvent_t e; cudaEventCreateWithFlags(&e, cudaEventDisableTiming);
        return e;
    }();
    static cudaEvent_t evF = []() {
        cudaEvent_t e; cudaEventCreateWithFlags(&e, cudaEventDisableTiming);
        return e;
    }();

    float *q, *q2, *kb, *kb2, *kr, *kr2, *rq, *lg, *lgr, *dsb, *dvb;
    float *s0, *v0, *s1v, *v1, *s2, *v2, *r;
    cudaGetSymbolAddress((void**)&q,   g_q);
    cudaGetSymbolAddress((void**)&q2,  g_q2);
    cudaGetSymbolAddress((void**)&kb,  g_k);
    cudaGetSymbolAddress((void**)&kb2, g_k2);
    cudaGetSymbolAddress((void**)&kr,  g_kr);
    cudaGetSymbolAddress((void**)&kr2, g_kr2);
    cudaGetSymbolAddress((void**)&rq,  g_rq);
    cudaGetSymbolAddress((void**)&lg,  g_lg);
    cudaGetSymbolAddress((void**)&lgr, g_lgr);
    cudaGetSymbolAddress((void**)&dsb, g_ds);
    cudaGetSymbolAddress((void**)&dvb, g_dv);
    cudaGetSymbolAddress((void**)&s0,  g_s0);
    cudaGetSymbolAddress((void**)&v0,  g_v0);
    cudaGetSymbolAddress((void**)&s1v, g_s1);
    cudaGetSymbolAddress((void**)&v1,  g_v1);
    cudaGetSymbolAddress((void**)&s2,  g_s2);
    cudaGetSymbolAddress((void**)&v2,  g_v2);
    cudaGetSymbolAddress((void**)&r,   g_r);

    // fork: head work (fill + rq projections) runs on s1, overlapping t1's
    // qk_gemm+atb on stream 0. fill joins back before t1's topk_scatter;
    // rq is consumed by read_level(0) on s1 (in-order, after ev0).
    cudaEventRecord(evH, 0);
    cudaStreamWaitEvent(s1, evH, 0);
    fill_ds_dv<<<2048, 256, 0, s1>>>(dsb, (float4*)dvb, BATCH * NS0,
                                     BATCH * NS0 * DIM / 4);
    cudaEventRecord(evFill, s1);
    rq_gemm_sk<<<dim3(2, TOK / 64, 3 * BATCH), 256, 0, s1>>>(tok_val, rr, rq);

    // ---- level 0, transition 1 (inlined: needs fill-join before topk) ----
    qk_gemm_sk<<<dim3(2, TOK / 64 + NS0 / 64, BATCH), 256>>>(tok_val, mv0, wr,
        q, q2, kb, kb2, TOK, NS0);
    launch_atb(q, q2, kb, kb2, lg, TOK, NS0, 0);
    cudaStreamWaitEvent((cudaStream_t)0, evFill, 0);
    topk_scatter<<<BATCH * TOK / 8, 256>>>(lg, tok_val, tok_state, dsb, dvb,
                                           nullptr, TOK, NS0);
    apply_both<<<BATCH * NS0 + BATCH, 256>>>(ms0, dsb, s0, mv0, dvb, v0,
                                             lgam, lbet, NS0);
    run_trans(v0, s0, NS0, v0, NS0, pr + 0 * 2 * DR, nullptr,
              s0, v0, s0, v0, lgam + 0 * DIM, lbet + 0 * DIM,
              q, q2, kb, kb2, lg, dsb, dvb);
    cudaEventRecord(ev0, 0);
    cudaStreamWaitEvent(s1, ev0, 0);
    read_level(0, v0, NS0, rr, rp, rg, tok_val, out, rq, kr, kr2, lgr, r, s1);

    // ---- level 1 ----
    run_trans(v0, s0, NS0, mv1, NS1, lr + 0 * 2 * DR, nullptr,
              ms1, mv1, s1v, v1, lgam + 1 * DIM, lbet + 1 * DIM,
              q, q2, kb, kb2, lg, dsb, dvb);
    run_trans(tok_val, tok_state, TOK, v1, NS1, sr + 0 * 2 * DR, sg + 0,
              s1v, v1, s1v, v1, lgam + 1 * DIM, lbet + 1 * DIM,
              q, q2, kb, kb2, lg, dsb, dvb);
    run_trans(v1, s1v, NS1, v1, NS1, pr + 1 * 2 * DR, nullptr,
              s1v, v1, s1v, v1, lgam + 1 * DIM, lbet + 1 * DIM,
              q, q2, kb, kb2, lg, dsb, dvb);
    cudaEventRecord(ev1, 0);
    cudaStreamWaitEvent(s1, ev1, 0);
    read_level(1, v1, NS1, rr, rp, rg, tok_val, out, rq, kr, kr2, lgr, r, s1);

    // ---- level 2 ----
    run_trans(v1, s1v, NS1, mv2, NS2, lr + 1 * 2 * DR, nullptr,
              ms2, mv2, s2, v2, lgam + 2 * DIM, lbet + 2 * DIM,
              q, q2, kb, kb2, lg, dsb, dvb);
    run_trans(v0, s0, NS0, v2, NS2, sr + 1 * 2 * DR, sg + 1,
              s2, v2, s2, v2, lgam + 2 * DIM, lbet + 2 * DIM,
              q, q2, kb, kb2, lg, dsb, dvb);
    run_trans(v2, s2, NS2, v2, NS2, pr + 2 * 2 * DR, nullptr,
              s2, v2, s2, v2, lgam + 2 * DIM, lbet + 2 * DIM,
              q, q2, kb, kb2, lg, dsb, dvb);
    cudaEventRecord(ev2, 0);
    cudaStreamWaitEvent(s1, ev2, 0);
    read_level(2, v2, NS2, rr, rp, rg, tok_val, out, rq, kr, kr2, lgr, r, s1);

    // join read stream back into the main (captured) stream
    cudaEventRecord(evF, s1);
    cudaStreamWaitEvent((cudaStream_t)0, evF, 0);
}

// round 13
// speedup vs baseline: 1.2086x; 1.0108x over previous
#include <cuda_runtime.h>
#include <math.h>
#include <stdint.h>

#define BATCH 4
#define TOK   1024
#define DIM   512
#define RDIM  64
#define NS0   1024
#define NS1   256
#define NS2   64
#define DR    (DIM*RDIM)   /* 32768 */

// ---------------- scratch (static device memory; no cudaMalloc) -------------
__device__ float g_q [BATCH*TOK*RDIM];
__device__ float g_q2[BATCH*TOK*RDIM];
__device__ float g_k [BATCH*NS0*RDIM];
__device__ float g_k2[BATCH*NS0*RDIM];
__device__ float g_kr [BATCH*NS0*RDIM];     // read-path k partials (stream s1)
__device__ float g_kr2[BATCH*NS0*RDIM];
__device__ float g_rq[2*3*BATCH*TOK*RDIM];  // [split][route][b] read-path q parts
__device__ float g_q4a[BATCH*TOK*RDIM];     // t4 (tok->L1 skip) q partials
__device__ float g_q4b[BATCH*TOK*RDIM];
__device__ float g_q7a[BATCH*NS0*RDIM];     // t7 (v0->L2 skip) q partials
__device__ float g_q7b[BATCH*NS0*RDIM];
__device__ float g_lg [BATCH*TOK*NS0];      // transition logits (16MB)
__device__ float g_lgr[BATCH*TOK*NS0];      // read-path logits/attn (16MB)
__device__ float g_ds[BATCH*NS0];
__device__ float g_dv[BATCH*NS0*DIM];
__device__ float g_s0[BATCH*NS0];
__device__ float g_v0[BATCH*NS0*DIM];
__device__ float g_s1[BATCH*NS1];
__device__ float g_v1[BATCH*NS1*DIM];
__device__ float g_s2[BATCH*NS2];
__device__ float g_v2[BATCH*NS2*DIM];
__device__ float g_r [BATCH*TOK*DIM];

// ---------------- tf32 helpers ------------------------------------------------
__device__ __forceinline__ uint32_t f2tf32(float x) {
    uint32_t u;
    asm("cvt.rna.tf32.f32 %0, %1;" : "=r"(u) : "f"(x));
    return u;
}
__device__ __forceinline__ void mma_tf32(float* c, uint32_t a0, uint32_t a1,
                                         uint32_t a2, uint32_t a3,
                                         uint32_t b0, uint32_t b1) {
    asm volatile(
        "mma.sync.aligned.m16n8k8.row.col.f32.tf32.tf32.f32 "
        "{%0,%1,%2,%3}, {%4,%5,%6,%7}, {%8,%9}, {%0,%1,%2,%3};"
        : "+f"(c[0]), "+f"(c[1]), "+f"(c[2]), "+f"(c[3])
        : "r"(a0), "r"(a1), "r"(a2), "r"(a3), "r"(b0), "r"(b1));
}

// order-preserving monotone encoding of float (total order, -inf lowest)
__device__ __forceinline__ uint32_t fmono(float x) {
    uint32_t u = __float_as_uint(x);
    return (u & 0x80000000u) ? ~u : (u | 0x80000000u);
}
__device__ __forceinline__ float fdemono(uint32_t k) {
    uint32_t u = (k & 0x80000000u) ? (k & 0x7fffffffu) : ~k;
    return __uint_as_float(u);
}

// ---------------- fused zero of ds + dv (head only) --------------------------
__global__ void fill_ds_dv(float* __restrict__ ds, float4* __restrict__ dv4,
                           int nds, int ndv4) {
    const int stride = gridDim.x * blockDim.x;
    const int i0 = blockIdx.x * blockDim.x + threadIdx.x;
    for (int j = i0; j < nds; j += stride) ds[j] = 0.f;
    const float4 z = make_float4(0.f, 0.f, 0.f, 0.f);
    for (int j = i0; j < ndv4; j += stride) dv4[j] = z;
}

// ============ split-K projection GEMM core (64x64 tile, K=256 slice) =========
__device__ __forceinline__ void proj_body(const float* __restrict__ Ab,
                                          const float* __restrict__ Bb,
                                          float* __restrict__ Cb, int m0)
{
    __shared__ float sAt[16][68];
    __shared__ float sBt[16][68];
    const int tid = threadIdx.x;
    const int tx = tid & 15, ty = tid >> 4;
    const int arow = tid >> 2, ak4 = (tid & 3) << 2;
    const int bk = tid >> 4, bn4 = (tid & 15) << 2;

    float acc[4][4];
#pragma unroll
    for (int i = 0; i < 4; i++)
#pragma unroll
        for (int j = 0; j < 4; j++) acc[i][j] = 0.f;

    float4 pa = *(const float4*)(Ab + (size_t)(m0 + arow) * DIM + ak4);
    float4 pb = *(const float4*)(Bb + (size_t)bk * RDIM + bn4);
    sAt[ak4 + 0][arow] = pa.x; sAt[ak4 + 1][arow] = pa.y;
    sAt[ak4 + 2][arow] = pa.z; sAt[ak4 + 3][arow] = pa.w;
    *(float4*)&sBt[bk][bn4] = pb;
    __syncthreads();

    for (int k0 = 16; k0 < 256; k0 += 16) {
        pa = *(const float4*)(Ab + (size_t)(m0 + arow) * DIM + k0 + ak4);
        pb = *(const float4*)(Bb + (size_t)(k0 + bk) * RDIM + bn4);
#pragma unroll
        for (int kk = 0; kk < 16; kk++) {
            float4 a  = *(const float4*)&sAt[kk][ty << 2];
            float4 bq = *(const float4*)&sBt[kk][tx << 2];
            float aa[4] = {a.x, a.y, a.z, a.w};
            float bb[4] = {bq.x, bq.y, bq.z, bq.w};
#pragma unroll
            for (int i = 0; i < 4; i++)
#pragma unroll
                for (int j = 0; j < 4; j++) acc[i][j] += aa[i] * bb[j];
        }
        __syncthreads();
        sAt[ak4 + 0][arow] = pa.x; sAt[ak4 + 1][arow] = pa.y;
        sAt[ak4 + 2][arow] = pa.z; sAt[ak4 + 3][arow] = pa.w;
        *(float4*)&sBt[bk][bn4] = pb;
        __syncthreads();
    }
#pragma unroll
    for (int kk = 0; kk < 16; kk++) {
        float4 a  = *(const float4*)&sAt[kk][ty << 2];
        float4 bq = *(const float4*)&sBt[kk][tx << 2];
        float aa[4] = {a.x, a.y, a.z, a.w};
        float bb[4] = {bq.x, bq.y, bq.z, bq.w};
#pragma unroll
        for (int i = 0; i < 4; i++)
#pragma unroll
            for (int j = 0; j < 4; j++) acc[i][j] += aa[i] * bb[j];
    }
#pragma unroll
    for (int i = 0; i < 4; i++) {
        size_t idx = (size_t)(m0 + (ty << 2) + i) * RDIM + (tx << 2);
        *(float4*)(Cb + idx) = make_float4(acc[i][0], acc[i][1], acc[i][2], acc[i][3]);
    }
}

// dual q/k projection, split-K=2. grid (2, Ns/64 + Nd/64, BATCH)
// Ns=0 -> k-only; Nd=0 -> q-only.
__global__ void __launch_bounds__(256)
qk_gemm_sk(const float* __restrict__ src, const float* __restrict__ dst,
           const float* __restrict__ W,
           float* __restrict__ q0, float* __restrict__ q1,
           float* __restrict__ k0, float* __restrict__ k1, int Ns, int Nd)
{
    const int b = blockIdx.z, s = blockIdx.x;
    const int nyq = Ns >> 6;
    const bool isQ = (int)blockIdx.y < nyq;
    const float* Ab = (isQ ? src + (size_t)b * Ns * DIM
                           : dst + (size_t)b * Nd * DIM) + s * 256;
    const float* Bb = (isQ ? W : W + DR) + (size_t)s * 256 * RDIM;
    float* Cb = isQ ? (s ? q1 : q0) + (size_t)b * Ns * RDIM
                    : (s ? k1 : k0) + (size_t)b * Nd * RDIM;
    const int m0 = (isQ ? blockIdx.y : blockIdx.y - nyq) * 64;
    proj_body(Ab, Bb, Cb, m0);
}

// read-path q projections: 3 routes in one launch. grid (2, TOK/64, 3*BATCH)
__global__ void __launch_bounds__(256)
rq_gemm_sk(const float* __restrict__ tok, const float* __restrict__ rr,
           float* __restrict__ rqp)
{
    const int s = blockIdx.x;
    const int l = blockIdx.z / BATCH, b = blockIdx.z % BATCH;
    const float* Ab = tok + (size_t)b * TOK * DIM + s * 256;
    const float* Bb = rr + (size_t)l * 2 * DR + (size_t)s * 256 * RDIM;
    float* Cb = rqp + ((size_t)(s * 3 + l) * BATCH + b) * TOK * RDIM;
    proj_body(Ab, Bb, Cb, blockIdx.y * 64);
}

// ---------------- logits GEMM (64x64 tile, small cases) ----------------------
__global__ void __launch_bounds__(256)
atb_gemm(const float* __restrict__ A0, const float* __restrict__ A1,
         const float* __restrict__ B0, const float* __restrict__ B1,
         float* __restrict__ C, int M, int N)
{
    __shared__ float sAt[64][68];
    __shared__ float sBt[64][68];
    const int b = blockIdx.z;
    const size_t aoff = (size_t)b * M * 64;
    const size_t boff = (size_t)b * N * 64;
    const int m0 = blockIdx.y * 64, n0 = blockIdx.x * 64;
    const int tid = threadIdx.x;
    const int tx = tid & 15, ty = tid >> 4;
    const int row = tid >> 2, q4 = (tid & 3) << 2;

#pragma unroll
    for (int c = 0; c < 4; c++) {
        const int kk0 = q4 + c * 16;
        const size_t ai = aoff + (size_t)(m0 + row) * 64 + kk0;
        const size_t bi = boff + (size_t)(n0 + row) * 64 + kk0;
        float4 av = *(const float4*)(A0 + ai);
        float4 a1 = *(const float4*)(A1 + ai);
        float4 bv = *(const float4*)(B0 + bi);
        float4 b1 = *(const float4*)(B1 + bi);
        av.x += a1.x; av.y += a1.y; av.z += a1.z; av.w += a1.w;
        bv.x += b1.x; bv.y += b1.y; bv.z += b1.z; bv.w += b1.w;
        sAt[kk0 + 0][row] = av.x; sAt[kk0 + 1][row] = av.y;
        sAt[kk0 + 2][row] = av.z; sAt[kk0 + 3][row] = av.w;
        sBt[kk0 + 0][row] = bv.x; sBt[kk0 + 1][row] = bv.y;
        sBt[kk0 + 2][row] = bv.z; sBt[kk0 + 3][row] = bv.w;
    }
    __syncthreads();

    float acc[4][4];
#pragma unroll
    for (int i = 0; i < 4; i++)
#pragma unroll
        for (int j = 0; j < 4; j++) acc[i][j] = 0.f;
#pragma unroll 16
    for (int kk = 0; kk < 64; kk++) {
        float4 a  = *(const float4*)&sAt[kk][ty << 2];
        float4 bq = *(const float4*)&sBt[kk][tx << 2];
        float aa[4] = {a.x, a.y, a.z, a.w};
        float bb[4] = {bq.x, bq.y, bq.z, bq.w};
#pragma unroll
        for (int i = 0; i < 4; i++)
#pragma unroll
            for (int j = 0; j < 4; j++) acc[i][j] += aa[i] * bb[j];
    }
#pragma unroll
    for (int i = 0; i < 4; i++) {
        size_t idx = (size_t)b * M * N + (size_t)(m0 + (ty << 2) + i) * N + n0 + (tx << 2);
        float4 cv = make_float4(0.125f * acc[i][0], 0.125f * acc[i][1],
                                0.125f * acc[i][2], 0.125f * acc[i][3]);
        *(float4*)(C + idx) = cv;
    }
}

// ---------------- logits GEMM big: 128x128 tile, 8x8 micro, K=64 resident ----
__global__ void __launch_bounds__(256)
atb_big(const float* __restrict__ A0, const float* __restrict__ A1,
        const float* __restrict__ B0, const float* __restrict__ B1,
        float* __restrict__ C, int M, int N)
{
    extern __shared__ float sm[];
    float (*sAt)[132] = (float(*)[132])sm;
    float (*sBt)[132] = (float(*)[132])(sm + 64 * 132);
    const int b = blockIdx.z;
    const size_t aoff = (size_t)b * M * 64;
    const size_t boff = (size_t)b * N * 64;
    const int m0 = blockIdx.y * 128, n0 = blockIdx.x * 128;
    const int tid = threadIdx.x;
    const int tx = tid & 15, ty = tid >> 4;

    for (int idx = tid; idx < 2048; idx += 256) {
        const int row = idx >> 4, kq = (idx & 15) << 2;
        const size_t ai = aoff + (size_t)(m0 + row) * 64 + kq;
        const size_t bi = boff + (size_t)(n0 + row) * 64 + kq;
        float4 av = *(const float4*)(A0 + ai);
        float4 a1 = *(const float4*)(A1 + ai);
        float4 bv = *(const float4*)(B0 + bi);
        float4 b1 = *(const float4*)(B1 + bi);
        av.x += a1.x; av.y += a1.y; av.z += a1.z; av.w += a1.w;
        bv.x += b1.x; bv.y += b1.y; bv.z += b1.z; bv.w += b1.w;
        sAt[kq + 0][row] = av.x; sAt[kq + 1][row] = av.y;
        sAt[kq + 2][row] = av.z; sAt[kq + 3][row] = av.w;
        sBt[kq + 0][row] = bv.x; sBt[kq + 1][row] = bv.y;
        sBt[kq + 2][row] = bv.z; sBt[kq + 3][row] = bv.w;
    }
    __syncthreads();

    float acc[8][8];
#pragma unroll
    for (int i = 0; i < 8; i++)
#pragma unroll
        for (int j = 0; j < 8; j++) acc[i][j] = 0.f;

#pragma unroll 8
    for (int kk = 0; kk < 64; kk++) {
        float4 a0 = *(const float4*)&sAt[kk][ty << 2];
        float4 a1 = *(const float4*)&sAt[kk][64 + (ty << 2)];
        float4 b0 = *(const float4*)&sBt[kk][tx << 2];
        float4 b1 = *(const float4*)&sBt[kk][64 + (tx << 2)];
        float av[8] = {a0.x, a0.y, a0.z, a0.w, a1.x, a1.y, a1.z, a1.w};
        float bv[8] = {b0.x, b0.y, b0.z, b0.w, b1.x, b1.y, b1.z, b1.w};
#pragma unroll
        for (int i = 0; i < 8; i++)
#pragma unroll
            for (int j = 0; j < 8; j++) acc[i][j] += av[i] * bv[j];
    }

#pragma unroll
    for (int ih = 0; ih < 2; ih++)
#pragma unroll
        for (int i = 0; i < 4; i++) {
            const int m = m0 + ih * 64 + (ty << 2) + i;
            const size_t base = (size_t)b * M * N + (size_t)m * N + n0;
#pragma unroll
            for (int jh = 0; jh < 2; jh++) {
                const int r = ih * 4 + i;
                float4 cv = make_float4(0.125f * acc[r][jh * 4 + 0],
                                        0.125f * acc[r][jh * 4 + 1],
                                        0.125f * acc[r][jh * 4 + 2],
                                        0.125f * acc[r][jh * 4 + 3]);
                *(float4*)(C + base + jh * 64 + (tx << 2)) = cv;
            }
        }
}

// ---------------- tf32 tensor-core GEMM: 128x128 tile, warp 64x32 ------------
__global__ void __launch_bounds__(256)
ab_gemm_tf32(const float* __restrict__ A, const float* __restrict__ Bm,
             float* __restrict__ C, const float* __restrict__ Cinit,
             const float* __restrict__ gatep,
             int M, int N, int K,
             long long strA, long long strB, long long strC)
{
    __shared__ uint32_t sA[16][136];
    __shared__ uint32_t sB[16][136];
    const int b = blockIdx.z;
    const float* Ab = A  + (size_t)b * strA;
    const float* Bb = Bm + (size_t)b * strB;
    const int m0 = blockIdx.y * 128, n0 = blockIdx.x * 128;
    const int tid = threadIdx.x, lane = tid & 31, warp = tid >> 5;
    const int wm = (warp >> 2) * 64, wn = (warp & 3) * 32;
    const int gid = lane >> 2, tid4 = lane & 3;
    const int arow = tid >> 1, ak = (tid & 1) * 8;
    const int bk = tid >> 4, bn = (tid & 15) * 8;

    float acc[4][4][4];
#pragma unroll
    for (int mi = 0; mi < 4; mi++)
#pragma unroll
        for (int ni = 0; ni < 4; ni++)
#pragma unroll
            for (int t = 0; t < 4; t++) acc[mi][ni][t] = 0.f;

    float4 pa0, pa1, pb0, pb1;
    {
        const float* ap = Ab + (size_t)(m0 + arow) * K + ak;
        pa0 = *(const float4*)ap; pa1 = *(const float4*)(ap + 4);
        const float* bp = Bb + (size_t)bk * N + n0 + bn;
        pb0 = *(const float4*)bp; pb1 = *(const float4*)(bp + 4);
        sA[ak + 0][arow] = f2tf32(pa0.x); sA[ak + 1][arow] = f2tf32(pa0.y);
        sA[ak + 2][arow] = f2tf32(pa0.z); sA[ak + 3][arow] = f2tf32(pa0.w);
        sA[ak + 4][arow] = f2tf32(pa1.x); sA[ak + 5][arow] = f2tf32(pa1.y);
        sA[ak + 6][arow] = f2tf32(pa1.z); sA[ak + 7][arow] = f2tf32(pa1.w);
        sB[bk][bn + 0] = f2tf32(pb0.x); sB[bk][bn + 1] = f2tf32(pb0.y);
        sB[bk][bn + 2] = f2tf32(pb0.z); sB[bk][bn + 3] = f2tf32(pb0.w);
        sB[bk][bn + 4] = f2tf32(pb1.x); sB[bk][bn + 5] = f2tf32(pb1.y);
        sB[bk][bn + 6] = f2tf32(pb1.z); sB[bk][bn + 7] = f2tf32(pb1.w);
        __syncthreads();
    }

#define TF32_COMPUTE_TILE                                                     \
    _Pragma("unroll")                                                         \
    for (int ks = 0; ks < 2; ks++) {                                          \
        const int kk = ks * 8;                                                \
        uint32_t af[4][4], bf[4][2];                                          \
        _Pragma("unroll")                                                     \
        for (int mi = 0; mi < 4; mi++) {                                      \
            const int m = wm + mi * 16 + gid;                                 \
            af[mi][0] = sA[kk + tid4][m];                                     \
            af[mi][1] = sA[kk + tid4][m + 8];                                 \
            af[mi][2] = sA[kk + 4 + tid4][m];                                 \
            af[mi][3] = sA[kk + 4 + tid4][m + 8];                             \
        }                                                                     \
        _Pragma("unroll")                                                     \
        for (int ni = 0; ni < 4; ni++) {                                      \
            const int n = wn + ni * 8 + gid;                                  \
            bf[ni][0] = sB[kk + tid4][n];                                     \
            bf[ni][1] = sB[kk + 4 + tid4][n];                                 \
        }                                                                     \
        _Pragma("unroll")                                                     \
        for (int mi = 0; mi < 4; mi++)                                        \
            _Pragma("unroll")                                                 \
            for (int ni = 0; ni < 4; ni++)                                    \
                mma_tf32(acc[mi][ni], af[mi][0], af[mi][1], af[mi][2],        \
                         af[mi][3], bf[ni][0], bf[ni][1]);                    \
    }

    for (int k0 = 16; k0 < K; k0 += 16) {
        const float* ap = Ab + (size_t)(m0 + arow) * K + k0 + ak;
        pa0 = *(const float4*)ap; pa1 = *(const float4*)(ap + 4);
        const float* bp = Bb + (size_t)(k0 + bk) * N + n0 + bn;
        pb0 = *(const float4*)bp; pb1 = *(const float4*)(bp + 4);
        TF32_COMPUTE_TILE
        __syncthreads();
        sA[ak + 0][arow] = f2tf32(pa0.x); sA[ak + 1][arow] = f2tf32(pa0.y);
        sA[ak + 2][arow] = f2tf32(pa0.z); sA[ak + 3][arow] = f2tf32(pa0.w);
        sA[ak + 4][arow] = f2tf32(pa1.x); sA[ak + 5][arow] = f2tf32(pa1.y);
        sA[ak + 6][arow] = f2tf32(pa1.z); sA[ak + 7][arow] = f2tf32(pa1.w);
        sB[bk][bn + 0] = f2tf32(pb0.x); sB[bk][bn + 1] = f2tf32(pb0.y);
        sB[bk][bn + 2] = f2tf32(pb0.z); sB[bk][bn + 3] = f2tf32(pb0.w);
        sB[bk][bn + 4] = f2tf32(pb1.x); sB[bk][bn + 5] = f2tf32(pb1.y);
        sB[bk][bn + 6] = f2tf32(pb1.z); sB[bk][bn + 7] = f2tf32(pb1.w);
        __syncthreads();
    }
    TF32_COMPUTE_TILE
#undef TF32_COMPUTE_TILE

    float alpha = 1.f;
    if (gatep) alpha = 1.f / (1.f + expf(-*gatep));
#pragma unroll
    for (int mi = 0; mi < 4; mi++) {
#pragma unroll
        for (int ni = 0; ni < 4; ni++) {
            const int r0 = m0 + wm + mi * 16 + gid;
            const int cc = n0 + wn + ni * 8 + 2 * tid4;
            const size_t i0 = (size_t)b * strC + (size_t)r0 * N + cc;
            const size_t i1 = (size_t)b * strC + (size_t)(r0 + 8) * N + cc;
            float2 v0 = make_float2(alpha * acc[mi][ni][0], alpha * acc[mi][ni][1]);
            float2 v1 = make_float2(alpha * acc[mi][ni][2], alpha * acc[mi][ni][3]);
            if (Cinit) {
                float2 c0 = *(const float2*)(Cinit + i0);
                float2 c1 = *(const float2*)(Cinit + i1);
                v0.x += c0.x; v0.y += c0.y;
                v1.x += c1.x; v1.y += c1.y;
            }
            *(float2*)(C + i0) = v0;
            *(float2*)(C + i1) = v1;
        }
    }
}

// ---------------- top-k + signed softmax + softplus-state scatter ------------
// one warp per source row. tie-break matches jax.lax.top_k (lower index first).
// Scan: fully-unrolled bubble insert (register-resident). Merge: smem lists +
// redux argmax (R10 win). FROZEN — two variants regressed.
__global__ void __launch_bounds__(256)
topk_scatter(const float* __restrict__ logits, const float* __restrict__ srcval,
             const float* __restrict__ srcstate, float* __restrict__ ds,
             float* __restrict__ dv, const float* __restrict__ gatep,
             int Ns, int Nd)
{
    __shared__ uint32_t skey[8][16][32];
    __shared__ int      sidx[8][16][32];
    const int warp = threadIdx.x >> 5, lane = threadIdx.x & 31;
    const int row = blockIdx.x * 8 + warp;      // = b*Ns + s
    const int b = row / Ns;
    const float* L = logits + (size_t)row * Nd;

    float tv[16]; int ti[16];
#pragma unroll
    for (int i = 0; i < 16; i++) { tv[i] = -INFINITY; ti[i] = 0x40000000; }

    // per-lane top-16 over strided candidates (sorted ascending)
    for (int n = lane; n < Nd; n += 32) {
        float c = L[n];
        if (c > tv[0]) {
            tv[0] = c; ti[0] = n;
#pragma unroll
            for (int i = 0; i < 15; i++) {
                if (tv[i] > tv[i + 1]) {
                    float t = tv[i]; tv[i] = tv[i + 1]; tv[i + 1] = t;
                    int u = ti[i]; ti[i] = ti[i + 1]; ti[i + 1] = u;
                }
            }
        }
    }

    // spill lane-private sorted list (descending) to shared for dynamic idx
#pragma unroll
    for (int j = 0; j < 16; j++) {
        skey[warp][j][lane] = fmono(tv[15 - j]);
        sidx[warp][j][lane] = ti[15 - j];
    }

    // merge: 16x [redux-max on keys, redux-min on idx for tie-break, pop]
    float sel_v = 0.f; int sel_i = 0;
    int pos = 0;
#pragma unroll 1
    for (int it = 0; it < 16; ++it) {
        uint32_t key = skey[warp][pos][lane];
        int idx = sidx[warp][pos][lane];
        uint32_t mx = __reduce_max_sync(0xffffffffu, key);
        unsigned cand = (key == mx) ? (unsigned)idx : 0x7fffffffu;
        unsigned mni = __reduce_min_sync(0xffffffffu, cand);
        pos += (key == mx && (unsigned)idx == mni) ? 1 : 0;
        if (lane == it) { sel_v = fdemono(mx); sel_i = (int)mni; }
    }

    // signed softmax over the 16 selected values (lanes 0..15 own one each)
    float a_ = (lane < 16) ? fabsf(sel_v) : -INFINITY;
    float m = a_;
#pragma unroll
    for (int o = 16; o; o >>= 1) m = fmaxf(m, __shfl_xor_sync(0xffffffffu, m, o));
    float e = (lane < 16) ? expf(a_ - m) : 0.f;
    float ssum = e;
#pragma unroll
    for (int o = 16; o; o >>= 1) ssum += __shfl_xor_sync(0xffffffffu, ssum, o);
    float sgn = (sel_v > 0.f) ? 1.f : ((sel_v < 0.f) ? -1.f : 0.f);
    float st = srcstate[row];
    float sp = fmaxf(st, 0.f) + log1pf(expf(-fabsf(st)));
    float gate = 1.f;
    if (gatep) gate = 1.f / (1.f + expf(-*gatep));
    float cc = sgn * (e / ssum) * sp * gate;

    if (lane < 16) atomicAdd(ds + (size_t)b * Nd + sel_i, cc);

    const float* srow = srcval + (size_t)row * DIM;
    float4 xr[4];
#pragma unroll
    for (int t = 0; t < 4; t++)
        xr[t] = *(const float4*)(srow + (lane << 2) + (t << 7));
#pragma unroll 1
    for (int i = 0; i < 16; i++) {
        float ci = __shfl_sync(0xffffffffu, cc, i);
        int   di = __shfl_sync(0xffffffffu, sel_i, i);
        float* dst = dv + ((size_t)b * Nd + di) * DIM + (lane << 2);
#pragma unroll
        for (int t = 0; t < 4; t++) {
            asm volatile("red.global.add.v4.f32 [%0], {%1, %2, %3, %4};"
                         :: "l"(dst + (t << 7)),
                            "f"(ci * xr[t].x), "f"(ci * xr[t].y),
                            "f"(ci * xr[t].z), "f"(ci * xr[t].w)
                         : "memory");
        }
    }
}

// ---------------- fused apply: LN rows + signed-softmax state (self-clean) ---
__global__ void __launch_bounds__(256)
apply_both(const float* __restrict__ st, float* __restrict__ ds,
           float* __restrict__ s_out,
           const float* __restrict__ val, float* __restrict__ dvv,
           float* __restrict__ v_out,
           const float* __restrict__ gamma, const float* __restrict__ beta,
           int Nd)
{
    const int tid = threadIdx.x;
    const int nln = BATCH * Nd;
    __shared__ float ss[256], sq[256];
    if ((int)blockIdx.x < nln) {
        const int row = blockIdx.x;
        float2 x = ((const float2*)(val + (size_t)row * DIM))[tid];
        float2 d = ((float2*)(dvv + (size_t)row * DIM))[tid];
        ((float2*)(dvv + (size_t)row * DIM))[tid] = make_float2(0.f, 0.f);
        x.x += d.x; x.y += d.y;
        ss[tid] = x.x + x.y;
        sq[tid] = x.x * x.x + x.y * x.y;
        __syncthreads();
        for (int o = 128; o; o >>= 1) {
            if (tid < o) { ss[tid] += ss[tid + o]; sq[tid] += sq[tid + o]; }
            __syncthreads();
        }
        float mean = ss[0] * (1.f / DIM);
        float var = sq[0] * (1.f / DIM) - mean * mean;
        float rs = rsqrtf(var + 1e-5f);
        float2 g = ((const float2*)gamma)[tid];
        float2 bb = ((const float2*)beta)[tid];
        float2 y;
        y.x = (x.x - mean) * rs * g.x + bb.x;
        y.y = (x.y - mean) * rs * g.y + bb.y;
        ((float2*)(v_out + (size_t)row * DIM))[tid] = y;
    } else {
        const int b = blockIdx.x - nln;
        const float* S = st + (size_t)b * Nd;
        float* D = ds + (size_t)b * Nd;
        float x[4]; float mx = -INFINITY;
#pragma unroll
        for (int i = 0; i < 4; i++) {
            int n = tid + i * 256;
            x[i] = (n < Nd) ? (S[n] + D[n]) : 0.f;
            if (n < Nd) { mx = fmaxf(mx, fabsf(x[i])); D[n] = 0.f; }
        }
        ss[tid] = mx; __syncthreads();
        for (int o = 128; o; o >>= 1) {
            if (tid < o) ss[tid] = fmaxf(ss[tid], ss[tid + o]);
            __syncthreads();
        }
        mx = ss[0]; __syncthreads();
        float e[4]; float s = 0.f;
#pragma unroll
        for (int i = 0; i < 4; i++) {
            int n = tid + i * 256;
            e[i] = (n < Nd) ? expf(fabsf(x[i]) - mx) : 0.f;
            s += e[i];
        }
        ss[tid] = s; __syncthreads();
        for (int o = 128; o; o >>= 1) {
            if (tid < o) ss[tid] += ss[tid + o];
            __syncthreads();
        }
        float inv = 1.f / ss[0];
#pragma unroll
        for (int i = 0; i < 4; i++) {
            int n = tid + i * 256;
            if (n < Nd) {
                float sgn = (x[i] > 0.f) ? 1.f : ((x[i] < 0.f) ? -1.f : 0.f);
                s_out[(size_t)b * Nd + n] = sgn * e[i] * inv;
            }
        }
    }
}

// ---------------- plain row softmax (read attention) -------------------------
__global__ void __launch_bounds__(256)
row_softmax(float* __restrict__ L, int N)
{
    const int row = blockIdx.x, tid = threadIdx.x;
    float* p = L + (size_t)row * N;
    float x[4]; float mx = -INFINITY;
#pragma unroll
    for (int i = 0; i < 4; i++) {
        int n = tid + i * 256;
        x[i] = (n < N) ? p[n] : -INFINITY;
        mx = fmaxf(mx, x[i]);
    }
    __shared__ float sm[256];
    sm[tid] = mx; __syncthreads();
    for (int o = 128; o; o >>= 1) { if (tid < o) sm[tid] = fmaxf(sm[tid], sm[tid + o]); __syncthreads(); }
    mx = sm[0]; __syncthreads();
    float e[4]; float s = 0.f;
#pragma unroll
    for (int i = 0; i < 4; i++) {
        int n = tid + i * 256;
        e[i] = (n < N) ? expf(x[i] - mx) : 0.f;
        s += e[i];
    }
    sm[tid] = s; __syncthreads();
    for (int o = 128; o; o >>= 1) { if (tid < o) sm[tid] += sm[tid + o]; __syncthreads(); }
    float inv = 1.f / sm[0];
#pragma unroll
    for (int i = 0; i < 4; i++) {
        int n = tid + i * 256;
        if (n < N) p[n] = e[i] * inv;
    }
}

// ---------------- host orchestration -----------------------------------------
static inline void launch_atb(const float* A0, const float* A1,
                              const float* B0, const float* B1,
                              float* C, int M, int N, cudaStream_t st)
{
    if (M >= 1024 && N >= 128 && (M % 128) == 0 && (N % 128) == 0)
        atb_big<<<dim3(N / 128, M / 128, BATCH), 256, 67584, st>>>(A0, A1, B0, B1, C, M, N);
    else
        atb_gemm<<<dim3(N / 64, M / 64, BATCH), 256, 0, st>>>(A0, A1, B0, B1, C, M, N);
}

static void run_trans(const float* srcv, const float* srcs, int Ns,
                      const float* dstv, int Nd,
                      const float* W, const float* gatep,
                      const float* st_in, const float* vl_in,
                      float* s_out, float* v_out,
                      const float* gamma, const float* beta,
                      float* q, float* q2, float* kb, float* kb2,
                      float* lg, float* dsb, float* dvb)
{
    qk_gemm_sk<<<dim3(2, Ns / 64 + Nd / 64, BATCH), 256>>>(srcv, dstv, W,
        q, q2, kb, kb2, Ns, Nd);
    launch_atb(q, q2, kb, kb2, lg, Ns, Nd, 0);
    topk_scatter<<<BATCH * Ns / 8, 256>>>(lg, srcv, srcs, dsb, dvb, gatep, Ns, Nd);
    apply_both<<<BATCH * Nd + BATCH, 256>>>(st_in, dsb, s_out, vl_in, dvb, v_out,
                                            gamma, beta, Nd);
}

// transition with PRECOMPUTED q partials (k-only projection in the chain)
static void run_trans_preq(const float* srcv, const float* srcs, int Ns,
                           const float* dstv, int Nd,
                           const float* W, const float* gatep,
                           const float* st_in, const float* vl_in,
                           float* s_out, float* v_out,
                           const float* gamma, const float* beta,
                           const float* qpre, const float* qpre2,
                           float* kb, float* kb2,
                           float* lg, float* dsb, float* dvb)
{
    qk_gemm_sk<<<dim3(2, Nd / 64, BATCH), 256>>>(srcv, dstv, W,
        kb, kb2, kb, kb2, 0, Nd);      // Ns=0 -> all blocks k-side
    launch_atb(qpre, qpre2, kb, kb2, lg, Ns, Nd, 0);
    topk_scatter<<<BATCH * Ns / 8, 256>>>(lg, srcv, srcs, dsb, dvb, gatep, Ns, Nd);
    apply_both<<<BATCH * Nd + BATCH, 256>>>(st_in, dsb, s_out, vl_in, dvb, v_out,
                                            gamma, beta, Nd);
}

static void read_level(int l, const float* mv, int S,
                       const float* rr, const float* rp, const float* rg,
                       const float* tok_val, float* out,
                       float* rq, float* kr, float* kr2, float* lgr, float* r,
                       cudaStream_t st)
{
    const size_t RQS = (size_t)3 * BATCH * TOK * RDIM;
    const size_t RQL = (size_t)BATCH * TOK * RDIM;
    qk_gemm_sk<<<dim3(2, S / 64, BATCH), 256, 0, st>>>(mv, mv,
        rr + (size_t)l * 2 * DR, kr, kr2, kr, kr2, 0, S);
    launch_atb(rq + (size_t)l * RQL, rq + RQS + (size_t)l * RQL, kr, kr2,
               lgr, TOK, S, st);
    row_softmax<<<BATCH * TOK, 256, 0, st>>>(lgr, S);
    ab_gemm_tf32<<<dim3(DIM / 128, TOK / 128, BATCH), 256, 0, st>>>(lgr, mv, r,
        nullptr, nullptr, TOK, DIM, S, (long long)TOK * S, (long long)S * DIM,
        (long long)TOK * DIM);
    ab_gemm_tf32<<<dim3(DIM / 128, TOK / 128, BATCH), 256, 0, st>>>(r,
        rp + (size_t)l * DIM * DIM, out, (l == 0) ? tok_val : out, rg + l,
        TOK, DIM, DIM, (long long)TOK * DIM, 0, (long long)TOK * DIM);
}

extern "C" void kernel_launch(void* const* d_in, const int* in_sizes, int n_in,
                              void* d_out, int out_size)
{
    const float* tok_val   = (const float*)d_in[0];
    const float* tok_state = (const float*)d_in[1];
    const float* ms0 = (const float*)d_in[2];
    const float* mv0 = (const float*)d_in[3];
    const float* ms1 = (const float*)d_in[4];
    const float* mv1 = (const float*)d_in[5];
    const float* ms2 = (const float*)d_in[6];
    const float* mv2 = (const float*)d_in[7];
    const float* wr  = (const float*)d_in[8];
    const float* pr  = (const float*)d_in[9];
    const float* lr  = (const float*)d_in[10];
    const float* sr  = (const float*)d_in[11];
    const float* sg  = (const float*)d_in[12];
    const float* lgam = (const float*)d_in[13];
    const float* lbet = (const float*)d_in[14];
    const float* rr  = (const float*)d_in[15];
    const float* rp  = (const float*)d_in[16];
    const float* rg  = (const float*)d_in[17];
    float* out = (float*)d_out;

    static bool _attr = []() {
        cudaFuncSetAttribute(atb_big,
            cudaFuncAttributeMaxDynamicSharedMemorySize, 67584);
        return true;
    }();
    (void)_attr;
    static cudaStream_t s1 = []() {
        cudaStream_t s; cudaStreamCreateWithFlags(&s, cudaStreamNonBlocking);
        return s;
    }();
    static cudaEvent_t evH = []() {
        cudaEvent_t e; cudaEventCreateWithFlags(&e, cudaEventDisableTiming);
        return e;
    }();
    static cudaEvent_t evFill = []() {
        cudaEvent_t e; cudaEventCreateWithFlags(&e, cudaEventDisableTiming);
        return e;
    }();
    static cudaEvent_t evQ4 = []() {
        cudaEvent_t e; cudaEventCreateWithFlags(&e, cudaEventDisableTiming);
        return e;
    }();
    static cudaEvent_t evQ7 = []() {
        cudaEvent_t e; cudaEventCreateWithFlags(&e, cudaEventDisableTiming);
        return e;
    }();
    static cudaEvent_t ev0 = []() {
        cudaEvent_t e; cudaEventCreateWithFlags(&e, cudaEventDisableTiming);
        return e;
    }();
    static cudaEvent_t ev1 = []() {
        cudaEvent_t e; cudaEventCreateWithFlags(&e, cudaEventDisableTiming);
        return e;
    }();
    static cudaEvent_t ev2 = []() {
        cudaEvent_t e; cudaEventCreateWithFlags(&e, cudaEventDisableTiming);
        return e;
    }();
    static cudaEvent_t evF = []() {
        cudaEvent_t e; cudaEventCreateWithFlags(&e, cudaEventDisableTiming);
        return e;
    }();

    float *q, *q2, *kb, *kb2, *kr, *kr2, *rq, *lg, *lgr, *dsb, *dvb;
    float *q4a, *q4b, *q7a, *q7b;
    float *s0, *v0, *s1v, *v1, *s2, *v2, *r;
    cudaGetSymbolAddress((void**)&q,   g_q);
    cudaGetSymbolAddress((void**)&q2,  g_q2);
    cudaGetSymbolAddress((void**)&kb,  g_k);
    cudaGetSymbolAddress((void**)&kb2, g_k2);
    cudaGetSymbolAddress((void**)&kr,  g_kr);
    cudaGetSymbolAddress((void**)&kr2, g_kr2);
    cudaGetSymbolAddress((void**)&rq,  g_rq);
    cudaGetSymbolAddress((void**)&q4a, g_q4a);
    cudaGetSymbolAddress((void**)&q4b, g_q4b);
    cudaGetSymbolAddress((void**)&q7a, g_q7a);
    cudaGetSymbolAddress((void**)&q7b, g_q7b);
    cudaGetSymbolAddress((void**)&lg,  g_lg);
    cudaGetSymbolAddress((void**)&lgr, g_lgr);
    cudaGetSymbolAddress((void**)&dsb, g_ds);
    cudaGetSymbolAddress((void**)&dvb, g_dv);
    cudaGetSymbolAddress((void**)&s0,  g_s0);
    cudaGetSymbolAddress((void**)&v0,  g_v0);
    cudaGetSymbolAddress((void**)&s1v, g_s1);
    cudaGetSymbolAddress((void**)&v1,  g_v1);
    cudaGetSymbolAddress((void**)&s2,  g_s2);
    cudaGetSymbolAddress((void**)&v2,  g_v2);
    cudaGetSymbolAddress((void**)&r,   g_r);

    // fork: head work runs on s1, overlapping t1's qk_gemm+atb on stream 0.
    // fill joins before t1's topk; rq is consumed by read_level(0) on s1;
    // t4's q projection (tok_val @ sr[0][0]) joins before t4's atb.
    cudaEventRecord(evH, 0);
    cudaStreamWaitEvent(s1, evH, 0);
    fill_ds_dv<<<2048, 256, 0, s1>>>(dsb, (float4*)dvb, BATCH * NS0,
                                     BATCH * NS0 * DIM / 4);
    cudaEventRecord(evFill, s1);
    rq_gemm_sk<<<dim3(2, TOK / 64, 3 * BATCH), 256, 0, s1>>>(tok_val, rr, rq);
    // t4 q precompute (q-only: Nd = 0)
    qk_gemm_sk<<<dim3(2, TOK / 64, BATCH), 256, 0, s1>>>(tok_val, tok_val,
        sr + 0 * 2 * DR, q4a, q4b, q4a, q4b, TOK, 0);
    cudaEventRecord(evQ4, s1);

    // ---- level 0, transition 1 (inlined: needs fill-join before topk) ----
    qk_gemm_sk<<<dim3(2, TOK / 64 + NS0 / 64, BATCH), 256>>>(tok_val, mv0, wr,
        q, q2, kb, kb2, TOK, NS0);
    launch_atb(q, q2, kb, kb2, lg, TOK, NS0, 0);
    cudaStreamWaitEvent((cudaStream_t)0, evFill, 0);
    topk_scatter<<<BATCH * TOK / 8, 256>>>(lg, tok_val, tok_state, dsb, dvb,
                                           nullptr, TOK, NS0);
    apply_both<<<BATCH * NS0 + BATCH, 256>>>(ms0, dsb, s0, mv0, dvb, v0,
                                             lgam, lbet, NS0);
    run_trans(v0, s0, NS0, v0, NS0, pr + 0 * 2 * DR, nullptr,
              s0, v0, s0, v0, lgam + 0 * DIM, lbet + 0 * DIM,
              q, q2, kb, kb2, lg, dsb, dvb);
    cudaEventRecord(ev0, 0);
    // s1: t7 q precompute (v0 @ sr[1][0]) then read level 0
    cudaStreamWaitEvent(s1, ev0, 0);
    qk_gemm_sk<<<dim3(2, NS0 / 64, BATCH), 256, 0, s1>>>(v0, v0,
        sr + 1 * 2 * DR, q7a, q7b, q7a, q7b, NS0, 0);
    cudaEventRecord(evQ7, s1);
    read_level(0, v0, NS0, rr, rp, rg, tok_val, out, rq, kr, kr2, lgr, r, s1);

    // ---- level 1 ----
    run_trans(v0, s0, NS0, mv1, NS1, lr + 0 * 2 * DR, nullptr,
              ms1, mv1, s1v, v1, lgam + 1 * DIM, lbet + 1 * DIM,
              q, q2, kb, kb2, lg, dsb, dvb);
    cudaStreamWaitEvent((cudaStream_t)0, evQ4, 0);
    run_trans_preq(tok_val, tok_state, TOK, v1, NS1, sr + 0 * 2 * DR, sg + 0,
                   s1v, v1, s1v, v1, lgam + 1 * DIM, lbet + 1 * DIM,
                   q4a, q4b, kb, kb2, lg, dsb, dvb);
    run_trans(v1, s1v, NS1, v1, NS1, pr + 1 * 2 * DR, nullptr,
              s1v, v1, s1v, v1, lgam + 1 * DIM, lbet + 1 * DIM,
              q, q2, kb, kb2, lg, dsb, dvb);
    cudaEventRecord(ev1, 0);
    cudaStreamWaitEvent(s1, ev1, 0);
    read_level(1, v1, NS1, rr, rp, rg, tok_val, out, rq, kr, kr2, lgr, r, s1);

    // ---- level 2 ----
    run_trans(v1, s1v, NS1, mv2, NS2, lr + 1 * 2 * DR, nullptr,
              ms2, mv2, s2, v2, lgam + 2 * DIM, lbet + 2 * DIM,
              q, q2, kb, kb2, lg, dsb, dvb);
    cudaStreamWaitEvent((cudaStream_t)0, evQ7, 0);
    run_trans_preq(v0, s0, NS0, v2, NS2, sr + 1 * 2 * DR, sg + 1,
                   s2, v2, s2, v2, lgam + 2 * DIM, lbet + 2 * DIM,
                   q7a, q7b, kb, kb2, lg, dsb, dvb);
    run_trans(v2, s2, NS2, v2, NS2, pr + 2 * 2 * DR, nullptr,
              s2, v2, s2, v2, lgam + 2 * DIM, lbet + 2 * DIM,
              q, q2, kb, kb2, lg, dsb, dvb);
    cudaEventRecord(ev2, 0);
    cudaStreamWaitEvent(s1, ev2, 0);
    read_level(2, v2, NS2, rr, rp, rg, tok_val, out, rq, kr, kr2, lgr, r, s1);

    // join read stream back into the main (captured) stream
    cudaEventRecord(evF, s1);
    cudaStreamWaitEvent((cudaStream_t)0, evF, 0);
}

// round 14
// speedup vs baseline: 1.2550x; 1.0384x over previous
#include <cuda_runtime.h>
#include <math.h>
#include <stdint.h>

#define BATCH 4
#define TOK   1024
#define DIM   512
#define RDIM  64
#define NS0   1024
#define NS1   256
#define NS2   64
#define DR    (DIM*RDIM)   /* 32768 */

#if defined(__CUDA_ARCH__) && __CUDA_ARCH__ >= 900
#define GRID_DEP_SYNC() cudaGridDependencySynchronize()
#else
#define GRID_DEP_SYNC() ((void)0)
#endif

// ---------------- scratch (static device memory; no cudaMalloc) -------------
__device__ float g_q [BATCH*TOK*RDIM];
__device__ float g_q2[BATCH*TOK*RDIM];
__device__ float g_k [BATCH*NS0*RDIM];
__device__ float g_k2[BATCH*NS0*RDIM];
__device__ float g_kr [BATCH*NS0*RDIM];     // read-path k partials (stream s1)
__device__ float g_kr2[BATCH*NS0*RDIM];
__device__ float g_rq[2*3*BATCH*TOK*RDIM];  // [split][route][b] read-path q parts
__device__ float g_q4a[BATCH*TOK*RDIM];     // t4 (tok->L1 skip) q partials
__device__ float g_q4b[BATCH*TOK*RDIM];
__device__ float g_q7a[BATCH*NS0*RDIM];     // t7 (v0->L2 skip) q partials
__device__ float g_q7b[BATCH*NS0*RDIM];
__device__ float g_lg [BATCH*TOK*NS0];      // transition logits (16MB)
__device__ float g_lgr[BATCH*TOK*NS0];      // read-path logits/attn (16MB)
__device__ float g_ds[BATCH*NS0];
__device__ float g_dv[BATCH*NS0*DIM];
__device__ float g_s0[BATCH*NS0];
__device__ float g_v0[BATCH*NS0*DIM];
__device__ float g_s1[BATCH*NS1];
__device__ float g_v1[BATCH*NS1*DIM];
__device__ float g_s2[BATCH*NS2];
__device__ float g_v2[BATCH*NS2*DIM];
__device__ float g_r [BATCH*TOK*DIM];

// ---------------- tf32 helpers ------------------------------------------------
__device__ __forceinline__ uint32_t f2tf32(float x) {
    uint32_t u;
    asm("cvt.rna.tf32.f32 %0, %1;" : "=r"(u) : "f"(x));
    return u;
}
__device__ __forceinline__ void mma_tf32(float* c, uint32_t a0, uint32_t a1,
                                         uint32_t a2, uint32_t a3,
                                         uint32_t b0, uint32_t b1) {
    asm volatile(
        "mma.sync.aligned.m16n8k8.row.col.f32.tf32.tf32.f32 "
        "{%0,%1,%2,%3}, {%4,%5,%6,%7}, {%8,%9}, {%0,%1,%2,%3};"
        : "+f"(c[0]), "+f"(c[1]), "+f"(c[2]), "+f"(c[3])
        : "r"(a0), "r"(a1), "r"(a2), "r"(a3), "r"(b0), "r"(b1));
}

// order-preserving monotone encoding of float (total order, -inf lowest)
__device__ __forceinline__ uint32_t fmono(float x) {
    uint32_t u = __float_as_uint(x);
    return (u & 0x80000000u) ? ~u : (u | 0x80000000u);
}
__device__ __forceinline__ float fdemono(uint32_t k) {
    uint32_t u = (k & 0x80000000u) ? (k & 0x7fffffffu) : ~k;
    return __uint_as_float(u);
}

// ---------------- fused zero of ds + dv (head only) --------------------------
__global__ void fill_ds_dv(float* __restrict__ ds, float4* __restrict__ dv4,
                           int nds, int ndv4) {
    GRID_DEP_SYNC();
    const int stride = gridDim.x * blockDim.x;
    const int i0 = blockIdx.x * blockDim.x + threadIdx.x;
    for (int j = i0; j < nds; j += stride) ds[j] = 0.f;
    const float4 z = make_float4(0.f, 0.f, 0.f, 0.f);
    for (int j = i0; j < ndv4; j += stride) dv4[j] = z;
}

// ============ split-K projection GEMM core (64x64 tile, K=256 slice) =========
__device__ __forceinline__ void proj_body(const float* __restrict__ Ab,
                                          const float* __restrict__ Bb,
                                          float* __restrict__ Cb, int m0)
{
    __shared__ float sAt[16][68];
    __shared__ float sBt[16][68];
    const int tid = threadIdx.x;
    const int tx = tid & 15, ty = tid >> 4;
    const int arow = tid >> 2, ak4 = (tid & 3) << 2;
    const int bk = tid >> 4, bn4 = (tid & 15) << 2;

    float acc[4][4];
#pragma unroll
    for (int i = 0; i < 4; i++)
#pragma unroll
        for (int j = 0; j < 4; j++) acc[i][j] = 0.f;

    float4 pa = *(const float4*)(Ab + (size_t)(m0 + arow) * DIM + ak4);
    float4 pb = *(const float4*)(Bb + (size_t)bk * RDIM + bn4);
    sAt[ak4 + 0][arow] = pa.x; sAt[ak4 + 1][arow] = pa.y;
    sAt[ak4 + 2][arow] = pa.z; sAt[ak4 + 3][arow] = pa.w;
    *(float4*)&sBt[bk][bn4] = pb;
    __syncthreads();

    for (int k0 = 16; k0 < 256; k0 += 16) {
        pa = *(const float4*)(Ab + (size_t)(m0 + arow) * DIM + k0 + ak4);
        pb = *(const float4*)(Bb + (size_t)(k0 + bk) * RDIM + bn4);
#pragma unroll
        for (int kk = 0; kk < 16; kk++) {
            float4 a  = *(const float4*)&sAt[kk][ty << 2];
            float4 bq = *(const float4*)&sBt[kk][tx << 2];
            float aa[4] = {a.x, a.y, a.z, a.w};
            float bb[4] = {bq.x, bq.y, bq.z, bq.w};
#pragma unroll
            for (int i = 0; i < 4; i++)
#pragma unroll
                for (int j = 0; j < 4; j++) acc[i][j] += aa[i] * bb[j];
        }
        __syncthreads();
        sAt[ak4 + 0][arow] = pa.x; sAt[ak4 + 1][arow] = pa.y;
        sAt[ak4 + 2][arow] = pa.z; sAt[ak4 + 3][arow] = pa.w;
        *(float4*)&sBt[bk][bn4] = pb;
        __syncthreads();
    }
#pragma unroll
    for (int kk = 0; kk < 16; kk++) {
        float4 a  = *(const float4*)&sAt[kk][ty << 2];
        float4 bq = *(const float4*)&sBt[kk][tx << 2];
        float aa[4] = {a.x, a.y, a.z, a.w};
        float bb[4] = {bq.x, bq.y, bq.z, bq.w};
#pragma unroll
        for (int i = 0; i < 4; i++)
#pragma unroll
            for (int j = 0; j < 4; j++) acc[i][j] += aa[i] * bb[j];
    }
#pragma unroll
    for (int i = 0; i < 4; i++) {
        size_t idx = (size_t)(m0 + (ty << 2) + i) * RDIM + (tx << 2);
        *(float4*)(Cb + idx) = make_float4(acc[i][0], acc[i][1], acc[i][2], acc[i][3]);
    }
}

// dual q/k projection, split-K=2. grid (2, Ns/64 + Nd/64, BATCH)
// Ns=0 -> k-only; Nd=0 -> q-only.
__global__ void __launch_bounds__(256)
qk_gemm_sk(const float* __restrict__ src, const float* __restrict__ dst,
           const float* __restrict__ W,
           float* __restrict__ q0, float* __restrict__ q1,
           float* __restrict__ k0, float* __restrict__ k1, int Ns, int Nd)
{
    GRID_DEP_SYNC();
    const int b = blockIdx.z, s = blockIdx.x;
    const int nyq = Ns >> 6;
    const bool isQ = (int)blockIdx.y < nyq;
    const float* Ab = (isQ ? src + (size_t)b * Ns * DIM
                           : dst + (size_t)b * Nd * DIM) + s * 256;
    const float* Bb = (isQ ? W : W + DR) + (size_t)s * 256 * RDIM;
    float* Cb = isQ ? (s ? q1 : q0) + (size_t)b * Ns * RDIM
                    : (s ? k1 : k0) + (size_t)b * Nd * RDIM;
    const int m0 = (isQ ? blockIdx.y : blockIdx.y - nyq) * 64;
    proj_body(Ab, Bb, Cb, m0);
}

// read-path q projections: 3 routes in one launch. grid (2, TOK/64, 3*BATCH)
__global__ void __launch_bounds__(256)
rq_gemm_sk(const float* __restrict__ tok, const float* __restrict__ rr,
           float* __restrict__ rqp)
{
    GRID_DEP_SYNC();
    const int s = blockIdx.x;
    const int l = blockIdx.z / BATCH, b = blockIdx.z % BATCH;
    const float* Ab = tok + (size_t)b * TOK * DIM + s * 256;
    const float* Bb = rr + (size_t)l * 2 * DR + (size_t)s * 256 * RDIM;
    float* Cb = rqp + ((size_t)(s * 3 + l) * BATCH + b) * TOK * RDIM;
    proj_body(Ab, Bb, Cb, blockIdx.y * 64);
}

// ---------------- logits GEMM (64x64 tile, small cases) ----------------------
__global__ void __launch_bounds__(256)
atb_gemm(const float* __restrict__ A0, const float* __restrict__ A1,
         const float* __restrict__ B0, const float* __restrict__ B1,
         float* __restrict__ C, int M, int N)
{
    GRID_DEP_SYNC();
    __shared__ float sAt[64][68];
    __shared__ float sBt[64][68];
    const int b = blockIdx.z;
    const size_t aoff = (size_t)b * M * 64;
    const size_t boff = (size_t)b * N * 64;
    const int m0 = blockIdx.y * 64, n0 = blockIdx.x * 64;
    const int tid = threadIdx.x;
    const int tx = tid & 15, ty = tid >> 4;
    const int row = tid >> 2, q4 = (tid & 3) << 2;

#pragma unroll
    for (int c = 0; c < 4; c++) {
        const int kk0 = q4 + c * 16;
        const size_t ai = aoff + (size_t)(m0 + row) * 64 + kk0;
        const size_t bi = boff + (size_t)(n0 + row) * 64 + kk0;
        float4 av = *(const float4*)(A0 + ai);
        float4 a1 = *(const float4*)(A1 + ai);
        float4 bv = *(const float4*)(B0 + bi);
        float4 b1 = *(const float4*)(B1 + bi);
        av.x += a1.x; av.y += a1.y; av.z += a1.z; av.w += a1.w;
        bv.x += b1.x; bv.y += b1.y; bv.z += b1.z; bv.w += b1.w;
        sAt[kk0 + 0][row] = av.x; sAt[kk0 + 1][row] = av.y;
        sAt[kk0 + 2][row] = av.z; sAt[kk0 + 3][row] = av.w;
        sBt[kk0 + 0][row] = bv.x; sBt[kk0 + 1][row] = bv.y;
        sBt[kk0 + 2][row] = bv.z; sBt[kk0 + 3][row] = bv.w;
    }
    __syncthreads();

    float acc[4][4];
#pragma unroll
    for (int i = 0; i < 4; i++)
#pragma unroll
        for (int j = 0; j < 4; j++) acc[i][j] = 0.f;
#pragma unroll 16
    for (int kk = 0; kk < 64; kk++) {
        float4 a  = *(const float4*)&sAt[kk][ty << 2];
        float4 bq = *(const float4*)&sBt[kk][tx << 2];
        float aa[4] = {a.x, a.y, a.z, a.w};
        float bb[4] = {bq.x, bq.y, bq.z, bq.w};
#pragma unroll
        for (int i = 0; i < 4; i++)
#pragma unroll
            for (int j = 0; j < 4; j++) acc[i][j] += aa[i] * bb[j];
    }
#pragma unroll
    for (int i = 0; i < 4; i++) {
        size_t idx = (size_t)b * M * N + (size_t)(m0 + (ty << 2) + i) * N + n0 + (tx << 2);
        float4 cv = make_float4(0.125f * acc[i][0], 0.125f * acc[i][1],
                                0.125f * acc[i][2], 0.125f * acc[i][3]);
        *(float4*)(C + idx) = cv;
    }
}

// ---------------- logits GEMM big: 128x128 tile, 8x8 micro, K=64 resident ----
__global__ void __launch_bounds__(256)
atb_big(const float* __restrict__ A0, const float* __restrict__ A1,
        const float* __restrict__ B0, const float* __restrict__ B1,
        float* __restrict__ C, int M, int N)
{
    GRID_DEP_SYNC();
    extern __shared__ float sm[];
    float (*sAt)[132] = (float(*)[132])sm;
    float (*sBt)[132] = (float(*)[132])(sm + 64 * 132);
    const int b = blockIdx.z;
    const size_t aoff = (size_t)b * M * 64;
    const size_t boff = (size_t)b * N * 64;
    const int m0 = blockIdx.y * 128, n0 = blockIdx.x * 128;
    const int tid = threadIdx.x;
    const int tx = tid & 15, ty = tid >> 4;

    for (int idx = tid; idx < 2048; idx += 256) {
        const int row = idx >> 4, kq = (idx & 15) << 2;
        const size_t ai = aoff + (size_t)(m0 + row) * 64 + kq;
        const size_t bi = boff + (size_t)(n0 + row) * 64 + kq;
        float4 av = *(const float4*)(A0 + ai);
        float4 a1 = *(const float4*)(A1 + ai);
        float4 bv = *(const float4*)(B0 + bi);
        float4 b1 = *(const float4*)(B1 + bi);
        av.x += a1.x; av.y += a1.y; av.z += a1.z; av.w += a1.w;
        bv.x += b1.x; bv.y += b1.y; bv.z += b1.z; bv.w += b1.w;
        sAt[kq + 0][row] = av.x; sAt[kq + 1][row] = av.y;
        sAt[kq + 2][row] = av.z; sAt[kq + 3][row] = av.w;
        sBt[kq + 0][row] = bv.x; sBt[kq + 1][row] = bv.y;
        sBt[kq + 2][row] = bv.z; sBt[kq + 3][row] = bv.w;
    }
    __syncthreads();

    float acc[8][8];
#pragma unroll
    for (int i = 0; i < 8; i++)
#pragma unroll
        for (int j = 0; j < 8; j++) acc[i][j] = 0.f;

#pragma unroll 8
    for (int kk = 0; kk < 64; kk++) {
        float4 a0 = *(const float4*)&sAt[kk][ty << 2];
        float4 a1 = *(const float4*)&sAt[kk][64 + (ty << 2)];
        float4 b0 = *(const float4*)&sBt[kk][tx << 2];
        float4 b1 = *(const float4*)&sBt[kk][64 + (tx << 2)];
        float av[8] = {a0.x, a0.y, a0.z, a0.w, a1.x, a1.y, a1.z, a1.w};
        float bv[8] = {b0.x, b0.y, b0.z, b0.w, b1.x, b1.y, b1.z, b1.w};
#pragma unroll
        for (int i = 0; i < 8; i++)
#pragma unroll
            for (int j = 0; j < 8; j++) acc[i][j] += av[i] * bv[j];
    }

#pragma unroll
    for (int ih = 0; ih < 2; ih++)
#pragma unroll
        for (int i = 0; i < 4; i++) {
            const int m = m0 + ih * 64 + (ty << 2) + i;
            const size_t base = (size_t)b * M * N + (size_t)m * N + n0;
#pragma unroll
            for (int jh = 0; jh < 2; jh++) {
                const int r = ih * 4 + i;
                float4 cv = make_float4(0.125f * acc[r][jh * 4 + 0],
                                        0.125f * acc[r][jh * 4 + 1],
                                        0.125f * acc[r][jh * 4 + 2],
                                        0.125f * acc[r][jh * 4 + 3]);
                *(float4*)(C + base + jh * 64 + (tx << 2)) = cv;
            }
        }
}

// ---------------- tf32 tensor-core GEMM: 128x128 tile, warp 64x32 ------------
__global__ void __launch_bounds__(256)
ab_gemm_tf32(const float* __restrict__ A, const float* __restrict__ Bm,
             float* __restrict__ C, const float* __restrict__ Cinit,
             const float* __restrict__ gatep,
             int M, int N, int K,
             long long strA, long long strB, long long strC)
{
    GRID_DEP_SYNC();
    __shared__ uint32_t sA[16][136];
    __shared__ uint32_t sB[16][136];
    const int b = blockIdx.z;
    const float* Ab = A  + (size_t)b * strA;
    const float* Bb = Bm + (size_t)b * strB;
    const int m0 = blockIdx.y * 128, n0 = blockIdx.x * 128;
    const int tid = threadIdx.x, lane = tid & 31, warp = tid >> 5;
    const int wm = (warp >> 2) * 64, wn = (warp & 3) * 32;
    const int gid = lane >> 2, tid4 = lane & 3;
    const int arow = tid >> 1, ak = (tid & 1) * 8;
    const int bk = tid >> 4, bn = (tid & 15) * 8;

    float acc[4][4][4];
#pragma unroll
    for (int mi = 0; mi < 4; mi++)
#pragma unroll
        for (int ni = 0; ni < 4; ni++)
#pragma unroll
            for (int t = 0; t < 4; t++) acc[mi][ni][t] = 0.f;

    float4 pa0, pa1, pb0, pb1;
    {
        const float* ap = Ab + (size_t)(m0 + arow) * K + ak;
        pa0 = *(const float4*)ap; pa1 = *(const float4*)(ap + 4);
        const float* bp = Bb + (size_t)bk * N + n0 + bn;
        pb0 = *(const float4*)bp; pb1 = *(const float4*)(bp + 4);
        sA[ak + 0][arow] = f2tf32(pa0.x); sA[ak + 1][arow] = f2tf32(pa0.y);
        sA[ak + 2][arow] = f2tf32(pa0.z); sA[ak + 3][arow] = f2tf32(pa0.w);
        sA[ak + 4][arow] = f2tf32(pa1.x); sA[ak + 5][arow] = f2tf32(pa1.y);
        sA[ak + 6][arow] = f2tf32(pa1.z); sA[ak + 7][arow] = f2tf32(pa1.w);
        sB[bk][bn + 0] = f2tf32(pb0.x); sB[bk][bn + 1] = f2tf32(pb0.y);
        sB[bk][bn + 2] = f2tf32(pb0.z); sB[bk][bn + 3] = f2tf32(pb0.w);
        sB[bk][bn + 4] = f2tf32(pb1.x); sB[bk][bn + 5] = f2tf32(pb1.y);
        sB[bk][bn + 6] = f2tf32(pb1.z); sB[bk][bn + 7] = f2tf32(pb1.w);
        __syncthreads();
    }

#define TF32_COMPUTE_TILE                                                     \
    _Pragma("unroll")                                                         \
    for (int ks = 0; ks < 2; ks++) {                                          \
        const int kk = ks * 8;                                                \
        uint32_t af[4][4], bf[4][2];                                          \
        _Pragma("unroll")                                                     \
        for (int mi = 0; mi < 4; mi++) {                                      \
            const int m = wm + mi * 16 + gid;                                 \
            af[mi][0] = sA[kk + tid4][m];                                     \
            af[mi][1] = sA[kk + tid4][m + 8];                                 \
            af[mi][2] = sA[kk + 4 + tid4][m];                                 \
            af[mi][3] = sA[kk + 4 + tid4][m + 8];                             \
        }                                                                     \
        _Pragma("unroll")                                                     \
        for (int ni = 0; ni < 4; ni++) {                                      \
            const int n = wn + ni * 8 + gid;                                  \
            bf[ni][0] = sB[kk + tid4][n];                                     \
            bf[ni][1] = sB[kk + 4 + tid4][n];                                 \
        }                                                                     \
        _Pragma("unroll")                                                     \
        for (int mi = 0; mi < 4; mi++)                                        \
            _Pragma("unroll")                                                 \
            for (int ni = 0; ni < 4; ni++)                                    \
                mma_tf32(acc[mi][ni], af[mi][0], af[mi][1], af[mi][2],        \
                         af[mi][3], bf[ni][0], bf[ni][1]);                    \
    }

    for (int k0 = 16; k0 < K; k0 += 16) {
        const float* ap = Ab + (size_t)(m0 + arow) * K + k0 + ak;
        pa0 = *(const float4*)ap; pa1 = *(const float4*)(ap + 4);
        const float* bp = Bb + (size_t)(k0 + bk) * N + n0 + bn;
        pb0 = *(const float4*)bp; pb1 = *(const float4*)(bp + 4);
        TF32_COMPUTE_TILE
        __syncthreads();
        sA[ak + 0][arow] = f2tf32(pa0.x); sA[ak + 1][arow] = f2tf32(pa0.y);
        sA[ak + 2][arow] = f2tf32(pa0.z); sA[ak + 3][arow] = f2tf32(pa0.w);
        sA[ak + 4][arow] = f2tf32(pa1.x); sA[ak + 5][arow] = f2tf32(pa1.y);
        sA[ak + 6][arow] = f2tf32(pa1.z); sA[ak + 7][arow] = f2tf32(pa1.w);
        sB[bk][bn + 0] = f2tf32(pb0.x); sB[bk][bn + 1] = f2tf32(pb0.y);
        sB[bk][bn + 2] = f2tf32(pb0.z); sB[bk][bn + 3] = f2tf32(pb0.w);
        sB[bk][bn + 4] = f2tf32(pb1.x); sB[bk][bn + 5] = f2tf32(pb1.y);
        sB[bk][bn + 6] = f2tf32(pb1.z); sB[bk][bn + 7] = f2tf32(pb1.w);
        __syncthreads();
    }
    TF32_COMPUTE_TILE
#undef TF32_COMPUTE_TILE

    float alpha = 1.f;
    if (gatep) alpha = 1.f / (1.f + expf(-*gatep));
#pragma unroll
    for (int mi = 0; mi < 4; mi++) {
#pragma unroll
        for (int ni = 0; ni < 4; ni++) {
            const int r0 = m0 + wm + mi * 16 + gid;
            const int cc = n0 + wn + ni * 8 + 2 * tid4;
            const size_t i0 = (size_t)b * strC + (size_t)r0 * N + cc;
            const size_t i1 = (size_t)b * strC + (size_t)(r0 + 8) * N + cc;
            float2 v0 = make_float2(alpha * acc[mi][ni][0], alpha * acc[mi][ni][1]);
            float2 v1 = make_float2(alpha * acc[mi][ni][2], alpha * acc[mi][ni][3]);
            if (Cinit) {
                float2 c0 = *(const float2*)(Cinit + i0);
                float2 c1 = *(const float2*)(Cinit + i1);
                v0.x += c0.x; v0.y += c0.y;
                v1.x += c1.x; v1.y += c1.y;
            }
            *(float2*)(C + i0) = v0;
            *(float2*)(C + i1) = v1;
        }
    }
}

// ---------------- top-k + signed softmax + softplus-state scatter ------------
// one warp per source row. tie-break matches jax.lax.top_k (lower index first).
// Scan: fully-unrolled bubble insert (register-resident). Merge: smem lists +
// redux argmax (R10 win). FROZEN — two variants regressed.
__global__ void __launch_bounds__(256)
topk_scatter(const float* __restrict__ logits, const float* __restrict__ srcval,
             const float* __restrict__ srcstate, float* __restrict__ ds,
             float* __restrict__ dv, const float* __restrict__ gatep,
             int Ns, int Nd)
{
    GRID_DEP_SYNC();
    __shared__ uint32_t skey[8][16][32];
    __shared__ int      sidx[8][16][32];
    const int warp = threadIdx.x >> 5, lane = threadIdx.x & 31;
    const int row = blockIdx.x * 8 + warp;      // = b*Ns + s
    const int b = row / Ns;
    const float* L = logits + (size_t)row * Nd;

    float tv[16]; int ti[16];
#pragma unroll
    for (int i = 0; i < 16; i++) { tv[i] = -INFINITY; ti[i] = 0x40000000; }

    // per-lane top-16 over strided candidates (sorted ascending)
    for (int n = lane; n < Nd; n += 32) {
        float c = L[n];
        if (c > tv[0]) {
            tv[0] = c; ti[0] = n;
#pragma unroll
            for (int i = 0; i < 15; i++) {
                if (tv[i] > tv[i + 1]) {
                    float t = tv[i]; tv[i] = tv[i + 1]; tv[i + 1] = t;
                    int u = ti[i]; ti[i] = ti[i + 1]; ti[i + 1] = u;
                }
            }
        }
    }

    // spill lane-private sorted list (descending) to shared for dynamic idx
#pragma unroll
    for (int j = 0; j < 16; j++) {
        skey[warp][j][lane] = fmono(tv[15 - j]);
        sidx[warp][j][lane] = ti[15 - j];
    }

    // merge: 16x [redux-max on keys, redux-min on idx for tie-break, pop]
    float sel_v = 0.f; int sel_i = 0;
    int pos = 0;
#pragma unroll 1
    for (int it = 0; it < 16; ++it) {
        uint32_t key = skey[warp][pos][lane];
        int idx = sidx[warp][pos][lane];
        uint32_t mx = __reduce_max_sync(0xffffffffu, key);
        unsigned cand = (key == mx) ? (unsigned)idx : 0x7fffffffu;
        unsigned mni = __reduce_min_sync(0xffffffffu, cand);
        pos += (key == mx && (unsigned)idx == mni) ? 1 : 0;
        if (lane == it) { sel_v = fdemono(mx); sel_i = (int)mni; }
    }

    // signed softmax over the 16 selected values (lanes 0..15 own one each)
    float a_ = (lane < 16) ? fabsf(sel_v) : -INFINITY;
    float m = a_;
#pragma unroll
    for (int o = 16; o; o >>= 1) m = fmaxf(m, __shfl_xor_sync(0xffffffffu, m, o));
    float e = (lane < 16) ? expf(a_ - m) : 0.f;
    float ssum = e;
#pragma unroll
    for (int o = 16; o; o >>= 1) ssum += __shfl_xor_sync(0xffffffffu, ssum, o);
    float sgn = (sel_v > 0.f) ? 1.f : ((sel_v < 0.f) ? -1.f : 0.f);
    float st = srcstate[row];
    float sp = fmaxf(st, 0.f) + log1pf(expf(-fabsf(st)));
    float gate = 1.f;
    if (gatep) gate = 1.f / (1.f + expf(-*gatep));
    float cc = sgn * (e / ssum) * sp * gate;

    if (lane < 16) atomicAdd(ds + (size_t)b * Nd + sel_i, cc);

    const float* srow = srcval + (size_t)row * DIM;
    float4 xr[4];
#pragma unroll
    for (int t = 0; t < 4; t++)
        xr[t] = *(const float4*)(srow + (lane << 2) + (t << 7));
#pragma unroll 1
    for (int i = 0; i < 16; i++) {
        float ci = __shfl_sync(0xffffffffu, cc, i);
        int   di = __shfl_sync(0xffffffffu, sel_i, i);
        float* dst = dv + ((size_t)b * Nd + di) * DIM + (lane << 2);
#pragma unroll
        for (int t = 0; t < 4; t++) {
            asm volatile("red.global.add.v4.f32 [%0], {%1, %2, %3, %4};"
                         :: "l"(dst + (t << 7)),
                            "f"(ci * xr[t].x), "f"(ci * xr[t].y),
                            "f"(ci * xr[t].z), "f"(ci * xr[t].w)
                         : "memory");
        }
    }
}

// ---------------- fused apply: LN rows + signed-softmax state (self-clean) ---
__global__ void __launch_bounds__(256)
apply_both(const float* __restrict__ st, float* __restrict__ ds,
           float* __restrict__ s_out,
           const float* __restrict__ val, float* __restrict__ dvv,
           float* __restrict__ v_out,
           const float* __restrict__ gamma, const float* __restrict__ beta,
           int Nd)
{
    GRID_DEP_SYNC();
    const int tid = threadIdx.x;
    const int nln = BATCH * Nd;
    __shared__ float ss[256], sq[256];
    if ((int)blockIdx.x < nln) {
        const int row = blockIdx.x;
        float2 x = ((const float2*)(val + (size_t)row * DIM))[tid];
        float2 d = ((float2*)(dvv + (size_t)row * DIM))[tid];
        ((float2*)(dvv + (size_t)row * DIM))[tid] = make_float2(0.f, 0.f);
        x.x += d.x; x.y += d.y;
        ss[tid] = x.x + x.y;
        sq[tid] = x.x * x.x + x.y * x.y;
        __syncthreads();
        for (int o = 128; o; o >>= 1) {
            if (tid < o) { ss[tid] += ss[tid + o]; sq[tid] += sq[tid + o]; }
            __syncthreads();
        }
        float mean = ss[0] * (1.f / DIM);
        float var = sq[0] * (1.f / DIM) - mean * mean;
        float rs = rsqrtf(var + 1e-5f);
        float2 g = ((const float2*)gamma)[tid];
        float2 bb = ((const float2*)beta)[tid];
        float2 y;
        y.x = (x.x - mean) * rs * g.x + bb.x;
        y.y = (x.y - mean) * rs * g.y + bb.y;
        ((float2*)(v_out + (size_t)row * DIM))[tid] = y;
    } else {
        const int b = blockIdx.x - nln;
        const float* S = st + (size_t)b * Nd;
        float* D = ds + (size_t)b * Nd;
        float x[4]; float mx = -INFINITY;
#pragma unroll
        for (int i = 0; i < 4; i++) {
            int n = tid + i * 256;
            x[i] = (n < Nd) ? (S[n] + D[n]) : 0.f;
            if (n < Nd) { mx = fmaxf(mx, fabsf(x[i])); D[n] = 0.f; }
        }
        ss[tid] = mx; __syncthreads();
        for (int o = 128; o; o >>= 1) {
            if (tid < o) ss[tid] = fmaxf(ss[tid], ss[tid + o]);
            __syncthreads();
        }
        mx = ss[0]; __syncthreads();
        float e[4]; float s = 0.f;
#pragma unroll
        for (int i = 0; i < 4; i++) {
            int n = tid + i * 256;
            e[i] = (n < Nd) ? expf(fabsf(x[i]) - mx) : 0.f;
            s += e[i];
        }
        ss[tid] = s; __syncthreads();
        for (int o = 128; o; o >>= 1) {
            if (tid < o) ss[tid] += ss[tid + o];
            __syncthreads();
        }
        float inv = 1.f / ss[0];
#pragma unroll
        for (int i = 0; i < 4; i++) {
            int n = tid + i * 256;
            if (n < Nd) {
                float sgn = (x[i] > 0.f) ? 1.f : ((x[i] < 0.f) ? -1.f : 0.f);
                s_out[(size_t)b * Nd + n] = sgn * e[i] * inv;
            }
        }
    }
}

// ---------------- plain row softmax (read attention) -------------------------
__global__ void __launch_bounds__(256)
row_softmax(float* __restrict__ L, int N)
{
    GRID_DEP_SYNC();
    const int row = blockIdx.x, tid = threadIdx.x;
    float* p = L + (size_t)row * N;
    float x[4]; float mx = -INFINITY;
#pragma unroll
    for (int i = 0; i < 4; i++) {
        int n = tid + i * 256;
        x[i] = (n < N) ? p[n] : -INFINITY;
        mx = fmaxf(mx, x[i]);
    }
    __shared__ float sm[256];
    sm[tid] = mx; __syncthreads();
    for (int o = 128; o; o >>= 1) { if (tid < o) sm[tid] = fmaxf(sm[tid], sm[tid + o]); __syncthreads(); }
    mx = sm[0]; __syncthreads();
    float e[4]; float s = 0.f;
#pragma unroll
    for (int i = 0; i < 4; i++) {
        int n = tid + i * 256;
        e[i] = (n < N) ? expf(x[i] - mx) : 0.f;
        s += e[i];
    }
    sm[tid] = s; __syncthreads();
    for (int o = 128; o; o >>= 1) { if (tid < o) sm[tid] += sm[tid + o]; __syncthreads(); }
    float inv = 1.f / sm[0];
#pragma unroll
    for (int i = 0; i < 4; i++) {
        int n = tid + i * 256;
        if (n < N) p[n] = e[i] * inv;
    }
}

// ---------------- host orchestration -----------------------------------------
// PDL launch: successor may launch while predecessor runs; GRID_DEP_SYNC at
// each kernel's first statement preserves exact data ordering.
template <typename K, typename... Args>
static inline void launch_pdl(K kern, dim3 grid, dim3 block, size_t smem,
                              cudaStream_t st, Args... args)
{
    cudaLaunchConfig_t cfg = {};
    cfg.gridDim = grid; cfg.blockDim = block;
    cfg.dynamicSmemBytes = smem; cfg.stream = st;
    cudaLaunchAttribute at[1];
    at[0].id = cudaLaunchAttributeProgrammaticStreamSerialization;
    at[0].val.programmaticStreamSerializationAllowed = 1;
    cfg.attrs = at; cfg.numAttrs = 1;
    cudaLaunchKernelEx(&cfg, kern, args...);
}

static inline void launch_atb(const float* A0, const float* A1,
                              const float* B0, const float* B1,
                              float* C, int M, int N, cudaStream_t st)
{
    if (M >= 1024 && N >= 128 && (M % 128) == 0 && (N % 128) == 0)
        launch_pdl(atb_big, dim3(N / 128, M / 128, BATCH), dim3(256), 67584, st,
                   A0, A1, B0, B1, C, M, N);
    else
        launch_pdl(atb_gemm, dim3(N / 64, M / 64, BATCH), dim3(256), 0, st,
                   A0, A1, B0, B1, C, M, N);
}

static void run_trans(const float* srcv, const float* srcs, int Ns,
                      const float* dstv, int Nd,
                      const float* W, const float* gatep,
                      const float* st_in, const float* vl_in,
                      float* s_out, float* v_out,
                      const float* gamma, const float* beta,
                      float* q, float* q2, float* kb, float* kb2,
                      float* lg, float* dsb, float* dvb)
{
    launch_pdl(qk_gemm_sk, dim3(2, Ns / 64 + Nd / 64, BATCH), dim3(256), 0,
               (cudaStream_t)0, srcv, dstv, W, q, q2, kb, kb2, Ns, Nd);
    launch_atb(q, q2, kb, kb2, lg, Ns, Nd, 0);
    launch_pdl(topk_scatter, dim3(BATCH * Ns / 8), dim3(256), 0,
               (cudaStream_t)0, lg, srcv, srcs, dsb, dvb, gatep, Ns, Nd);
    launch_pdl(apply_both, dim3(BATCH * Nd + BATCH), dim3(256), 0,
               (cudaStream_t)0, st_in, dsb, s_out, vl_in, dvb, v_out,
               gamma, beta, Nd);
}

// transition with PRECOMPUTED q partials (k-only projection in the chain)
static void run_trans_preq(const float* srcv, const float* srcs, int Ns,
                           const float* dstv, int Nd,
                           const float* W, const float* gatep,
                           const float* st_in, const float* vl_in,
                           float* s_out, float* v_out,
                           const float* gamma, const float* beta,
                           const float* qpre, const float* qpre2,
                           float* kb, float* kb2,
                           float* lg, float* dsb, float* dvb)
{
    launch_pdl(qk_gemm_sk, dim3(2, Nd / 64, BATCH), dim3(256), 0,
               (cudaStream_t)0, srcv, dstv, W, kb, kb2, kb, kb2, 0, Nd);
    launch_atb(qpre, qpre2, kb, kb2, lg, Ns, Nd, 0);
    launch_pdl(topk_scatter, dim3(BATCH * Ns / 8), dim3(256), 0,
               (cudaStream_t)0, lg, srcv, srcs, dsb, dvb, gatep, Ns, Nd);
    launch_pdl(apply_both, dim3(BATCH * Nd + BATCH), dim3(256), 0,
               (cudaStream_t)0, st_in, dsb, s_out, vl_in, dvb, v_out,
               gamma, beta, Nd);
}

static void read_level(int l, const float* mv, int S,
                       const float* rr, const float* rp, const float* rg,
                       const float* tok_val, float* out,
                       float* rq, float* kr, float* kr2, float* lgr, float* r,
                       cudaStream_t st)
{
    const size_t RQS = (size_t)3 * BATCH * TOK * RDIM;
    const size_t RQL = (size_t)BATCH * TOK * RDIM;
    launch_pdl(qk_gemm_sk, dim3(2, S / 64, BATCH), dim3(256), 0, st,
               (const float*)mv, (const float*)mv, rr + (size_t)l * 2 * DR,
               kr, kr2, kr, kr2, 0, S);
    launch_atb(rq + (size_t)l * RQL, rq + RQS + (size_t)l * RQL, kr, kr2,
               lgr, TOK, S, st);
    launch_pdl(row_softmax, dim3(BATCH * TOK), dim3(256), 0, st, lgr, S);
    launch_pdl(ab_gemm_tf32, dim3(DIM / 128, TOK / 128, BATCH), dim3(256), 0, st,
               (const float*)lgr, mv, r, (const float*)nullptr,
               (const float*)nullptr, TOK, DIM, S,
               (long long)TOK * S, (long long)S * DIM, (long long)TOK * DIM);
    launch_pdl(ab_gemm_tf32, dim3(DIM / 128, TOK / 128, BATCH), dim3(256), 0, st,
               (const float*)r, rp + (size_t)l * DIM * DIM, out,
               (l == 0) ? tok_val : (const float*)out, rg + l, TOK, DIM, DIM,
               (long long)TOK * DIM, (long long)0, (long long)TOK * DIM);
}

extern "C" void kernel_launch(void* const* d_in, const int* in_sizes, int n_in,
                              void* d_out, int out_size)
{
    const float* tok_val   = (const float*)d_in[0];
    const float* tok_state = (const float*)d_in[1];
    const float* ms0 = (const float*)d_in[2];
    const float* mv0 = (const float*)d_in[3];
    const float* ms1 = (const float*)d_in[4];
    const float* mv1 = (const float*)d_in[5];
    const float* ms2 = (const float*)d_in[6];
    const float* mv2 = (const float*)d_in[7];
    const float* wr  = (const float*)d_in[8];
    const float* pr  = (const float*)d_in[9];
    const float* lr  = (const float*)d_in[10];
    const float* sr  = (const float*)d_in[11];
    const float* sg  = (const float*)d_in[12];
    const float* lgam = (const float*)d_in[13];
    const float* lbet = (const float*)d_in[14];
    const float* rr  = (const float*)d_in[15];
    const float* rp  = (const float*)d_in[16];
    const float* rg  = (const float*)d_in[17];
    float* out = (float*)d_out;

    static bool _attr = []() {
        cudaFuncSetAttribute(atb_big,
            cudaFuncAttributeMaxDynamicSharedMemorySize, 67584);
        return true;
    }();
    (void)_attr;
    static cudaStream_t s1 = []() {
        cudaStream_t s; cudaStreamCreateWithFlags(&s, cudaStreamNonBlocking);
        return s;
    }();
    static cudaEvent_t evH = []() {
        cudaEvent_t e; cudaEventCreateWithFlags(&e, cudaEventDisableTiming);
        return e;
    }();
    static cudaEvent_t evFill = []() {
        cudaEvent_t e; cudaEventCreateWithFlags(&e, cudaEventDisableTiming);
        return e;
    }();
    static cudaEvent_t evQ4 = []() {
        cudaEvent_t e; cudaEventCreateWithFlags(&e, cudaEventDisableTiming);
        return e;
    }();
    static cudaEvent_t evQ7 = []() {
        cudaEvent_t e; cudaEventCreateWithFlags(&e, cudaEventDisableTiming);
        return e;
    }();
    static cudaEvent_t ev0 = []() {
        cudaEvent_t e; cudaEventCreateWithFlags(&e, cudaEventDisableTiming);
        return e;
    }();
    static cudaEvent_t ev1 = []() {
        cudaEvent_t e; cudaEventCreateWithFlags(&e, cudaEventDisableTiming);
        return e;
    }();
    static cudaEvent_t ev2 = []() {
        cudaEvent_t e; cudaEventCreateWithFlags(&e, cudaEventDisableTiming);
        return e;
    }();
    static cudaEvent_t evF = []() {
        cudaEvent_t e; cudaEventCreateWithFlags(&e, cudaEventDisableTiming);
        return e;
    }();

    float *q, *q2, *kb, *kb2, *kr, *kr2, *rq, *lg, *lgr, *dsb, *dvb;
    float *q4a, *q4b, *q7a, *q7b;
    float *s0, *v0, *s1v, *v1, *s2, *v2, *r;
    cudaGetSymbolAddress((void**)&q,   g_q);
    cudaGetSymbolAddress((void**)&q2,  g_q2);
    cudaGetSymbolAddress((void**)&kb,  g_k);
    cudaGetSymbolAddress((void**)&kb2, g_k2);
    cudaGetSymbolAddress((void**)&kr,  g_kr);
    cudaGetSymbolAddress((void**)&kr2, g_kr2);
    cudaGetSymbolAddress((void**)&rq,  g_rq);
    cudaGetSymbolAddress((void**)&q4a, g_q4a);
    cudaGetSymbolAddress((void**)&q4b, g_q4b);
    cudaGetSymbolAddress((void**)&q7a, g_q7a);
    cudaGetSymbolAddress((void**)&q7b, g_q7b);
    cudaGetSymbolAddress((void**)&lg,  g_lg);
    cudaGetSymbolAddress((void**)&lgr, g_lgr);
    cudaGetSymbolAddress((void**)&dsb, g_ds);
    cudaGetSymbolAddress((void**)&dvb, g_dv);
    cudaGetSymbolAddress((void**)&s0,  g_s0);
    cudaGetSymbolAddress((void**)&v0,  g_v0);
    cudaGetSymbolAddress((void**)&s1v, g_s1);
    cudaGetSymbolAddress((void**)&v1,  g_v1);
    cudaGetSymbolAddress((void**)&s2,  g_s2);
    cudaGetSymbolAddress((void**)&v2,  g_v2);
    cudaGetSymbolAddress((void**)&r,   g_r);

    // fork: head work on s1 overlapping t1 on stream 0 (same as R13)
    cudaEventRecord(evH, 0);
    cudaStreamWaitEvent(s1, evH, 0);
    launch_pdl(fill_ds_dv, dim3(2048), dim3(256), 0, s1,
               dsb, (float4*)dvb, BATCH * NS0, BATCH * NS0 * DIM / 4);
    cudaEventRecord(evFill, s1);
    launch_pdl(rq_gemm_sk, dim3(2, TOK / 64, 3 * BATCH), dim3(256), 0, s1,
               tok_val, rr, rq);
    launch_pdl(qk_gemm_sk, dim3(2, TOK / 64, BATCH), dim3(256), 0, s1,
               tok_val, tok_val, sr + 0 * 2 * DR, q4a, q4b, q4a, q4b, TOK, 0);
    cudaEventRecord(evQ4, s1);

    // ---- level 0, transition 1 (inlined: needs fill-join before topk) ----
    launch_pdl(qk_gemm_sk, dim3(2, TOK / 64 + NS0 / 64, BATCH), dim3(256), 0,
               (cudaStream_t)0, tok_val, mv0, wr, q, q2, kb, kb2, TOK, NS0);
    launch_atb(q, q2, kb, kb2, lg, TOK, NS0, 0);
    cudaStreamWaitEvent((cudaStream_t)0, evFill, 0);
    launch_pdl(topk_scatter, dim3(BATCH * TOK / 8), dim3(256), 0,
               (cudaStream_t)0, (const float*)lg, tok_val, tok_state,
               dsb, dvb, (const float*)nullptr, TOK, NS0);
    launch_pdl(apply_both, dim3(BATCH * NS0 + BATCH), dim3(256), 0,
               (cudaStream_t)0, ms0, dsb, s0, mv0, dvb, v0, lgam, lbet, NS0);
    run_trans(v0, s0, NS0, v0, NS0, pr + 0 * 2 * DR, nullptr,
              s0, v0, s0, v0, lgam + 0 * DIM, lbet + 0 * DIM,
              q, q2, kb, kb2, lg, dsb, dvb);
    cudaEventRecord(ev0, 0);
    // s1: t7 q precompute (v0 @ sr[1][0]) then read level 0
    cudaStreamWaitEvent(s1, ev0, 0);
    launch_pdl(qk_gemm_sk, dim3(2, NS0 / 64, BATCH), dim3(256), 0, s1,
               (const float*)v0, (const float*)v0, sr + 1 * 2 * DR,
               q7a, q7b, q7a, q7b, NS0, 0);
    cudaEventRecord(evQ7, s1);
    read_level(0, v0, NS0, rr, rp, rg, tok_val, out, rq, kr, kr2, lgr, r, s1);

    // ---- level 1 ----
    run_trans(v0, s0, NS0, mv1, NS1, lr + 0 * 2 * DR, nullptr,
              ms1, mv1, s1v, v1, lgam + 1 * DIM, lbet + 1 * DIM,
              q, q2, kb, kb2, lg, dsb, dvb);
    cudaStreamWaitEvent((cudaStream_t)0, evQ4, 0);
    run_trans_preq(tok_val, tok_state, TOK, v1, NS1, sr + 0 * 2 * DR, sg + 0,
                   s1v, v1, s1v, v1, lgam + 1 * DIM, lbet + 1 * DIM,
                   q4a, q4b, kb, kb2, lg, dsb, dvb);
    run_trans(v1, s1v, NS1, v1, NS1, pr + 1 * 2 * DR, nullptr,
              s1v, v1, s1v, v1, lgam + 1 * DIM, lbet + 1 * DIM,
              q, q2, kb, kb2, lg, dsb, dvb);
    cudaEventRecord(ev1, 0);
    cudaStreamWaitEvent(s1, ev1, 0);
    read_level(1, v1, NS1, rr, rp, rg, tok_val, out, rq, kr, kr2, lgr, r, s1);

    // ---- level 2 ----
    run_trans(v1, s1v, NS1, mv2, NS2, lr + 1 * 2 * DR, nullptr,
              ms2, mv2, s2, v2, lgam + 2 * DIM, lbet + 2 * DIM,
              q, q2, kb, kb2, lg, dsb, dvb);
    cudaStreamWaitEvent((cudaStream_t)0, evQ7, 0);
    run_trans_preq(v0, s0, NS0, v2, NS2, sr + 1 * 2 * DR, sg + 1,
                   s2, v2, s2, v2, lgam + 2 * DIM, lbet + 2 * DIM,
                   q7a, q7b, kb, kb2, lg, dsb, dvb);
    run_trans(v2, s2, NS2, v2, NS2, pr + 2 * 2 * DR, nullptr,
              s2, v2, s2, v2, lgam + 2 * DIM, lbet + 2 * DIM,
              q, q2, kb, kb2, lg, dsb, dvb);
    cudaEventRecord(ev2, 0);
    cudaStreamWaitEvent(s1, ev2, 0);
    read_level(2, v2, NS2, rr, rp, rg, tok_val, out, rq, kr, kr2, lgr, r, s1);

    // join read stream back into the main (captured) stream
    cudaEventRecord(evF, s1);
    cudaStreamWaitEvent((cudaStream_t)0, evF, 0);
}

// round 15
// speedup vs baseline: 1.2903x; 1.0281x over previous
#include <cuda_runtime.h>
#include <math.h>
#include <stdint.h>

#define BATCH 4
#define TOK   1024
#define DIM   512
#define RDIM  64
#define NS0   1024
#define NS1   256
#define NS2   64
#define DR    (DIM*RDIM)   /* 32768 */

#if defined(__CUDA_ARCH__) && __CUDA_ARCH__ >= 900
#define GRID_DEP_SYNC() cudaGridDependencySynchronize()
#else
#define GRID_DEP_SYNC() ((void)0)
#endif

// ---------------- scratch (static device memory; no cudaMalloc) -------------
__device__ float g_q [BATCH*TOK*RDIM];
__device__ float g_q2[BATCH*TOK*RDIM];
__device__ float g_k [BATCH*NS0*RDIM];
__device__ float g_k2[BATCH*NS0*RDIM];
__device__ float g_kr [BATCH*NS0*RDIM];     // read-path k partials (stream s1)
__device__ float g_kr2[BATCH*NS0*RDIM];
__device__ float g_rq[2*3*BATCH*TOK*RDIM];  // [split][route][b] read-path q parts
__device__ float g_q4a[BATCH*TOK*RDIM];     // t4 (tok->L1 skip) q partials
__device__ float g_q4b[BATCH*TOK*RDIM];
__device__ float g_q7a[BATCH*NS0*RDIM];     // t7 (v0->L2 skip) q partials
__device__ float g_q7b[BATCH*NS0*RDIM];
__device__ float g_lg [BATCH*TOK*NS0];      // transition logits (16MB)
__device__ float g_lgr[BATCH*TOK*NS0];      // read-path logits/attn (16MB)
__device__ float g_ds[BATCH*NS0];
__device__ float g_dv[BATCH*NS0*DIM];
__device__ float g_s0[BATCH*NS0];
__device__ float g_v0[BATCH*NS0*DIM];
__device__ float g_s1[BATCH*NS1];
__device__ float g_v1[BATCH*NS1*DIM];
__device__ float g_s2[BATCH*NS2];
__device__ float g_v2[BATCH*NS2*DIM];
__device__ float g_r [BATCH*TOK*DIM];

// ---------------- tf32 helpers ------------------------------------------------
__device__ __forceinline__ uint32_t f2tf32(float x) {
    uint32_t u;
    asm("cvt.rna.tf32.f32 %0, %1;" : "=r"(u) : "f"(x));
    return u;
}
__device__ __forceinline__ void mma_tf32(float* c, uint32_t a0, uint32_t a1,
                                         uint32_t a2, uint32_t a3,
                                         uint32_t b0, uint32_t b1) {
    asm volatile(
        "mma.sync.aligned.m16n8k8.row.col.f32.tf32.tf32.f32 "
        "{%0,%1,%2,%3}, {%4,%5,%6,%7}, {%8,%9}, {%0,%1,%2,%3};"
        : "+f"(c[0]), "+f"(c[1]), "+f"(c[2]), "+f"(c[3])
        : "r"(a0), "r"(a1), "r"(a2), "r"(a3), "r"(b0), "r"(b1));
}

// order-preserving monotone encoding of float (total order, -inf lowest)
__device__ __forceinline__ uint32_t fmono(float x) {
    uint32_t u = __float_as_uint(x);
    return (u & 0x80000000u) ? ~u : (u | 0x80000000u);
}
__device__ __forceinline__ float fdemono(uint32_t k) {
    uint32_t u = (k & 0x80000000u) ? (k & 0x7fffffffu) : ~k;
    return __uint_as_float(u);
}

// ---------------- fused zero of ds + dv (head only) --------------------------
__global__ void fill_ds_dv(float* __restrict__ ds, float4* __restrict__ dv4,
                           int nds, int ndv4) {
    GRID_DEP_SYNC();
    const int stride = gridDim.x * blockDim.x;
    const int i0 = blockIdx.x * blockDim.x + threadIdx.x;
    for (int j = i0; j < nds; j += stride) ds[j] = 0.f;
    const float4 z = make_float4(0.f, 0.f, 0.f, 0.f);
    for (int j = i0; j < ndv4; j += stride) dv4[j] = z;
}

// ============ split-K projection GEMM core (64x64 tile, K=256 slice) =========
// K-tile widened 16 -> 32: each thread prefetches 4 float4 (MLP=4) to hide
// L2/DRAM latency at the low grid-limited occupancy these kernels run at.
__device__ __forceinline__ void proj_body(const float* __restrict__ Ab,
                                          const float* __restrict__ Bb,
                                          float* __restrict__ Cb, int m0)
{
    __shared__ float sAt[32][68];
    __shared__ float sBt[32][68];
    const int tid = threadIdx.x;
    const int tx = tid & 15, ty = tid >> 4;
    const int arow = tid >> 2, ak4 = (tid & 3) << 2;   // A row 0..63, col 0/4/8/12
    const int bk = tid >> 4,  bn4 = (tid & 15) << 2;   // B k-row 0..15, col 0..60

    float acc[4][4];
#pragma unroll
    for (int i = 0; i < 4; i++)
#pragma unroll
        for (int j = 0; j < 4; j++) acc[i][j] = 0.f;

    const float* arow_p = Ab + (size_t)(m0 + arow) * DIM;
    float4 pa0 = *(const float4*)(arow_p + ak4);
    float4 pa1 = *(const float4*)(arow_p + 16 + ak4);
    float4 pb0 = *(const float4*)(Bb + (size_t)bk * RDIM + bn4);
    float4 pb1 = *(const float4*)(Bb + (size_t)(bk + 16) * RDIM + bn4);
    sAt[ak4 + 0][arow] = pa0.x; sAt[ak4 + 1][arow] = pa0.y;
    sAt[ak4 + 2][arow] = pa0.z; sAt[ak4 + 3][arow] = pa0.w;
    sAt[16 + ak4 + 0][arow] = pa1.x; sAt[16 + ak4 + 1][arow] = pa1.y;
    sAt[16 + ak4 + 2][arow] = pa1.z; sAt[16 + ak4 + 3][arow] = pa1.w;
    *(float4*)&sBt[bk][bn4]      = pb0;
    *(float4*)&sBt[bk + 16][bn4] = pb1;
    __syncthreads();

    for (int k0 = 32; k0 < 256; k0 += 32) {
        pa0 = *(const float4*)(arow_p + k0 + ak4);
        pa1 = *(const float4*)(arow_p + k0 + 16 + ak4);
        pb0 = *(const float4*)(Bb + (size_t)(k0 + bk) * RDIM + bn4);
        pb1 = *(const float4*)(Bb + (size_t)(k0 + bk + 16) * RDIM + bn4);
#pragma unroll
        for (int kk = 0; kk < 32; kk++) {
            float4 a  = *(const float4*)&sAt[kk][ty << 2];
            float4 bq = *(const float4*)&sBt[kk][tx << 2];
            float aa[4] = {a.x, a.y, a.z, a.w};
            float bb[4] = {bq.x, bq.y, bq.z, bq.w};
#pragma unroll
            for (int i = 0; i < 4; i++)
#pragma unroll
                for (int j = 0; j < 4; j++) acc[i][j] += aa[i] * bb[j];
        }
        __syncthreads();
        sAt[ak4 + 0][arow] = pa0.x; sAt[ak4 + 1][arow] = pa0.y;
        sAt[ak4 + 2][arow] = pa0.z; sAt[ak4 + 3][arow] = pa0.w;
        sAt[16 + ak4 + 0][arow] = pa1.x; sAt[16 + ak4 + 1][arow] = pa1.y;
        sAt[16 + ak4 + 2][arow] = pa1.z; sAt[16 + ak4 + 3][arow] = pa1.w;
        *(float4*)&sBt[bk][bn4]      = pb0;
        *(float4*)&sBt[bk + 16][bn4] = pb1;
        __syncthreads();
    }
#pragma unroll
    for (int kk = 0; kk < 32; kk++) {
        float4 a  = *(const float4*)&sAt[kk][ty << 2];
        float4 bq = *(const float4*)&sBt[kk][tx << 2];
        float aa[4] = {a.x, a.y, a.z, a.w};
        float bb[4] = {bq.x, bq.y, bq.z, bq.w};
#pragma unroll
        for (int i = 0; i < 4; i++)
#pragma unroll
            for (int j = 0; j < 4; j++) acc[i][j] += aa[i] * bb[j];
    }
#pragma unroll
    for (int i = 0; i < 4; i++) {
        size_t idx = (size_t)(m0 + (ty << 2) + i) * RDIM + (tx << 2);
        *(float4*)(Cb + idx) = make_float4(acc[i][0], acc[i][1], acc[i][2], acc[i][3]);
    }
}

// dual q/k projection, split-K=2. grid (2, Ns/64 + Nd/64, BATCH)
// Ns=0 -> k-only; Nd=0 -> q-only.
__global__ void __launch_bounds__(256)
qk_gemm_sk(const float* __restrict__ src, const float* __restrict__ dst,
           const float* __restrict__ W,
           float* __restrict__ q0, float* __restrict__ q1,
           float* __restrict__ k0, float* __restrict__ k1, int Ns, int Nd)
{
    GRID_DEP_SYNC();
    const int b = blockIdx.z, s = blockIdx.x;
    const int nyq = Ns >> 6;
    const bool isQ = (int)blockIdx.y < nyq;
    const float* Ab = (isQ ? src + (size_t)b * Ns * DIM
                           : dst + (size_t)b * Nd * DIM) + s * 256;
    const float* Bb = (isQ ? W : W + DR) + (size_t)s * 256 * RDIM;
    float* Cb = isQ ? (s ? q1 : q0) + (size_t)b * Ns * RDIM
                    : (s ? k1 : k0) + (size_t)b * Nd * RDIM;
    const int m0 = (isQ ? blockIdx.y : blockIdx.y - nyq) * 64;
    proj_body(Ab, Bb, Cb, m0);
}

// read-path q projections: 3 routes in one launch. grid (2, TOK/64, 3*BATCH)
__global__ void __launch_bounds__(256)
rq_gemm_sk(const float* __restrict__ tok, const float* __restrict__ rr,
           float* __restrict__ rqp)
{
    GRID_DEP_SYNC();
    const int s = blockIdx.x;
    const int l = blockIdx.z / BATCH, b = blockIdx.z % BATCH;
    const float* Ab = tok + (size_t)b * TOK * DIM + s * 256;
    const float* Bb = rr + (size_t)l * 2 * DR + (size_t)s * 256 * RDIM;
    float* Cb = rqp + ((size_t)(s * 3 + l) * BATCH + b) * TOK * RDIM;
    proj_body(Ab, Bb, Cb, blockIdx.y * 64);
}

// ---------------- logits GEMM (64x64 tile, small cases) ----------------------
__global__ void __launch_bounds__(256)
atb_gemm(const float* __restrict__ A0, const float* __restrict__ A1,
         const float* __restrict__ B0, const float* __restrict__ B1,
         float* __restrict__ C, int M, int N)
{
    GRID_DEP_SYNC();
    __shared__ float sAt[64][68];
    __shared__ float sBt[64][68];
    const int b = blockIdx.z;
    const size_t aoff = (size_t)b * M * 64;
    const size_t boff = (size_t)b * N * 64;
    const int m0 = blockIdx.y * 64, n0 = blockIdx.x * 64;
    const int tid = threadIdx.x;
    const int tx = tid & 15, ty = tid >> 4;
    const int row = tid >> 2, q4 = (tid & 3) << 2;

#pragma unroll
    for (int c = 0; c < 4; c++) {
        const int kk0 = q4 + c * 16;
        const size_t ai = aoff + (size_t)(m0 + row) * 64 + kk0;
        const size_t bi = boff + (size_t)(n0 + row) * 64 + kk0;
        float4 av = *(const float4*)(A0 + ai);
        float4 a1 = *(const float4*)(A1 + ai);
        float4 bv = *(const float4*)(B0 + bi);
        float4 b1 = *(const float4*)(B1 + bi);
        av.x += a1.x; av.y += a1.y; av.z += a1.z; av.w += a1.w;
        bv.x += b1.x; bv.y += b1.y; bv.z += b1.z; bv.w += b1.w;
        sAt[kk0 + 0][row] = av.x; sAt[kk0 + 1][row] = av.y;
        sAt[kk0 + 2][row] = av.z; sAt[kk0 + 3][row] = av.w;
        sBt[kk0 + 0][row] = bv.x; sBt[kk0 + 1][row] = bv.y;
        sBt[kk0 + 2][row] = bv.z; sBt[kk0 + 3][row] = bv.w;
    }
    __syncthreads();

    float acc[4][4];
#pragma unroll
    for (int i = 0; i < 4; i++)
#pragma unroll
        for (int j = 0; j < 4; j++) acc[i][j] = 0.f;
#pragma unroll 16
    for (int kk = 0; kk < 64; kk++) {
        float4 a  = *(const float4*)&sAt[kk][ty << 2];
        float4 bq = *(const float4*)&sBt[kk][tx << 2];
        float aa[4] = {a.x, a.y, a.z, a.w};
        float bb[4] = {bq.x, bq.y, bq.z, bq.w};
#pragma unroll
        for (int i = 0; i < 4; i++)
#pragma unroll
            for (int j = 0; j < 4; j++) acc[i][j] += aa[i] * bb[j];
    }
#pragma unroll
    for (int i = 0; i < 4; i++) {
        size_t idx = (size_t)b * M * N + (size_t)(m0 + (ty << 2) + i) * N + n0 + (tx << 2);
        float4 cv = make_float4(0.125f * acc[i][0], 0.125f * acc[i][1],
                                0.125f * acc[i][2], 0.125f * acc[i][3]);
        *(float4*)(C + idx) = cv;
    }
}

// ---------------- logits GEMM big: 128x128 tile, 8x8 micro, K=64 resident ----
__global__ void __launch_bounds__(256)
atb_big(const float* __restrict__ A0, const float* __restrict__ A1,
        const float* __restrict__ B0, const float* __restrict__ B1,
        float* __restrict__ C, int M, int N)
{
    GRID_DEP_SYNC();
    extern __shared__ float sm[];
    float (*sAt)[132] = (float(*)[132])sm;
    float (*sBt)[132] = (float(*)[132])(sm + 64 * 132);
    const int b = blockIdx.z;
    const size_t aoff = (size_t)b * M * 64;
    const size_t boff = (size_t)b * N * 64;
    const int m0 = blockIdx.y * 128, n0 = blockIdx.x * 128;
    const int tid = threadIdx.x;
    const int tx = tid & 15, ty = tid >> 4;

    for (int idx = tid; idx < 2048; idx += 256) {
        const int row = idx >> 4, kq = (idx & 15) << 2;
        const size_t ai = aoff + (size_t)(m0 + row) * 64 + kq;
        const size_t bi = boff + (size_t)(n0 + row) * 64 + kq;
        float4 av = *(const float4*)(A0 + ai);
        float4 a1 = *(const float4*)(A1 + ai);
        float4 bv = *(const float4*)(B0 + bi);
        float4 b1 = *(const float4*)(B1 + bi);
        av.x += a1.x; av.y += a1.y; av.z += a1.z; av.w += a1.w;
        bv.x += b1.x; bv.y += b1.y; bv.z += b1.z; bv.w += b1.w;
        sAt[kq + 0][row] = av.x; sAt[kq + 1][row] = av.y;
        sAt[kq + 2][row] = av.z; sAt[kq + 3][row] = av.w;
        sBt[kq + 0][row] = bv.x; sBt[kq + 1][row] = bv.y;
        sBt[kq + 2][row] = bv.z; sBt[kq + 3][row] = bv.w;
    }
    __syncthreads();

    float acc[8][8];
#pragma unroll
    for (int i = 0; i < 8; i++)
#pragma unroll
        for (int j = 0; j < 8; j++) acc[i][j] = 0.f;

#pragma unroll 8
    for (int kk = 0; kk < 64; kk++) {
        float4 a0 = *(const float4*)&sAt[kk][ty << 2];
        float4 a1 = *(const float4*)&sAt[kk][64 + (ty << 2)];
        float4 b0 = *(const float4*)&sBt[kk][tx << 2];
        float4 b1 = *(const float4*)&sBt[kk][64 + (tx << 2)];
        float av[8] = {a0.x, a0.y, a0.z, a0.w, a1.x, a1.y, a1.z, a1.w};
        float bv[8] = {b0.x, b0.y, b0.z, b0.w, b1.x, b1.y, b1.z, b1.w};
#pragma unroll
        for (int i = 0; i < 8; i++)
#pragma unroll
            for (int j = 0; j < 8; j++) acc[i][j] += av[i] * bv[j];
    }

#pragma unroll
    for (int ih = 0; ih < 2; ih++)
#pragma unroll
        for (int i = 0; i < 4; i++) {
            const int m = m0 + ih * 64 + (ty << 2) + i;
            const size_t base = (size_t)b * M * N + (size_t)m * N + n0;
#pragma unroll
            for (int jh = 0; jh < 2; jh++) {
                const int r = ih * 4 + i;
                float4 cv = make_float4(0.125f * acc[r][jh * 4 + 0],
                                        0.125f * acc[r][jh * 4 + 1],
                                        0.125f * acc[r][jh * 4 + 2],
                                        0.125f * acc[r][jh * 4 + 3]);
                *(float4*)(C + base + jh * 64 + (tx << 2)) = cv;
            }
        }
}

// ---------------- tf32 tensor-core GEMM: 128x128 tile, warp 64x32 ------------
__global__ void __launch_bounds__(256)
ab_gemm_tf32(const float* __restrict__ A, const float* __restrict__ Bm,
             float* __restrict__ C, const float* __restrict__ Cinit,
             const float* __restrict__ gatep,
             int M, int N, int K,
             long long strA, long long strB, long long strC)
{
    GRID_DEP_SYNC();
    __shared__ uint32_t sA[16][136];
    __shared__ uint32_t sB[16][136];
    const int b = blockIdx.z;
    const float* Ab = A  + (size_t)b * strA;
    const float* Bb = Bm + (size_t)b * strB;
    const int m0 = blockIdx.y * 128, n0 = blockIdx.x * 128;
    const int tid = threadIdx.x, lane = tid & 31, warp = tid >> 5;
    const int wm = (warp >> 2) * 64, wn = (warp & 3) * 32;
    const int gid = lane >> 2, tid4 = lane & 3;
    const int arow = tid >> 1, ak = (tid & 1) * 8;
    const int bk = tid >> 4, bn = (tid & 15) * 8;

    float acc[4][4][4];
#pragma unroll
    for (int mi = 0; mi < 4; mi++)
#pragma unroll
        for (int ni = 0; ni < 4; ni++)
#pragma unroll
            for (int t = 0; t < 4; t++) acc[mi][ni][t] = 0.f;

    float4 pa0, pa1, pb0, pb1;
    {
        const float* ap = Ab + (size_t)(m0 + arow) * K + ak;
        pa0 = *(const float4*)ap; pa1 = *(const float4*)(ap + 4);
        const float* bp = Bb + (size_t)bk * N + n0 + bn;
        pb0 = *(const float4*)bp; pb1 = *(const float4*)(bp + 4);
        sA[ak + 0][arow] = f2tf32(pa0.x); sA[ak + 1][arow] = f2tf32(pa0.y);
        sA[ak + 2][arow] = f2tf32(pa0.z); sA[ak + 3][arow] = f2tf32(pa0.w);
        sA[ak + 4][arow] = f2tf32(pa1.x); sA[ak + 5][arow] = f2tf32(pa1.y);
        sA[ak + 6][arow] = f2tf32(pa1.z); sA[ak + 7][arow] = f2tf32(pa1.w);
        sB[bk][bn + 0] = f2tf32(pb0.x); sB[bk][bn + 1] = f2tf32(pb0.y);
        sB[bk][bn + 2] = f2tf32(pb0.z); sB[bk][bn + 3] = f2tf32(pb0.w);
        sB[bk][bn + 4] = f2tf32(pb1.x); sB[bk][bn + 5] = f2tf32(pb1.y);
        sB[bk][bn + 6] = f2tf32(pb1.z); sB[bk][bn + 7] = f2tf32(pb1.w);
        __syncthreads();
    }

#define TF32_COMPUTE_TILE                                                     \
    _Pragma("unroll")                                                         \
    for (int ks = 0; ks < 2; ks++) {                                          \
        const int kk = ks * 8;                                                \
        uint32_t af[4][4], bf[4][2];                                          \
        _Pragma("unroll")                                                     \
        for (int mi = 0; mi < 4; mi++) {                                      \
            const int m = wm + mi * 16 + gid;                                 \
            af[mi][0] = sA[kk + tid4][m];                                     \
            af[mi][1] = sA[kk + tid4][m + 8];                                 \
            af[mi][2] = sA[kk + 4 + tid4][m];                                 \
            af[mi][3] = sA[kk + 4 + tid4][m + 8];                             \
        }                                                                     \
        _Pragma("unroll")                                                     \
        for (int ni = 0; ni < 4; ni++) {                                      \
            const int n = wn + ni * 8 + gid;                                  \
            bf[ni][0] = sB[kk + tid4][n];                                     \
            bf[ni][1] = sB[kk + 4 + tid4][n];                                 \
        }                                                                     \
        _Pragma("unroll")                                                     \
        for (int mi = 0; mi < 4; mi++)                                        \
            _Pragma("unroll")                                                 \
            for (int ni = 0; ni < 4; ni++)                                    \
                mma_tf32(acc[mi][ni], af[mi][0], af[mi][1], af[mi][2],        \
                         af[mi][3], bf[ni][0], bf[ni][1]);                    \
    }

    for (int k0 = 16; k0 < K; k0 += 16) {
        const float* ap = Ab + (size_t)(m0 + arow) * K + k0 + ak;
        pa0 = *(const float4*)ap; pa1 = *(const float4*)(ap + 4);
        const float* bp = Bb + (size_t)(k0 + bk) * N + n0 + bn;
        pb0 = *(const float4*)bp; pb1 = *(const float4*)(bp + 4);
        TF32_COMPUTE_TILE
        __syncthreads();
        sA[ak + 0][arow] = f2tf32(pa0.x); sA[ak + 1][arow] = f2tf32(pa0.y);
        sA[ak + 2][arow] = f2tf32(pa0.z); sA[ak + 3][arow] = f2tf32(pa0.w);
        sA[ak + 4][arow] = f2tf32(pa1.x); sA[ak + 5][arow] = f2tf32(pa1.y);
        sA[ak + 6][arow] = f2tf32(pa1.z); sA[ak + 7][arow] = f2tf32(pa1.w);
        sB[bk][bn + 0] = f2tf32(pb0.x); sB[bk][bn + 1] = f2tf32(pb0.y);
        sB[bk][bn + 2] = f2tf32(pb0.z); sB[bk][bn + 3] = f2tf32(pb0.w);
        sB[bk][bn + 4] = f2tf32(pb1.x); sB[bk][bn + 5] = f2tf32(pb1.y);
        sB[bk][bn + 6] = f2tf32(pb1.z); sB[bk][bn + 7] = f2tf32(pb1.w);
        __syncthreads();
    }
    TF32_COMPUTE_TILE
#undef TF32_COMPUTE_TILE

    float alpha = 1.f;
    if (gatep) alpha = 1.f / (1.f + expf(-*gatep));
#pragma unroll
    for (int mi = 0; mi < 4; mi++) {
#pragma unroll
        for (int ni = 0; ni < 4; ni++) {
            const int r0 = m0 + wm + mi * 16 + gid;
            const int cc = n0 + wn + ni * 8 + 2 * tid4;
            const size_t i0 = (size_t)b * strC + (size_t)r0 * N + cc;
            const size_t i1 = (size_t)b * strC + (size_t)(r0 + 8) * N + cc;
            float2 v0 = make_float2(alpha * acc[mi][ni][0], alpha * acc[mi][ni][1]);
            float2 v1 = make_float2(alpha * acc[mi][ni][2], alpha * acc[mi][ni][3]);
            if (Cinit) {
                float2 c0 = *(const float2*)(Cinit + i0);
                float2 c1 = *(const float2*)(Cinit + i1);
                v0.x += c0.x; v0.y += c0.y;
                v1.x += c1.x; v1.y += c1.y;
            }
            *(float2*)(C + i0) = v0;
            *(float2*)(C + i1) = v1;
        }
    }
}

// ---------------- top-k + signed softmax + softplus-state scatter ------------
// one warp per source row. tie-break matches jax.lax.top_k (lower index first).
// Scan: fully-unrolled bubble insert (register-resident). Merge: smem lists +
// redux argmax (R10 win). FROZEN — two variants regressed.
__global__ void __launch_bounds__(256)
topk_scatter(const float* __restrict__ logits, const float* __restrict__ srcval,
             const float* __restrict__ srcstate, float* __restrict__ ds,
             float* __restrict__ dv, const float* __restrict__ gatep,
             int Ns, int Nd)
{
    GRID_DEP_SYNC();
    __shared__ uint32_t skey[8][16][32];
    __shared__ int      sidx[8][16][32];
    const int warp = threadIdx.x >> 5, lane = threadIdx.x & 31;
    const int row = blockIdx.x * 8 + warp;      // = b*Ns + s
    const int b = row / Ns;
    const float* L = logits + (size_t)row * Nd;

    float tv[16]; int ti[16];
#pragma unroll
    for (int i = 0; i < 16; i++) { tv[i] = -INFINITY; ti[i] = 0x40000000; }

    // per-lane top-16 over strided candidates (sorted ascending)
    for (int n = lane; n < Nd; n += 32) {
        float c = L[n];
        if (c > tv[0]) {
            tv[0] = c; ti[0] = n;
#pragma unroll
            for (int i = 0; i < 15; i++) {
                if (tv[i] > tv[i + 1]) {
                    float t = tv[i]; tv[i] = tv[i + 1]; tv[i + 1] = t;
                    int u = ti[i]; ti[i] = ti[i + 1]; ti[i + 1] = u;
                }
            }
        }
    }

    // spill lane-private sorted list (descending) to shared for dynamic idx
#pragma unroll
    for (int j = 0; j < 16; j++) {
        skey[warp][j][lane] = fmono(tv[15 - j]);
        sidx[warp][j][lane] = ti[15 - j];
    }

    // merge: 16x [redux-max on keys, redux-min on idx for tie-break, pop]
    float sel_v = 0.f; int sel_i = 0;
    int pos = 0;
#pragma unroll 1
    for (int it = 0; it < 16; ++it) {
        uint32_t key = skey[warp][pos][lane];
        int idx = sidx[warp][pos][lane];
        uint32_t mx = __reduce_max_sync(0xffffffffu, key);
        unsigned cand = (key == mx) ? (unsigned)idx : 0x7fffffffu;
        unsigned mni = __reduce_min_sync(0xffffffffu, cand);
        pos += (key == mx && (unsigned)idx == mni) ? 1 : 0;
        if (lane == it) { sel_v = fdemono(mx); sel_i = (int)mni; }
    }

    // signed softmax over the 16 selected values (lanes 0..15 own one each)
    float a_ = (lane < 16) ? fabsf(sel_v) : -INFINITY;
    float m = a_;
#pragma unroll
    for (int o = 16; o; o >>= 1) m = fmaxf(m, __shfl_xor_sync(0xffffffffu, m, o));
    float e = (lane < 16) ? expf(a_ - m) : 0.f;
    float ssum = e;
#pragma unroll
    for (int o = 16; o; o >>= 1) ssum += __shfl_xor_sync(0xffffffffu, ssum, o);
    float sgn = (sel_v > 0.f) ? 1.f : ((sel_v < 0.f) ? -1.f : 0.f);
    float st = srcstate[row];
    float sp = fmaxf(st, 0.f) + log1pf(expf(-fabsf(st)));
    float gate = 1.f;
    if (gatep) gate = 1.f / (1.f + expf(-*gatep));
    float cc = sgn * (e / ssum) * sp * gate;

    if (lane < 16) atomicAdd(ds + (size_t)b * Nd + sel_i, cc);

    const float* srow = srcval + (size_t)row * DIM;
    float4 xr[4];
#pragma unroll
    for (int t = 0; t < 4; t++)
        xr[t] = *(const float4*)(srow + (lane << 2) + (t << 7));
#pragma unroll 1
    for (int i = 0; i < 16; i++) {
        float ci = __shfl_sync(0xffffffffu, cc, i);
        int   di = __shfl_sync(0xffffffffu, sel_i, i);
        float* dst = dv + ((size_t)b * Nd + di) * DIM + (lane << 2);
#pragma unroll
        for (int t = 0; t < 4; t++) {
            asm volatile("red.global.add.v4.f32 [%0], {%1, %2, %3, %4};"
                         :: "l"(dst + (t << 7)),
                            "f"(ci * xr[t].x), "f"(ci * xr[t].y),
                            "f"(ci * xr[t].z), "f"(ci * xr[t].w)
                         : "memory");
        }
    }
}

// ---------------- fused apply: LN rows + signed-softmax state (self-clean) ---
__global__ void __launch_bounds__(256)
apply_both(const float* __restrict__ st, float* __restrict__ ds,
           float* __restrict__ s_out,
           const float* __restrict__ val, float* __restrict__ dvv,
           float* __restrict__ v_out,
           const float* __restrict__ gamma, const float* __restrict__ beta,
           int Nd)
{
    GRID_DEP_SYNC();
    const int tid = threadIdx.x;
    const int nln = BATCH * Nd;
    __shared__ float ss[256], sq[256];
    if ((int)blockIdx.x < nln) {
        const int row = blockIdx.x;
        float2 x = ((const float2*)(val + (size_t)row * DIM))[tid];
        float2 d = ((float2*)(dvv + (size_t)row * DIM))[tid];
        ((float2*)(dvv + (size_t)row * DIM))[tid] = make_float2(0.f, 0.f);
        x.x += d.x; x.y += d.y;
        ss[tid] = x.x + x.y;
        sq[tid] = x.x * x.x + x.y * x.y;
        __syncthreads();
        for (int o = 128; o; o >>= 1) {
            if (tid < o) { ss[tid] += ss[tid + o]; sq[tid] += sq[tid + o]; }
            __syncthreads();
        }
        float mean = ss[0] * (1.f / DIM);
        float var = sq[0] * (1.f / DIM) - mean * mean;
        float rs = rsqrtf(var + 1e-5f);
        float2 g = ((const float2*)gamma)[tid];
        float2 bb = ((const float2*)beta)[tid];
        float2 y;
        y.x = (x.x - mean) * rs * g.x + bb.x;
        y.y = (x.y - mean) * rs * g.y + bb.y;
        ((float2*)(v_out + (size_t)row * DIM))[tid] = y;
    } else {
        const int b = blockIdx.x - nln;
        const float* S = st + (size_t)b * Nd;
        float* D = ds + (size_t)b * Nd;
        float x[4]; float mx = -INFINITY;
#pragma unroll
        for (int i = 0; i < 4; i++) {
            int n = tid + i * 256;
            x[i] = (n < Nd) ? (S[n] + D[n]) : 0.f;
            if (n < Nd) { mx = fmaxf(mx, fabsf(x[i])); D[n] = 0.f; }
        }
        ss[tid] = mx; __syncthreads();
        for (int o = 128; o; o >>= 1) {
            if (tid < o) ss[tid] = fmaxf(ss[tid], ss[tid + o]);
            __syncthreads();
        }
        mx = ss[0]; __syncthreads();
        float e[4]; float s = 0.f;
#pragma unroll
        for (int i = 0; i < 4; i++) {
            int n = tid + i * 256;
            e[i] = (n < Nd) ? expf(fabsf(x[i]) - mx) : 0.f;
            s += e[i];
        }
        ss[tid] = s; __syncthreads();
        for (int o = 128; o; o >>= 1) {
            if (tid < o) ss[tid] += ss[tid + o];
            __syncthreads();
        }
        float inv = 1.f / ss[0];
#pragma unroll
        for (int i = 0; i < 4; i++) {
            int n = tid + i * 256;
            if (n < Nd) {
                float sgn = (x[i] > 0.f) ? 1.f : ((x[i] < 0.f) ? -1.f : 0.f);
                s_out[(size_t)b * Nd + n] = sgn * e[i] * inv;
            }
        }
    }
}

// ---------------- plain row softmax (read attention) -------------------------
__global__ void __launch_bounds__(256)
row_softmax(float* __restrict__ L, int N)
{
    GRID_DEP_SYNC();
    const int row = blockIdx.x, tid = threadIdx.x;
    float* p = L + (size_t)row * N;
    float x[4]; float mx = -INFINITY;
#pragma unroll
    for (int i = 0; i < 4; i++) {
        int n = tid + i * 256;
        x[i] = (n < N) ? p[n] : -INFINITY;
        mx = fmaxf(mx, x[i]);
    }
    __shared__ float sm[256];
    sm[tid] = mx; __syncthreads();
    for (int o = 128; o; o >>= 1) { if (tid < o) sm[tid] = fmaxf(sm[tid], sm[tid + o]); __syncthreads(); }
    mx = sm[0]; __syncthreads();
    float e[4]; float s = 0.f;
#pragma unroll
    for (int i = 0; i < 4; i++) {
        int n = tid + i * 256;
        e[i] = (n < N) ? expf(x[i] - mx) : 0.f;
        s += e[i];
    }
    sm[tid] = s; __syncthreads();
    for (int o = 128; o; o >>= 1) { if (tid < o) sm[tid] += sm[tid + o]; __syncthreads(); }
    float inv = 1.f / sm[0];
#pragma unroll
    for (int i = 0; i < 4; i++) {
        int n = tid + i * 256;
        if (n < N) p[n] = e[i] * inv;
    }
}

// ---------------- host orchestration -----------------------------------------
// PDL launch: successor may launch while predecessor runs; GRID_DEP_SYNC at
// each kernel's first statement preserves exact data ordering.
template <typename K, typename... Args>
static inline void launch_pdl(K kern, dim3 grid, dim3 block, size_t smem,
                              cudaStream_t st, Args... args)
{
    cudaLaunchConfig_t cfg = {};
    cfg.gridDim = grid; cfg.blockDim = block;
    cfg.dynamicSmemBytes = smem; cfg.stream = st;
    cudaLaunchAttribute at[1];
    at[0].id = cudaLaunchAttributeProgrammaticStreamSerialization;
    at[0].val.programmaticStreamSerializationAllowed = 1;
    cfg.attrs = at; cfg.numAttrs = 1;
    cudaLaunchKernelEx(&cfg, kern, args...);
}

static inline void launch_atb(const float* A0, const float* A1,
                              const float* B0, const float* B1,
                              float* C, int M, int N, cudaStream_t st)
{
    if (M >= 1024 && N >= 128 && (M % 128) == 0 && (N % 128) == 0)
        launch_pdl(atb_big, dim3(N / 128, M / 128, BATCH), dim3(256), 67584, st,
                   A0, A1, B0, B1, C, M, N);
    else
        launch_pdl(atb_gemm, dim3(N / 64, M / 64, BATCH), dim3(256), 0, st,
                   A0, A1, B0, B1, C, M, N);
}

static void run_trans(const float* srcv, const float* srcs, int Ns,
                      const float* dstv, int Nd,
                      const float* W, const float* gatep,
                      const float* st_in, const float* vl_in,
                      float* s_out, float* v_out,
                      const float* gamma, const float* beta,
                      float* q, float* q2, float* kb, float* kb2,
                      float* lg, float* dsb, float* dvb)
{
    launch_pdl(qk_gemm_sk, dim3(2, Ns / 64 + Nd / 64, BATCH), dim3(256), 0,
               (cudaStream_t)0, srcv, dstv, W, q, q2, kb, kb2, Ns, Nd);
    launch_atb(q, q2, kb, kb2, lg, Ns, Nd, 0);
    launch_pdl(topk_scatter, dim3(BATCH * Ns / 8), dim3(256), 0,
               (cudaStream_t)0, lg, srcv, srcs, dsb, dvb, gatep, Ns, Nd);
    launch_pdl(apply_both, dim3(BATCH * Nd + BATCH), dim3(256), 0,
               (cudaStream_t)0, st_in, dsb, s_out, vl_in, dvb, v_out,
               gamma, beta, Nd);
}

// transition with PRECOMPUTED q partials (k-only projection in the chain)
static void run_trans_preq(const float* srcv, const float* srcs, int Ns,
                           const float* dstv, int Nd,
                           const float* W, const float* gatep,
                           const float* st_in, const float* vl_in,
                           float* s_out, float* v_out,
                           const float* gamma, const float* beta,
                           const float* qpre, const float* qpre2,
                           float* kb, float* kb2,
                           float* lg, float* dsb, float* dvb)
{
    launch_pdl(qk_gemm_sk, dim3(2, Nd / 64, BATCH), dim3(256), 0,
               (cudaStream_t)0, srcv, dstv, W, kb, kb2, kb, kb2, 0, Nd);
    launch_atb(qpre, qpre2, kb, kb2, lg, Ns, Nd, 0);
    launch_pdl(topk_scatter, dim3(BATCH * Ns / 8), dim3(256), 0,
               (cudaStream_t)0, lg, srcv, srcs, dsb, dvb, gatep, Ns, Nd);
    launch_pdl(apply_both, dim3(BATCH * Nd + BATCH), dim3(256), 0,
               (cudaStream_t)0, st_in, dsb, s_out, vl_in, dvb, v_out,
               gamma, beta, Nd);
}

static void read_level(int l, const float* mv, int S,
                       const float* rr, const float* rp, const float* rg,
                       const float* tok_val, float* out,
                       float* rq, float* kr, float* kr2, float* lgr, float* r,
                       cudaStream_t st)
{
    const size_t RQS = (size_t)3 * BATCH * TOK * RDIM;
    const size_t RQL = (size_t)BATCH * TOK * RDIM;
    launch_pdl(qk_gemm_sk, dim3(2, S / 64, BATCH), dim3(256), 0, st,
               (const float*)mv, (const float*)mv, rr + (size_t)l * 2 * DR,
               kr, kr2, kr, kr2, 0, S);
    launch_atb(rq + (size_t)l * RQL, rq + RQS + (size_t)l * RQL, kr, kr2,
               lgr, TOK, S, st);
    launch_pdl(row_softmax, dim3(BATCH * TOK), dim3(256), 0, st, lgr, S);
    launch_pdl(ab_gemm_tf32, dim3(DIM / 128, TOK / 128, BATCH), dim3(256), 0, st,
               (const float*)lgr, mv, r, (const float*)nullptr,
               (const float*)nullptr, TOK, DIM, S,
               (long long)TOK * S, (long long)S * DIM, (long long)TOK * DIM);
    launch_pdl(ab_gemm_tf32, dim3(DIM / 128, TOK / 128, BATCH), dim3(256), 0, st,
               (const float*)r, rp + (size_t)l * DIM * DIM, out,
               (l == 0) ? tok_val : (const float*)out, rg + l, TOK, DIM, DIM,
               (long long)TOK * DIM, (long long)0, (long long)TOK * DIM);
}

extern "C" void kernel_launch(void* const* d_in, const int* in_sizes, int n_in,
                              void* d_out, int out_size)
{
    const float* tok_val   = (const float*)d_in[0];
    const float* tok_state = (const float*)d_in[1];
    const float* ms0 = (const float*)d_in[2];
    const float* mv0 = (const float*)d_in[3];
    const float* ms1 = (const float*)d_in[4];
    const float* mv1 = (const float*)d_in[5];
    const float* ms2 = (const float*)d_in[6];
    const float* mv2 = (const float*)d_in[7];
    const float* wr  = (const float*)d_in[8];
    const float* pr  = (const float*)d_in[9];
    const float* lr  = (const float*)d_in[10];
    const float* sr  = (const float*)d_in[11];
    const float* sg  = (const float*)d_in[12];
    const float* lgam = (const float*)d_in[13];
    const float* lbet = (const float*)d_in[14];
    const float* rr  = (const float*)d_in[15];
    const float* rp  = (const float*)d_in[16];
    const float* rg  = (const float*)d_in[17];
    float* out = (float*)d_out;

    static bool _attr = []() {
        cudaFuncSetAttribute(atb_big,
            cudaFuncAttributeMaxDynamicSharedMemorySize, 67584);
        return true;
    }();
    (void)_attr;
    static cudaStream_t s1 = []() {
        cudaStream_t s; cudaStreamCreateWithFlags(&s, cudaStreamNonBlocking);
        return s;
    }();
    static cudaEvent_t evH = []() {
        cudaEvent_t e; cudaEventCreateWithFlags(&e, cudaEventDisableTiming);
        return e;
    }();
    static cudaEvent_t evFill = []() {
        cudaEvent_t e; cudaEventCreateWithFlags(&e, cudaEventDisableTiming);
        return e;
    }();
    static cudaEvent_t evQ4 = []() {
        cudaEvent_t e; cudaEventCreateWithFlags(&e, cudaEventDisableTiming);
        return e;
    }();
    static cudaEvent_t evQ7 = []() {
        cudaEvent_t e; cudaEventCreateWithFlags(&e, cudaEventDisableTiming);
        return e;
    }();
    static cudaEvent_t ev0 = []() {
        cudaEvent_t e; cudaEventCreateWithFlags(&e, cudaEventDisableTiming);
        return e;
    }();
    static cudaEvent_t ev1 = []() {
        cudaEvent_t e; cudaEventCreateWithFlags(&e, cudaEventDisableTiming);
        return e;
    }();
    static cudaEvent_t ev2 = []() {
        cudaEvent_t e; cudaEventCreateWithFlags(&e, cudaEventDisableTiming);
        return e;
    }();
    static cudaEvent_t evF = []() {
        cudaEvent_t e; cudaEventCreateWithFlags(&e, cudaEventDisableTiming);
        return e;
    }();

    float *q, *q2, *kb, *kb2, *kr, *kr2, *rq, *lg, *lgr, *dsb, *dvb;
    float *q4a, *q4b, *q7a, *q7b;
    float *s0, *v0, *s1v, *v1, *s2, *v2, *r;
    cudaGetSymbolAddress((void**)&q,   g_q);
    cudaGetSymbolAddress((void**)&q2,  g_q2);
    cudaGetSymbolAddress((void**)&kb,  g_k);
    cudaGetSymbolAddress((void**)&kb2, g_k2);
    cudaGetSymbolAddress((void**)&kr,  g_kr);
    cudaGetSymbolAddress((void**)&kr2, g_kr2);
    cudaGetSymbolAddress((void**)&rq,  g_rq);
    cudaGetSymbolAddress((void**)&q4a, g_q4a);
    cudaGetSymbolAddress((void**)&q4b, g_q4b);
    cudaGetSymbolAddress((void**)&q7a, g_q7a);
    cudaGetSymbolAddress((void**)&q7b, g_q7b);
    cudaGetSymbolAddress((void**)&lg,  g_lg);
    cudaGetSymbolAddress((void**)&lgr, g_lgr);
    cudaGetSymbolAddress((void**)&dsb, g_ds);
    cudaGetSymbolAddress((void**)&dvb, g_dv);
    cudaGetSymbolAddress((void**)&s0,  g_s0);
    cudaGetSymbolAddress((void**)&v0,  g_v0);
    cudaGetSymbolAddress((void**)&s1v, g_s1);
    cudaGetSymbolAddress((void**)&v1,  g_v1);
    cudaGetSymbolAddress((void**)&s2,  g_s2);
    cudaGetSymbolAddress((void**)&v2,  g_v2);
    cudaGetSymbolAddress((void**)&r,   g_r);

    // fork: head work on s1 overlapping t1 on stream 0
    cudaEventRecord(evH, 0);
    cudaStreamWaitEvent(s1, evH, 0);
    launch_pdl(fill_ds_dv, dim3(2048), dim3(256), 0, s1,
               dsb, (float4*)dvb, BATCH * NS0, BATCH * NS0 * DIM / 4);
    cudaEventRecord(evFill, s1);
    launch_pdl(rq_gemm_sk, dim3(2, TOK / 64, 3 * BATCH), dim3(256), 0, s1,
               tok_val, rr, rq);
    launch_pdl(qk_gemm_sk, dim3(2, TOK / 64, BATCH), dim3(256), 0, s1,
               tok_val, tok_val, sr + 0 * 2 * DR, q4a, q4b, q4a, q4b, TOK, 0);
    cudaEventRecord(evQ4, s1);

    // ---- level 0, transition 1 (inlined: needs fill-join before topk) ----
    launch_pdl(qk_gemm_sk, dim3(2, TOK / 64 + NS0 / 64, BATCH), dim3(256), 0,
               (cudaStream_t)0, tok_val, mv0, wr, q, q2, kb, kb2, TOK, NS0);
    launch_atb(q, q2, kb, kb2, lg, TOK, NS0, 0);
    cudaStreamWaitEvent((cudaStream_t)0, evFill, 0);
    launch_pdl(topk_scatter, dim3(BATCH * TOK / 8), dim3(256), 0,
               (cudaStream_t)0, (const float*)lg, tok_val, tok_state,
               dsb, dvb, (const float*)nullptr, TOK, NS0);
    launch_pdl(apply_both, dim3(BATCH * NS0 + BATCH), dim3(256), 0,
               (cudaStream_t)0, ms0, dsb, s0, mv0, dvb, v0, lgam, lbet, NS0);
    run_trans(v0, s0, NS0, v0, NS0, pr + 0 * 2 * DR, nullptr,
              s0, v0, s0, v0, lgam + 0 * DIM, lbet + 0 * DIM,
              q, q2, kb, kb2, lg, dsb, dvb);
    cudaEventRecord(ev0, 0);
    // s1: t7 q precompute (v0 @ sr[1][0]) then read level 0
    cudaStreamWaitEvent(s1, ev0, 0);
    launch_pdl(qk_gemm_sk, dim3(2, NS0 / 64, BATCH), dim3(256), 0, s1,
               (const float*)v0, (const float*)v0, sr + 1 * 2 * DR,
               q7a, q7b, q7a, q7b, NS0, 0);
    cudaEventRecord(evQ7, s1);
    read_level(0, v0, NS0, rr, rp, rg, tok_val, out, rq, kr, kr2, lgr, r, s1);

    // ---- level 1 ----
    run_trans(v0, s0, NS0, mv1, NS1, lr + 0 * 2 * DR, nullptr,
              ms1, mv1, s1v, v1, lgam + 1 * DIM, lbet + 1 * DIM,
              q, q2, kb, kb2, lg, dsb, dvb);
    cudaStreamWaitEvent((cudaStream_t)0, evQ4, 0);
    run_trans_preq(tok_val, tok_state, TOK, v1, NS1, sr + 0 * 2 * DR, sg + 0,
                   s1v, v1, s1v, v1, lgam + 1 * DIM, lbet + 1 * DIM,
                   q4a, q4b, kb, kb2, lg, dsb, dvb);
    run_trans(v1, s1v, NS1, v1, NS1, pr + 1 * 2 * DR, nullptr,
              s1v, v1, s1v, v1, lgam + 1 * DIM, lbet + 1 * DIM,
              q, q2, kb, kb2, lg, dsb, dvb);
    cudaEventRecord(ev1, 0);
    cudaStreamWaitEvent(s1, ev1, 0);
    read_level(1, v1, NS1, rr, rp, rg, tok_val, out, rq, kr, kr2, lgr, r, s1);

    // ---- level 2 ----
    run_trans(v1, s1v, NS1, mv2, NS2, lr + 1 * 2 * DR, nullptr,
              ms2, mv2, s2, v2, lgam + 2 * DIM, lbet + 2 * DIM,
              q, q2, kb, kb2, lg, dsb, dvb);
    cudaStreamWaitEvent((cudaStream_t)0, evQ7, 0);
    run_trans_preq(v0, s0, NS0, v2, NS2, sr + 1 * 2 * DR, sg + 1,
                   s2, v2, s2, v2, lgam + 2 * DIM, lbet + 2 * DIM,
                   q7a, q7b, kb, kb2, lg, dsb, dvb);
    run_trans(v2, s2, NS2, v2, NS2, pr + 2 * 2 * DR, nullptr,
              s2, v2, s2, v2, lgam + 2 * DIM, lbet + 2 * DIM,
              q, q2, kb, kb2, lg, dsb, dvb);
    cudaEventRecord(ev2, 0);
    cudaStreamWaitEvent(s1, ev2, 0);
    read_level(2, v2, NS2, rr, rp, rg, tok_val, out, rq, kr, kr2, lgr, r, s1);

    // join read stream back into the main (captured) stream
    cudaEventRecord(evF, s1);
    cudaStreamWaitEvent((cudaStream_t)0, evF, 0);
}

// round 16
// speedup vs baseline: 1.3212x; 1.0240x over previous
#include <cuda_runtime.h>
#include <math.h>
#include <stdint.h>

#define BATCH 4
#define TOK   1024
#define DIM   512
#define RDIM  64
#define NS0   1024
#define NS1   256
#define NS2   64
#define DR    (DIM*RDIM)   /* 32768 */
#define SPLITK 4
#define KSLICE 128         /* DIM / SPLITK */

#if defined(__CUDA_ARCH__) && __CUDA_ARCH__ >= 900
#define GRID_DEP_SYNC() cudaGridDependencySynchronize()
#else
#define GRID_DEP_SYNC() ((void)0)
#endif

// ---------------- scratch (static device memory; no cudaMalloc) -------------
__device__ float g_q [SPLITK*BATCH*TOK*RDIM];
__device__ float g_k [SPLITK*BATCH*NS0*RDIM];
__device__ float g_kr[SPLITK*BATCH*NS0*RDIM];      // read-path k partials (s1)
__device__ float g_rq[SPLITK*3*BATCH*TOK*RDIM];    // [split][route][b] read q
__device__ float g_q4[SPLITK*BATCH*TOK*RDIM];      // t4 skip-q partials
__device__ float g_q7[SPLITK*BATCH*NS0*RDIM];      // t7 skip-q partials
__device__ float g_lg [BATCH*TOK*NS0];             // transition logits (16MB)
__device__ float g_lgr[BATCH*TOK*NS0];             // read-path logits/attn
__device__ float g_ds[BATCH*NS0];
__device__ float g_dv[BATCH*NS0*DIM];
__device__ float g_s0[BATCH*NS0];
__device__ float g_v0[BATCH*NS0*DIM];
__device__ float g_s1[BATCH*NS1];
__device__ float g_v1[BATCH*NS1*DIM];
__device__ float g_s2[BATCH*NS2];
__device__ float g_v2[BATCH*NS2*DIM];
__device__ float g_r [BATCH*TOK*DIM];

// ---------------- tf32 helpers ------------------------------------------------
__device__ __forceinline__ uint32_t f2tf32(float x) {
    uint32_t u;
    asm("cvt.rna.tf32.f32 %0, %1;" : "=r"(u) : "f"(x));
    return u;
}
__device__ __forceinline__ void mma_tf32(float* c, uint32_t a0, uint32_t a1,
                                         uint32_t a2, uint32_t a3,
                                         uint32_t b0, uint32_t b1) {
    asm volatile(
        "mma.sync.aligned.m16n8k8.row.col.f32.tf32.tf32.f32 "
        "{%0,%1,%2,%3}, {%4,%5,%6,%7}, {%8,%9}, {%0,%1,%2,%3};"
        : "+f"(c[0]), "+f"(c[1]), "+f"(c[2]), "+f"(c[3])
        : "r"(a0), "r"(a1), "r"(a2), "r"(a3), "r"(b0), "r"(b1));
}

// order-preserving monotone encoding of float (total order, -inf lowest)
__device__ __forceinline__ uint32_t fmono(float x) {
    uint32_t u = __float_as_uint(x);
    return (u & 0x80000000u) ? ~u : (u | 0x80000000u);
}
__device__ __forceinline__ float fdemono(uint32_t k) {
    uint32_t u = (k & 0x80000000u) ? (k & 0x7fffffffu) : ~k;
    return __uint_as_float(u);
}

// ---------------- fused zero of ds + dv (head only) --------------------------
__global__ void fill_ds_dv(float* __restrict__ ds, float4* __restrict__ dv4,
                           int nds, int ndv4) {
    GRID_DEP_SYNC();
    const int stride = gridDim.x * blockDim.x;
    const int i0 = blockIdx.x * blockDim.x + threadIdx.x;
    for (int j = i0; j < nds; j += stride) ds[j] = 0.f;
    const float4 z = make_float4(0.f, 0.f, 0.f, 0.f);
    for (int j = i0; j < ndv4; j += stride) dv4[j] = z;
}

// ============ split-K projection GEMM core (64x64 tile, K=128 slice) =========
// 32-deep K-tile: 4 float4 prefetches in flight (MLP=4).
__device__ __forceinline__ void proj_body(const float* __restrict__ Ab,
                                          const float* __restrict__ Bb,
                                          float* __restrict__ Cb, int m0)
{
    __shared__ float sAt[32][68];
    __shared__ float sBt[32][68];
    const int tid = threadIdx.x;
    const int tx = tid & 15, ty = tid >> 4;
    const int arow = tid >> 2, ak4 = (tid & 3) << 2;
    const int bk = tid >> 4,  bn4 = (tid & 15) << 2;

    float acc[4][4];
#pragma unroll
    for (int i = 0; i < 4; i++)
#pragma unroll
        for (int j = 0; j < 4; j++) acc[i][j] = 0.f;

    const float* arow_p = Ab + (size_t)(m0 + arow) * DIM;
    float4 pa0 = *(const float4*)(arow_p + ak4);
    float4 pa1 = *(const float4*)(arow_p + 16 + ak4);
    float4 pb0 = *(const float4*)(Bb + (size_t)bk * RDIM + bn4);
    float4 pb1 = *(const float4*)(Bb + (size_t)(bk + 16) * RDIM + bn4);
    sAt[ak4 + 0][arow] = pa0.x; sAt[ak4 + 1][arow] = pa0.y;
    sAt[ak4 + 2][arow] = pa0.z; sAt[ak4 + 3][arow] = pa0.w;
    sAt[16 + ak4 + 0][arow] = pa1.x; sAt[16 + ak4 + 1][arow] = pa1.y;
    sAt[16 + ak4 + 2][arow] = pa1.z; sAt[16 + ak4 + 3][arow] = pa1.w;
    *(float4*)&sBt[bk][bn4]      = pb0;
    *(float4*)&sBt[bk + 16][bn4] = pb1;
    __syncthreads();

    for (int k0 = 32; k0 < KSLICE; k0 += 32) {
        pa0 = *(const float4*)(arow_p + k0 + ak4);
        pa1 = *(const float4*)(arow_p + k0 + 16 + ak4);
        pb0 = *(const float4*)(Bb + (size_t)(k0 + bk) * RDIM + bn4);
        pb1 = *(const float4*)(Bb + (size_t)(k0 + bk + 16) * RDIM + bn4);
#pragma unroll
        for (int kk = 0; kk < 32; kk++) {
            float4 a  = *(const float4*)&sAt[kk][ty << 2];
            float4 bq = *(const float4*)&sBt[kk][tx << 2];
            float aa[4] = {a.x, a.y, a.z, a.w};
            float bb[4] = {bq.x, bq.y, bq.z, bq.w};
#pragma unroll
            for (int i = 0; i < 4; i++)
#pragma unroll
                for (int j = 0; j < 4; j++) acc[i][j] += aa[i] * bb[j];
        }
        __syncthreads();
        sAt[ak4 + 0][arow] = pa0.x; sAt[ak4 + 1][arow] = pa0.y;
        sAt[ak4 + 2][arow] = pa0.z; sAt[ak4 + 3][arow] = pa0.w;
        sAt[16 + ak4 + 0][arow] = pa1.x; sAt[16 + ak4 + 1][arow] = pa1.y;
        sAt[16 + ak4 + 2][arow] = pa1.z; sAt[16 + ak4 + 3][arow] = pa1.w;
        *(float4*)&sBt[bk][bn4]      = pb0;
        *(float4*)&sBt[bk + 16][bn4] = pb1;
        __syncthreads();
    }
#pragma unroll
    for (int kk = 0; kk < 32; kk++) {
        float4 a  = *(const float4*)&sAt[kk][ty << 2];
        float4 bq = *(const float4*)&sBt[kk][tx << 2];
        float aa[4] = {a.x, a.y, a.z, a.w};
        float bb[4] = {bq.x, bq.y, bq.z, bq.w};
#pragma unroll
        for (int i = 0; i < 4; i++)
#pragma unroll
            for (int j = 0; j < 4; j++) acc[i][j] += aa[i] * bb[j];
    }
#pragma unroll
    for (int i = 0; i < 4; i++) {
        size_t idx = (size_t)(m0 + (ty << 2) + i) * RDIM + (tx << 2);
        *(float4*)(Cb + idx) = make_float4(acc[i][0], acc[i][1], acc[i][2], acc[i][3]);
    }
}

// dual q/k projection, split-K=4. grid (4, Ns/64 + Nd/64, BATCH)
// Ns=0 -> k-only; Nd=0 -> q-only. Partials at base + s*stride.
__global__ void __launch_bounds__(256)
qk_gemm_sk(const float* __restrict__ src, const float* __restrict__ dst,
           const float* __restrict__ W,
           float* __restrict__ qb, float* __restrict__ kb,
           int Ns, int Nd, long long qstr, long long kstr)
{
    GRID_DEP_SYNC();
    const int b = blockIdx.z, s = blockIdx.x;
    const int nyq = Ns >> 6;
    const bool isQ = (int)blockIdx.y < nyq;
    const float* Ab = (isQ ? src + (size_t)b * Ns * DIM
                           : dst + (size_t)b * Nd * DIM) + s * KSLICE;
    const float* Bb = (isQ ? W : W + DR) + (size_t)s * KSLICE * RDIM;
    float* Cb = isQ ? qb + (size_t)s * qstr + (size_t)b * Ns * RDIM
                    : kb + (size_t)s * kstr + (size_t)b * Nd * RDIM;
    const int m0 = (isQ ? blockIdx.y : blockIdx.y - nyq) * 64;
    proj_body(Ab, Bb, Cb, m0);
}

// read-path q projections: 3 routes in one launch. grid (4, TOK/64, 3*BATCH)
__global__ void __launch_bounds__(256)
rq_gemm_sk(const float* __restrict__ tok, const float* __restrict__ rr,
           float* __restrict__ rqp)
{
    GRID_DEP_SYNC();
    const int s = blockIdx.x;
    const int l = blockIdx.z / BATCH, b = blockIdx.z % BATCH;
    const float* Ab = tok + (size_t)b * TOK * DIM + s * KSLICE;
    const float* Bb = rr + (size_t)l * 2 * DR + (size_t)s * KSLICE * RDIM;
    float* Cb = rqp + ((size_t)(s * 3 + l) * BATCH + b) * TOK * RDIM;
    proj_body(Ab, Bb, Cb, blockIdx.y * 64);
}

// ---------------- logits GEMM (64x64 tile): sums 4 split-K partials ----------
__global__ void __launch_bounds__(256)
atb_gemm(const float* __restrict__ A, const float* __restrict__ B2,
         float* __restrict__ C, int M, int N, long long sA, long long sB)
{
    GRID_DEP_SYNC();
    __shared__ float sAt[64][68];
    __shared__ float sBt[64][68];
    const int b = blockIdx.z;
    const size_t aoff = (size_t)b * M * 64;
    const size_t boff = (size_t)b * N * 64;
    const int m0 = blockIdx.y * 64, n0 = blockIdx.x * 64;
    const int tid = threadIdx.x;
    const int tx = tid & 15, ty = tid >> 4;
    const int row = tid >> 2, q4 = (tid & 3) << 2;

#pragma unroll
    for (int c = 0; c < 4; c++) {
        const int kk0 = q4 + c * 16;
        const size_t ai = aoff + (size_t)(m0 + row) * 64 + kk0;
        const size_t bi = boff + (size_t)(n0 + row) * 64 + kk0;
        float4 av = *(const float4*)(A + ai);
        float4 bv = *(const float4*)(B2 + bi);
#pragma unroll
        for (int s = 1; s < SPLITK; s++) {
            float4 a1 = *(const float4*)(A + (size_t)s * sA + ai);
            float4 b1 = *(const float4*)(B2 + (size_t)s * sB + bi);
            av.x += a1.x; av.y += a1.y; av.z += a1.z; av.w += a1.w;
            bv.x += b1.x; bv.y += b1.y; bv.z += b1.z; bv.w += b1.w;
        }
        sAt[kk0 + 0][row] = av.x; sAt[kk0 + 1][row] = av.y;
        sAt[kk0 + 2][row] = av.z; sAt[kk0 + 3][row] = av.w;
        sBt[kk0 + 0][row] = bv.x; sBt[kk0 + 1][row] = bv.y;
        sBt[kk0 + 2][row] = bv.z; sBt[kk0 + 3][row] = bv.w;
    }
    __syncthreads();

    float acc[4][4];
#pragma unroll
    for (int i = 0; i < 4; i++)
#pragma unroll
        for (int j = 0; j < 4; j++) acc[i][j] = 0.f;
#pragma unroll 16
    for (int kk = 0; kk < 64; kk++) {
        float4 a  = *(const float4*)&sAt[kk][ty << 2];
        float4 bq = *(const float4*)&sBt[kk][tx << 2];
        float aa[4] = {a.x, a.y, a.z, a.w};
        float bb[4] = {bq.x, bq.y, bq.z, bq.w};
#pragma unroll
        for (int i = 0; i < 4; i++)
#pragma unroll
            for (int j = 0; j < 4; j++) acc[i][j] += aa[i] * bb[j];
    }
#pragma unroll
    for (int i = 0; i < 4; i++) {
        size_t idx = (size_t)b * M * N + (size_t)(m0 + (ty << 2) + i) * N + n0 + (tx << 2);
        float4 cv = make_float4(0.125f * acc[i][0], 0.125f * acc[i][1],
                                0.125f * acc[i][2], 0.125f * acc[i][3]);
        *(float4*)(C + idx) = cv;
    }
}

// ---------------- logits GEMM big: 128x128 tile, sums 4 partials -------------
__global__ void __launch_bounds__(256)
atb_big(const float* __restrict__ A, const float* __restrict__ B2,
        float* __restrict__ C, int M, int N, long long sA, long long sB)
{
    GRID_DEP_SYNC();
    extern __shared__ float sm[];
    float (*sAt)[132] = (float(*)[132])sm;
    float (*sBt)[132] = (float(*)[132])(sm + 64 * 132);
    const int b = blockIdx.z;
    const size_t aoff = (size_t)b * M * 64;
    const size_t boff = (size_t)b * N * 64;
    const int m0 = blockIdx.y * 128, n0 = blockIdx.x * 128;
    const int tid = threadIdx.x;
    const int tx = tid & 15, ty = tid >> 4;

    for (int idx = tid; idx < 2048; idx += 256) {
        const int row = idx >> 4, kq = (idx & 15) << 2;
        const size_t ai = aoff + (size_t)(m0 + row) * 64 + kq;
        const size_t bi = boff + (size_t)(n0 + row) * 64 + kq;
        float4 av = *(const float4*)(A + ai);
        float4 bv = *(const float4*)(B2 + bi);
#pragma unroll
        for (int s = 1; s < SPLITK; s++) {
            float4 a1 = *(const float4*)(A + (size_t)s * sA + ai);
            float4 b1 = *(const float4*)(B2 + (size_t)s * sB + bi);
            av.x += a1.x; av.y += a1.y; av.z += a1.z; av.w += a1.w;
            bv.x += b1.x; bv.y += b1.y; bv.z += b1.z; bv.w += b1.w;
        }
        sAt[kq + 0][row] = av.x; sAt[kq + 1][row] = av.y;
        sAt[kq + 2][row] = av.z; sAt[kq + 3][row] = av.w;
        sBt[kq + 0][row] = bv.x; sBt[kq + 1][row] = bv.y;
        sBt[kq + 2][row] = bv.z; sBt[kq + 3][row] = bv.w;
    }
    __syncthreads();

    float acc[8][8];
#pragma unroll
    for (int i = 0; i < 8; i++)
#pragma unroll
        for (int j = 0; j < 8; j++) acc[i][j] = 0.f;

#pragma unroll 8
    for (int kk = 0; kk < 64; kk++) {
        float4 a0 = *(const float4*)&sAt[kk][ty << 2];
        float4 a1 = *(const float4*)&sAt[kk][64 + (ty << 2)];
        float4 b0 = *(const float4*)&sBt[kk][tx << 2];
        float4 b1 = *(const float4*)&sBt[kk][64 + (tx << 2)];
        float av[8] = {a0.x, a0.y, a0.z, a0.w, a1.x, a1.y, a1.z, a1.w};
        float bv[8] = {b0.x, b0.y, b0.z, b0.w, b1.x, b1.y, b1.z, b1.w};
#pragma unroll
        for (int i = 0; i < 8; i++)
#pragma unroll
            for (int j = 0; j < 8; j++) acc[i][j] += av[i] * bv[j];
    }

#pragma unroll
    for (int ih = 0; ih < 2; ih++)
#pragma unroll
        for (int i = 0; i < 4; i++) {
            const int m = m0 + ih * 64 + (ty << 2) + i;
            const size_t base = (size_t)b * M * N + (size_t)m * N + n0;
#pragma unroll
            for (int jh = 0; jh < 2; jh++) {
                const int r = ih * 4 + i;
                float4 cv = make_float4(0.125f * acc[r][jh * 4 + 0],
                                        0.125f * acc[r][jh * 4 + 1],
                                        0.125f * acc[r][jh * 4 + 2],
                                        0.125f * acc[r][jh * 4 + 3]);
                *(float4*)(C + base + jh * 64 + (tx << 2)) = cv;
            }
        }
}

// ---------------- tf32 tensor-core GEMM: 128x128 tile, warp 64x32 ------------
__global__ void __launch_bounds__(256)
ab_gemm_tf32(const float* __restrict__ A, const float* __restrict__ Bm,
             float* __restrict__ C, const float* __restrict__ Cinit,
             const float* __restrict__ gatep,
             int M, int N, int K,
             long long strA, long long strB, long long strC)
{
    GRID_DEP_SYNC();
    __shared__ uint32_t sA[16][136];
    __shared__ uint32_t sB[16][136];
    const int b = blockIdx.z;
    const float* Ab = A  + (size_t)b * strA;
    const float* Bb = Bm + (size_t)b * strB;
    const int m0 = blockIdx.y * 128, n0 = blockIdx.x * 128;
    const int tid = threadIdx.x, lane = tid & 31, warp = tid >> 5;
    const int wm = (warp >> 2) * 64, wn = (warp & 3) * 32;
    const int gid = lane >> 2, tid4 = lane & 3;
    const int arow = tid >> 1, ak = (tid & 1) * 8;
    const int bk = tid >> 4, bn = (tid & 15) * 8;

    float acc[4][4][4];
#pragma unroll
    for (int mi = 0; mi < 4; mi++)
#pragma unroll
        for (int ni = 0; ni < 4; ni++)
#pragma unroll
            for (int t = 0; t < 4; t++) acc[mi][ni][t] = 0.f;

    float4 pa0, pa1, pb0, pb1;
    {
        const float* ap = Ab + (size_t)(m0 + arow) * K + ak;
        pa0 = *(const float4*)ap; pa1 = *(const float4*)(ap + 4);
        const float* bp = Bb + (size_t)bk * N + n0 + bn;
        pb0 = *(const float4*)bp; pb1 = *(const float4*)(bp + 4);
        sA[ak + 0][arow] = f2tf32(pa0.x); sA[ak + 1][arow] = f2tf32(pa0.y);
        sA[ak + 2][arow] = f2tf32(pa0.z); sA[ak + 3][arow] = f2tf32(pa0.w);
        sA[ak + 4][arow] = f2tf32(pa1.x); sA[ak + 5][arow] = f2tf32(pa1.y);
        sA[ak + 6][arow] = f2tf32(pa1.z); sA[ak + 7][arow] = f2tf32(pa1.w);
        sB[bk][bn + 0] = f2tf32(pb0.x); sB[bk][bn + 1] = f2tf32(pb0.y);
        sB[bk][bn + 2] = f2tf32(pb0.z); sB[bk][bn + 3] = f2tf32(pb0.w);
        sB[bk][bn + 4] = f2tf32(pb1.x); sB[bk][bn + 5] = f2tf32(pb1.y);
        sB[bk][bn + 6] = f2tf32(pb1.z); sB[bk][bn + 7] = f2tf32(pb1.w);
        __syncthreads();
    }

#define TF32_COMPUTE_TILE                                                     \
    _Pragma("unroll")                                                         \
    for (int ks = 0; ks < 2; ks++) {                                          \
        const int kk = ks * 8;                                                \
        uint32_t af[4][4], bf[4][2];                                          \
        _Pragma("unroll")                                                     \
        for (int mi = 0; mi < 4; mi++) {                                      \
            const int m = wm + mi * 16 + gid;                                 \
            af[mi][0] = sA[kk + tid4][m];                                     \
            af[mi][1] = sA[kk + tid4][m + 8];                                 \
            af[mi][2] = sA[kk + 4 + tid4][m];                                 \
            af[mi][3] = sA[kk + 4 + tid4][m + 8];                             \
        }                                                                     \
        _Pragma("unroll")                                                     \
        for (int ni = 0; ni < 4; ni++) {                                      \
            const int n = wn + ni * 8 + gid;                                  \
            bf[ni][0] = sB[kk + tid4][n];                                     \
            bf[ni][1] = sB[kk + 4 + tid4][n];                                 \
        }                                                                     \
        _Pragma("unroll")                                                     \
        for (int mi = 0; mi < 4; mi++)                                        \
            _Pragma("unroll")                                                 \
            for (int ni = 0; ni < 4; ni++)                                    \
                mma_tf32(acc[mi][ni], af[mi][0], af[mi][1], af[mi][2],        \
                         af[mi][3], bf[ni][0], bf[ni][1]);                    \
    }

    for (int k0 = 16; k0 < K; k0 += 16) {
        const float* ap = Ab + (size_t)(m0 + arow) * K + k0 + ak;
        pa0 = *(const float4*)ap; pa1 = *(const float4*)(ap + 4);
        const float* bp = Bb + (size_t)(k0 + bk) * N + n0 + bn;
        pb0 = *(const float4*)bp; pb1 = *(const float4*)(bp + 4);
        TF32_COMPUTE_TILE
        __syncthreads();
        sA[ak + 0][arow] = f2tf32(pa0.x); sA[ak + 1][arow] = f2tf32(pa0.y);
        sA[ak + 2][arow] = f2tf32(pa0.z); sA[ak + 3][arow] = f2tf32(pa0.w);
        sA[ak + 4][arow] = f2tf32(pa1.x); sA[ak + 5][arow] = f2tf32(pa1.y);
        sA[ak + 6][arow] = f2tf32(pa1.z); sA[ak + 7][arow] = f2tf32(pa1.w);
        sB[bk][bn + 0] = f2tf32(pb0.x); sB[bk][bn + 1] = f2tf32(pb0.y);
        sB[bk][bn + 2] = f2tf32(pb0.z); sB[bk][bn + 3] = f2tf32(pb0.w);
        sB[bk][bn + 4] = f2tf32(pb1.x); sB[bk][bn + 5] = f2tf32(pb1.y);
        sB[bk][bn + 6] = f2tf32(pb1.z); sB[bk][bn + 7] = f2tf32(pb1.w);
        __syncthreads();
    }
    TF32_COMPUTE_TILE
#undef TF32_COMPUTE_TILE

    float alpha = 1.f;
    if (gatep) alpha = 1.f / (1.f + expf(-*gatep));
#pragma unroll
    for (int mi = 0; mi < 4; mi++) {
#pragma unroll
        for (int ni = 0; ni < 4; ni++) {
            const int r0 = m0 + wm + mi * 16 + gid;
            const int cc = n0 + wn + ni * 8 + 2 * tid4;
            const size_t i0 = (size_t)b * strC + (size_t)r0 * N + cc;
            const size_t i1 = (size_t)b * strC + (size_t)(r0 + 8) * N + cc;
            float2 v0 = make_float2(alpha * acc[mi][ni][0], alpha * acc[mi][ni][1]);
            float2 v1 = make_float2(alpha * acc[mi][ni][2], alpha * acc[mi][ni][3]);
            if (Cinit) {
                float2 c0 = *(const float2*)(Cinit + i0);
                float2 c1 = *(const float2*)(Cinit + i1);
                v0.x += c0.x; v0.y += c0.y;
                v1.x += c1.x; v1.y += c1.y;
            }
            *(float2*)(C + i0) = v0;
            *(float2*)(C + i1) = v1;
        }
    }
}

// ---------------- top-k + signed softmax + softplus-state scatter ------------
// FROZEN (R10 form): register scan + smem/redux merge. Exact lax.top_k ties.
__global__ void __launch_bounds__(256)
topk_scatter(const float* __restrict__ logits, const float* __restrict__ srcval,
             const float* __restrict__ srcstate, float* __restrict__ ds,
             float* __restrict__ dv, const float* __restrict__ gatep,
             int Ns, int Nd)
{
    GRID_DEP_SYNC();
    __shared__ uint32_t skey[8][16][32];
    __shared__ int      sidx[8][16][32];
    const int warp = threadIdx.x >> 5, lane = threadIdx.x & 31;
    const int row = blockIdx.x * 8 + warp;
    const int b = row / Ns;
    const float* L = logits + (size_t)row * Nd;

    float tv[16]; int ti[16];
#pragma unroll
    for (int i = 0; i < 16; i++) { tv[i] = -INFINITY; ti[i] = 0x40000000; }

    for (int n = lane; n < Nd; n += 32) {
        float c = L[n];
        if (c > tv[0]) {
            tv[0] = c; ti[0] = n;
#pragma unroll
            for (int i = 0; i < 15; i++) {
                if (tv[i] > tv[i + 1]) {
                    float t = tv[i]; tv[i] = tv[i + 1]; tv[i + 1] = t;
                    int u = ti[i]; ti[i] = ti[i + 1]; ti[i + 1] = u;
                }
            }
        }
    }

#pragma unroll
    for (int j = 0; j < 16; j++) {
        skey[warp][j][lane] = fmono(tv[15 - j]);
        sidx[warp][j][lane] = ti[15 - j];
    }

    float sel_v = 0.f; int sel_i = 0;
    int pos = 0;
#pragma unroll 1
    for (int it = 0; it < 16; ++it) {
        uint32_t key = skey[warp][pos][lane];
        int idx = sidx[warp][pos][lane];
        uint32_t mx = __reduce_max_sync(0xffffffffu, key);
        unsigned cand = (key == mx) ? (unsigned)idx : 0x7fffffffu;
        unsigned mni = __reduce_min_sync(0xffffffffu, cand);
        pos += (key == mx && (unsigned)idx == mni) ? 1 : 0;
        if (lane == it) { sel_v = fdemono(mx); sel_i = (int)mni; }
    }

    float a_ = (lane < 16) ? fabsf(sel_v) : -INFINITY;
    float m = a_;
#pragma unroll
    for (int o = 16; o; o >>= 1) m = fmaxf(m, __shfl_xor_sync(0xffffffffu, m, o));
    float e = (lane < 16) ? expf(a_ - m) : 0.f;
    float ssum = e;
#pragma unroll
    for (int o = 16; o; o >>= 1) ssum += __shfl_xor_sync(0xffffffffu, ssum, o);
    float sgn = (sel_v > 0.f) ? 1.f : ((sel_v < 0.f) ? -1.f : 0.f);
    float st = srcstate[row];
    float sp = fmaxf(st, 0.f) + log1pf(expf(-fabsf(st)));
    float gate = 1.f;
    if (gatep) gate = 1.f / (1.f + expf(-*gatep));
    float cc = sgn * (e / ssum) * sp * gate;

    if (lane < 16) atomicAdd(ds + (size_t)b * Nd + sel_i, cc);

    const float* srow = srcval + (size_t)row * DIM;
    float4 xr[4];
#pragma unroll
    for (int t = 0; t < 4; t++)
        xr[t] = *(const float4*)(srow + (lane << 2) + (t << 7));
#pragma unroll 1
    for (int i = 0; i < 16; i++) {
        float ci = __shfl_sync(0xffffffffu, cc, i);
        int   di = __shfl_sync(0xffffffffu, sel_i, i);
        float* dst = dv + ((size_t)b * Nd + di) * DIM + (lane << 2);
#pragma unroll
        for (int t = 0; t < 4; t++) {
            asm volatile("red.global.add.v4.f32 [%0], {%1, %2, %3, %4};"
                         :: "l"(dst + (t << 7)),
                            "f"(ci * xr[t].x), "f"(ci * xr[t].y),
                            "f"(ci * xr[t].z), "f"(ci * xr[t].w)
                         : "memory");
        }
    }
}

// ---------------- fused apply: LN rows + signed-softmax state (self-clean) ---
__global__ void __launch_bounds__(256)
apply_both(const float* __restrict__ st, float* __restrict__ ds,
           float* __restrict__ s_out,
           const float* __restrict__ val, float* __restrict__ dvv,
           float* __restrict__ v_out,
           const float* __restrict__ gamma, const float* __restrict__ beta,
           int Nd)
{
    GRID_DEP_SYNC();
    const int tid = threadIdx.x;
    const int nln = BATCH * Nd;
    __shared__ float ss[256], sq[256];
    if ((int)blockIdx.x < nln) {
        const int row = blockIdx.x;
        float2 x = ((const float2*)(val + (size_t)row * DIM))[tid];
        float2 d = ((float2*)(dvv + (size_t)row * DIM))[tid];
        ((float2*)(dvv + (size_t)row * DIM))[tid] = make_float2(0.f, 0.f);
        x.x += d.x; x.y += d.y;
        ss[tid] = x.x + x.y;
        sq[tid] = x.x * x.x + x.y * x.y;
        __syncthreads();
        for (int o = 128; o; o >>= 1) {
            if (tid < o) { ss[tid] += ss[tid + o]; sq[tid] += sq[tid + o]; }
            __syncthreads();
        }
        float mean = ss[0] * (1.f / DIM);
        float var = sq[0] * (1.f / DIM) - mean * mean;
        float rs = rsqrtf(var + 1e-5f);
        float2 g = ((const float2*)gamma)[tid];
        float2 bb = ((const float2*)beta)[tid];
        float2 y;
        y.x = (x.x - mean) * rs * g.x + bb.x;
        y.y = (x.y - mean) * rs * g.y + bb.y;
        ((float2*)(v_out + (size_t)row * DIM))[tid] = y;
    } else {
        const int b = blockIdx.x - nln;
        const float* S = st + (size_t)b * Nd;
        float* D = ds + (size_t)b * Nd;
        float x[4]; float mx = -INFINITY;
#pragma unroll
        for (int i = 0; i < 4; i++) {
            int n = tid + i * 256;
            x[i] = (n < Nd) ? (S[n] + D[n]) : 0.f;
            if (n < Nd) { mx = fmaxf(mx, fabsf(x[i])); D[n] = 0.f; }
        }
        ss[tid] = mx; __syncthreads();
        for (int o = 128; o; o >>= 1) {
            if (tid < o) ss[tid] = fmaxf(ss[tid], ss[tid + o]);
            __syncthreads();
        }
        mx = ss[0]; __syncthreads();
        float e[4]; float s = 0.f;
#pragma unroll
        for (int i = 0; i < 4; i++) {
            int n = tid + i * 256;
            e[i] = (n < Nd) ? expf(fabsf(x[i]) - mx) : 0.f;
            s += e[i];
        }
        ss[tid] = s; __syncthreads();
        for (int o = 128; o; o >>= 1) {
            if (tid < o) ss[tid] += ss[tid + o];
            __syncthreads();
        }
        float inv = 1.f / ss[0];
#pragma unroll
        for (int i = 0; i < 4; i++) {
            int n = tid + i * 256;
            if (n < Nd) {
                float sgn = (x[i] > 0.f) ? 1.f : ((x[i] < 0.f) ? -1.f : 0.f);
                s_out[(size_t)b * Nd + n] = sgn * e[i] * inv;
            }
        }
    }
}

// ---------------- plain row softmax (read attention) -------------------------
__global__ void __launch_bounds__(256)
row_softmax(float* __restrict__ L, int N)
{
    GRID_DEP_SYNC();
    const int row = blockIdx.x, tid = threadIdx.x;
    float* p = L + (size_t)row * N;
    float x[4]; float mx = -INFINITY;
#pragma unroll
    for (int i = 0; i < 4; i++) {
        int n = tid + i * 256;
        x[i] = (n < N) ? p[n] : -INFINITY;
        mx = fmaxf(mx, x[i]);
    }
    __shared__ float sm[256];
    sm[tid] = mx; __syncthreads();
    for (int o = 128; o; o >>= 1) { if (tid < o) sm[tid] = fmaxf(sm[tid], sm[tid + o]); __syncthreads(); }
    mx = sm[0]; __syncthreads();
    float e[4]; float s = 0.f;
#pragma unroll
    for (int i = 0; i < 4; i++) {
        int n = tid + i * 256;
        e[i] = (n < N) ? expf(x[i] - mx) : 0.f;
        s += e[i];
    }
    sm[tid] = s; __syncthreads();
    for (int o = 128; o; o >>= 1) { if (tid < o) sm[tid] += sm[tid + o]; __syncthreads(); }
    float inv = 1.f / sm[0];
#pragma unroll
    for (int i = 0; i < 4; i++) {
        int n = tid + i * 256;
        if (n < N) p[n] = e[i] * inv;
    }
}

// ---------------- host orchestration -----------------------------------------
template <typename K, typename... Args>
static inline void launch_pdl(K kern, dim3 grid, dim3 block, size_t smem,
                              cudaStream_t st, Args... args)
{
    cudaLaunchConfig_t cfg = {};
    cfg.gridDim = grid; cfg.blockDim = block;
    cfg.dynamicSmemBytes = smem; cfg.stream = st;
    cudaLaunchAttribute at[1];
    at[0].id = cudaLaunchAttributeProgrammaticStreamSerialization;
    at[0].val.programmaticStreamSerializationAllowed = 1;
    cfg.attrs = at; cfg.numAttrs = 1;
    cudaLaunchKernelEx(&cfg, kern, args...);
}

static inline void launch_atb(const float* A, const float* B,
                              float* C, int M, int N,
                              long long sA, long long sB, cudaStream_t st)
{
    if (M >= 1024 && N >= 128 && (M % 128) == 0 && (N % 128) == 0)
        launch_pdl(atb_big, dim3(N / 128, M / 128, BATCH), dim3(256), 67584, st,
                   A, B, C, M, N, sA, sB);
    else
        launch_pdl(atb_gemm, dim3(N / 64, M / 64, BATCH), dim3(256), 0, st,
                   A, B, C, M, N, sA, sB);
}

static void run_trans(const float* srcv, const float* srcs, int Ns,
                      const float* dstv, int Nd,
                      const float* W, const float* gatep,
                      const float* st_in, const float* vl_in,
                      float* s_out, float* v_out,
                      const float* gamma, const float* beta,
                      float* q, float* kb, float* lg, float* dsb, float* dvb)
{
    const long long qstr = (long long)BATCH * Ns * RDIM;
    const long long kstr = (long long)BATCH * Nd * RDIM;
    launch_pdl(qk_gemm_sk, dim3(SPLITK, Ns / 64 + Nd / 64, BATCH), dim3(256), 0,
               (cudaStream_t)0, srcv, dstv, W, q, kb, Ns, Nd, qstr, kstr);
    launch_atb(q, kb, lg, Ns, Nd, qstr, kstr, 0);
    launch_pdl(topk_scatter, dim3(BATCH * Ns / 8), dim3(256), 0,
               (cudaStream_t)0, lg, srcv, srcs, dsb, dvb, gatep, Ns, Nd);
    launch_pdl(apply_both, dim3(BATCH * Nd + BATCH), dim3(256), 0,
               (cudaStream_t)0, st_in, dsb, s_out, vl_in, dvb, v_out,
               gamma, beta, Nd);
}

// transition with PRECOMPUTED q partials (k-only projection in the chain)
static void run_trans_preq(const float* srcv, const float* srcs, int Ns,
                           const float* dstv, int Nd,
                           const float* W, const float* gatep,
                           const float* st_in, const float* vl_in,
                           float* s_out, float* v_out,
                           const float* gamma, const float* beta,
                           const float* qpre, long long qstr,
                           float* kb, float* lg, float* dsb, float* dvb)
{
    const long long kstr = (long long)BATCH * Nd * RDIM;
    launch_pdl(qk_gemm_sk, dim3(SPLITK, Nd / 64, BATCH), dim3(256), 0,
               (cudaStream_t)0, srcv, dstv, W, kb, kb, 0, Nd, kstr, kstr);
    launch_atb(qpre, kb, lg, Ns, Nd, qstr, kstr, 0);
    launch_pdl(topk_scatter, dim3(BATCH * Ns / 8), dim3(256), 0,
               (cudaStream_t)0, lg, srcv, srcs, dsb, dvb, gatep, Ns, Nd);
    launch_pdl(apply_both, dim3(BATCH * Nd + BATCH), dim3(256), 0,
               (cudaStream_t)0, st_in, dsb, s_out, vl_in, dvb, v_out,
               gamma, beta, Nd);
}

static void read_level(int l, const float* mv, int S,
                       const float* rr, const float* rp, const float* rg,
                       const float* tok_val, float* out,
                       float* rq, float* kr, float* lgr, float* r,
                       cudaStream_t st)
{
    const long long RQS = (long long)3 * BATCH * TOK * RDIM;  // split stride
    const size_t    RQL = (size_t)BATCH * TOK * RDIM;         // route stride
    const long long kstr = (long long)BATCH * S * RDIM;
    launch_pdl(qk_gemm_sk, dim3(SPLITK, S / 64, BATCH), dim3(256), 0, st,
               (const float*)mv, (const float*)mv, rr + (size_t)l * 2 * DR,
               kr, kr, 0, S, kstr, kstr);
    launch_atb(rq + (size_t)l * RQL, kr, lgr, TOK, S, RQS, kstr, st);
    launch_pdl(row_softmax, dim3(BATCH * TOK), dim3(256), 0, st, lgr, S);
    launch_pdl(ab_gemm_tf32, dim3(DIM / 128, TOK / 128, BATCH), dim3(256), 0, st,
               (const float*)lgr, mv, r, (const float*)nullptr,
               (const float*)nullptr, TOK, DIM, S,
               (long long)TOK * S, (long long)S * DIM, (long long)TOK * DIM);
    launch_pdl(ab_gemm_tf32, dim3(DIM / 128, TOK / 128, BATCH), dim3(256), 0, st,
               (const float*)r, rp + (size_t)l * DIM * DIM, out,
               (l == 0) ? tok_val : (const float*)out, rg + l, TOK, DIM, DIM,
               (long long)TOK * DIM, (long long)0, (long long)TOK * DIM);
}

extern "C" void kernel_launch(void* const* d_in, const int* in_sizes, int n_in,
                              void* d_out, int out_size)
{
    const float* tok_val   = (const float*)d_in[0];
    const float* tok_state = (const float*)d_in[1];
    const float* ms0 = (const float*)d_in[2];
    const float* mv0 = (const float*)d_in[3];
    const float* ms1 = (const float*)d_in[4];
    const float* mv1 = (const float*)d_in[5];
    const float* ms2 = (const float*)d_in[6];
    const float* mv2 = (const float*)d_in[7];
    const float* wr  = (const float*)d_in[8];
    const float* pr  = (const float*)d_in[9];
    const float* lr  = (const float*)d_in[10];
    const float* sr  = (const float*)d_in[11];
    const float* sg  = (const float*)d_in[12];
    const float* lgam = (const float*)d_in[13];
    const float* lbet = (const float*)d_in[14];
    const float* rr  = (const float*)d_in[15];
    const float* rp  = (const float*)d_in[16];
    const float* rg  = (const float*)d_in[17];
    float* out = (float*)d_out;

    static bool _attr = []() {
        cudaFuncSetAttribute(atb_big,
            cudaFuncAttributeMaxDynamicSharedMemorySize, 67584);
        return true;
    }();
    (void)_attr;
    static cudaStream_t s1 = []() {
        cudaStream_t s; cudaStreamCreateWithFlags(&s, cudaStreamNonBlocking);
        return s;
    }();
    static cudaEvent_t evH = []() {
        cudaEvent_t e; cudaEventCreateWithFlags(&e, cudaEventDisableTiming);
        return e;
    }();
    static cudaEvent_t evFill = []() {
        cudaEvent_t e; cudaEventCreateWithFlags(&e, cudaEventDisableTiming);
        return e;
    }();
    static cudaEvent_t evQ4 = []() {
        cudaEvent_t e; cudaEventCreateWithFlags(&e, cudaEventDisableTiming);
        return e;
    }();
    static cudaEvent_t evQ7 = []() {
        cudaEvent_t e; cudaEventCreateWithFlags(&e, cudaEventDisableTiming);
        return e;
    }();
    static cudaEvent_t ev0 = []() {
        cudaEvent_t e; cudaEventCreateWithFlags(&e, cudaEventDisableTiming);
        return e;
    }();
    static cudaEvent_t ev1 = []() {
        cudaEvent_t e; cudaEventCreateWithFlags(&e, cudaEventDisableTiming);
        return e;
    }();
    static cudaEvent_t ev2 = []() {
        cudaEvent_t e; cudaEventCreateWithFlags(&e, cudaEventDisableTiming);
        return e;
    }();
    static cudaEvent_t evF = []() {
        cudaEvent_t e; cudaEventCreateWithFlags(&e, cudaEventDisableTiming);
        return e;
    }();

    float *q, *kb, *kr, *rq, *q4, *q7, *lg, *lgr, *dsb, *dvb;
    float *s0, *v0, *s1v, *v1, *s2, *v2, *r;
    cudaGetSymbolAddress((void**)&q,   g_q);
    cudaGetSymbolAddress((void**)&kb,  g_k);
    cudaGetSymbolAddress((void**)&kr,  g_kr);
    cudaGetSymbolAddress((void**)&rq,  g_rq);
    cudaGetSymbolAddress((void**)&q4,  g_q4);
    cudaGetSymbolAddress((void**)&q7,  g_q7);
    cudaGetSymbolAddress((void**)&lg,  g_lg);
    cudaGetSymbolAddress((void**)&lgr, g_lgr);
    cudaGetSymbolAddress((void**)&dsb, g_ds);
    cudaGetSymbolAddress((void**)&dvb, g_dv);
    cudaGetSymbolAddress((void**)&s0,  g_s0);
    cudaGetSymbolAddress((void**)&v0,  g_v0);
    cudaGetSymbolAddress((void**)&s1v, g_s1);
    cudaGetSymbolAddress((void**)&v1,  g_v1);
    cudaGetSymbolAddress((void**)&s2,  g_s2);
    cudaGetSymbolAddress((void**)&v2,  g_v2);
    cudaGetSymbolAddress((void**)&r,   g_r);

    const long long QS_TOK = (long long)BATCH * TOK * RDIM;
    const long long QS_NS0 = (long long)BATCH * NS0 * RDIM;

    // fork: head work on s1 overlapping t1 on stream 0
    cudaEventRecord(evH, 0);
    cudaStreamWaitEvent(s1, evH, 0);
    launch_pdl(fill_ds_dv, dim3(2048), dim3(256), 0, s1,
               dsb, (float4*)dvb, BATCH * NS0, BATCH * NS0 * DIM / 4);
    cudaEventRecord(evFill, s1);
    launch_pdl(rq_gemm_sk, dim3(SPLITK, TOK / 64, 3 * BATCH), dim3(256), 0, s1,
               tok_val, rr, rq);
    launch_pdl(qk_gemm_sk, dim3(SPLITK, TOK / 64, BATCH), dim3(256), 0, s1,
               tok_val, tok_val, sr + 0 * 2 * DR, q4, q4, TOK, 0, QS_TOK, QS_TOK);
    cudaEventRecord(evQ4, s1);

    // ---- level 0, transition 1 (inlined: needs fill-join before topk) ----
    launch_pdl(qk_gemm_sk, dim3(SPLITK, TOK / 64 + NS0 / 64, BATCH), dim3(256), 0,
               (cudaStream_t)0, tok_val, mv0, wr, q, kb, TOK, NS0,
               QS_TOK, QS_NS0);
    launch_atb(q, kb, lg, TOK, NS0, QS_TOK, QS_NS0, 0);
    cudaStreamWaitEvent((cudaStream_t)0, evFill, 0);
    launch_pdl(topk_scatter, dim3(BATCH * TOK / 8), dim3(256), 0,
               (cudaStream_t)0, (const float*)lg, tok_val, tok_state,
               dsb, dvb, (const float*)nullptr, TOK, NS0);
    launch_pdl(apply_both, dim3(BATCH * NS0 + BATCH), dim3(256), 0,
               (cudaStream_t)0, ms0, dsb, s0, mv0, dvb, v0, lgam, lbet, NS0);
    run_trans(v0, s0, NS0, v0, NS0, pr + 0 * 2 * DR, nullptr,
              s0, v0, s0, v0, lgam + 0 * DIM, lbet + 0 * DIM,
              q, kb, lg, dsb, dvb);
    cudaEventRecord(ev0, 0);
    // s1: t7 q precompute (v0 @ sr[1][0]) then read level 0
    cudaStreamWaitEvent(s1, ev0, 0);
    launch_pdl(qk_gemm_sk, dim3(SPLITK, NS0 / 64, BATCH), dim3(256), 0, s1,
               (const float*)v0, (const float*)v0, sr + 1 * 2 * DR,
               q7, q7, NS0, 0, QS_NS0, QS_NS0);
    cudaEventRecord(evQ7, s1);
    read_level(0, v0, NS0, rr, rp, rg, tok_val, out, rq, kr, lgr, r, s1);

    // ---- level 1 ----
    run_trans(v0, s0, NS0, mv1, NS1, lr + 0 * 2 * DR, nullptr,
              ms1, mv1, s1v, v1, lgam + 1 * DIM, lbet + 1 * DIM,
              q, kb, lg, dsb, dvb);
    cudaStreamWaitEvent((cudaStream_t)0, evQ4, 0);
    run_trans_preq(tok_val, tok_state, TOK, v1, NS1, sr + 0 * 2 * DR, sg + 0,
                   s1v, v1, s1v, v1, lgam + 1 * DIM, lbet + 1 * DIM,
                   q4, QS_TOK, kb, lg, dsb, dvb);
    run_trans(v1, s1v, NS1, v1, NS1, pr + 1 * 2 * DR, nullptr,
              s1v, v1, s1v, v1, lgam + 1 * DIM, lbet + 1 * DIM,
              q, kb, lg, dsb, dvb);
    cudaEventRecord(ev1, 0);
    cudaStreamWaitEvent(s1, ev1, 0);
    read_level(1, v1, NS1, rr, rp, rg, tok_val, out, rq, kr, lgr, r, s1);

    // ---- level 2 ----
    run_trans(v1, s1v, NS1, mv2, NS2, lr + 1 * 2 * DR, nullptr,
              ms2, mv2, s2, v2, lgam + 2 * DIM, lbet + 2 * DIM,
              q, kb, lg, dsb, dvb);
    cudaStreamWaitEvent((cudaStream_t)0, evQ7, 0);
    run_trans_preq(v0, s0, NS0, v2, NS2, sr + 1 * 2 * DR, sg + 1,
                   s2, v2, s2, v2, lgam + 2 * DIM, lbet + 2 * DIM,
                   q7, QS_NS0, kb, lg, dsb, dvb);
    run_trans(v2, s2, NS2, v2, NS2, pr + 2 * 2 * DR, nullptr,
              s2, v2, s2, v2, lgam + 2 * DIM, lbet + 2 * DIM,
              q, kb, lg, dsb, dvb);
    cudaEventRecord(ev2, 0);
    cudaStreamWaitEvent(s1, ev2, 0);
    read_level(2, v2, NS2, rr, rp, rg, tok_val, out, rq, kr, lgr, r, s1);

    // join read stream back into the main (captured) stream
    cudaEventRecord(evF, s1);
    cudaStreamWaitEvent((cudaStream_t)0, evF, 0);
}